// round 1
// baseline (speedup 1.0000x reference)
#include <cuda_runtime.h>
#include <math.h>

#define LSEQ 4096
#define DMOD 768
#define DIN  1536
#define DST  16
#define RNK  48
#define NCOL 80        // DT_RANK + 2*D_STATE
#define NCHUNK 32
#define CHLEN  128     // LSEQ / NCHUNK
#define INV_LM (1.0f / (4096.0f * 768.0f))

// ---------------- scratch (global __device__, no allocations) ----------------
__device__ float d_wsum[DIN];
__device__ float d_uT[DMOD * LSEQ];            // u transposed: [d][l]
__device__ float d_xz[LSEQ * 2 * DIN];         // 4096 x 3072
__device__ float d_xs[LSEQ * DIN];             // post conv+silu
__device__ float d_g [LSEQ * DIN];             // silu(z)*w[d]*INV_LM
__device__ float d_dt[LSEQ * DIN];
__device__ float d_dbc[LSEQ * NCOL];
__device__ float d_P [NCHUNK * DIN * DST];
__device__ float d_E [NCHUNK * DIN * DST];
__device__ float d_Kc[NCHUNK * DIN * DST];
__device__ float d_part_conv[1024];
__device__ float d_part_scan[NCHUNK * 96];
__device__ float d_part_p2[96];

__device__ __forceinline__ float siluf(float x) { return x / (1.0f + __expf(-x)); }

__device__ __forceinline__ float blockReduceSum(float v) {
    __shared__ float sh[32];
    int lane = threadIdx.x & 31;
    int w    = threadIdx.x >> 5;
    #pragma unroll
    for (int o = 16; o > 0; o >>= 1) v += __shfl_down_sync(0xffffffffu, v, o);
    if (lane == 0) sh[w] = v;
    __syncthreads();
    int nw = blockDim.x >> 5;
    v = (threadIdx.x < nw) ? sh[threadIdx.x] : 0.0f;
    if (w == 0) {
        #pragma unroll
        for (int o = 16; o > 0; o >>= 1) v += __shfl_down_sync(0xffffffffu, v, o);
    }
    return v;  // valid on thread 0
}

// ---------------- K0: column sums of out_proj_w (768 x 1536) ----------------
__global__ void k_colsum(const float* __restrict__ opw) {
    int d = blockIdx.x * blockDim.x + threadIdx.x;
    if (d >= DIN) return;
    float s = 0.0f;
    for (int m = 0; m < DMOD; m++) s += opw[m * DIN + d];
    d_wsum[d] = s;
}

// ---------------- K1: patchify x (1,3,1024,1024) -> uT[d][l] ----------------
__global__ void k_patchify(const float* __restrict__ x) {
    int idx = blockIdx.x * blockDim.x + threadIdx.x;  // d*4096 + l
    if (idx >= DMOD * LSEQ) return;
    int d = idx >> 12;
    int l = idx & 4095;
    int c   = d >> 8;
    int r   = d & 255;
    int ih  = r >> 2;
    int iwq = r & 3;
    int iwr = l >> 8;
    int rest = l & 255;
    int a = rest >> 4;
    int b = rest & 15;
    int iw = iwq * 16 + iwr;
    int src = c * 1048576 + (ih * 16 + a) * 1024 + iw * 16 + b;
    d_uT[idx] = x[src];
}

// ---------------- K2: GEMM1  xz[l,n] = sum_k uT[k][l] * W1[n*768+k] ----------
#define BM 128
#define BN 128
#define BK 16
__global__ void k_gemm1(const float* __restrict__ W1) {
    __shared__ float As[BK][BM + 4];
    __shared__ float Bs[BK][BN + 4];
    int t  = threadIdx.x;          // 256
    int m0 = blockIdx.y * BM;      // l
    int n0 = blockIdx.x * BN;      // output channel
    int ty = t >> 4, tx = t & 15;
    float acc[8][8];
    #pragma unroll
    for (int i = 0; i < 8; i++)
        #pragma unroll
        for (int j = 0; j < 8; j++) acc[i][j] = 0.0f;

    for (int k0 = 0; k0 < DMOD; k0 += BK) {
        // A: uT is [k][l] -> direct coalesced load, no transpose
        #pragma unroll
        for (int p = t; p < 512; p += 256) {
            int k  = p >> 5;
            int mv = (p & 31) * 4;
            float4 v = *(const float4*)&d_uT[(k0 + k) * LSEQ + m0 + mv];
            *(float4*)&As[k][mv] = v;
        }
        // B: W1 rows n, transpose into Bs[k][n]
        #pragma unroll
        for (int p = t; p < 512; p += 256) {
            int n  = p >> 2;
            int kv = (p & 3) * 4;
            float4 v = *(const float4*)&W1[(n0 + n) * DMOD + k0 + kv];
            Bs[kv + 0][n] = v.x; Bs[kv + 1][n] = v.y;
            Bs[kv + 2][n] = v.z; Bs[kv + 3][n] = v.w;
        }
        __syncthreads();
        #pragma unroll
        for (int k = 0; k < BK; k++) {
            float4 a0 = *(float4*)&As[k][ty * 8];
            float4 a1 = *(float4*)&As[k][ty * 8 + 4];
            float4 b0 = *(float4*)&Bs[k][tx * 8];
            float4 b1 = *(float4*)&Bs[k][tx * 8 + 4];
            float av[8] = {a0.x, a0.y, a0.z, a0.w, a1.x, a1.y, a1.z, a1.w};
            float bv[8] = {b0.x, b0.y, b0.z, b0.w, b1.x, b1.y, b1.z, b1.w};
            #pragma unroll
            for (int i = 0; i < 8; i++)
                #pragma unroll
                for (int j = 0; j < 8; j++) acc[i][j] += av[i] * bv[j];
        }
        __syncthreads();
    }
    #pragma unroll
    for (int i = 0; i < 8; i++) {
        int row = m0 + ty * 8 + i;
        float4 v0 = {acc[i][0], acc[i][1], acc[i][2], acc[i][3]};
        float4 v1 = {acc[i][4], acc[i][5], acc[i][6], acc[i][7]};
        *(float4*)&d_xz[row * (2 * DIN) + n0 + tx * 8]     = v0;
        *(float4*)&d_xz[row * (2 * DIN) + n0 + tx * 8 + 4] = v1;
    }
}

// -------- K3: causal depthwise conv(4) + silu, g = silu(z)*w*inv, + xs*D*g ---
__global__ void k_conv(const float* __restrict__ convw,
                       const float* __restrict__ convb,
                       const float* __restrict__ Dvec) {
    float local = 0.0f;
    int total = LSEQ * DIN;
    for (int idx = blockIdx.x * blockDim.x + threadIdx.x; idx < total;
         idx += gridDim.x * blockDim.x) {
        int l  = idx / DIN;
        int ch = idx - l * DIN;
        float s = convb[ch];
        #pragma unroll
        for (int k = 0; k < 4; k++) {
            int lk = l - 3 + k;
            if (lk >= 0) s += convw[ch * 4 + k] * d_xz[lk * (2 * DIN) + ch];
        }
        float xsv = siluf(s);
        float zv  = d_xz[l * (2 * DIN) + DIN + ch];
        float gv  = siluf(zv) * d_wsum[ch] * INV_LM;
        d_xs[idx] = xsv;
        d_g[idx]  = gv;
        local += xsv * Dvec[ch] * gv;
    }
    float tot = blockReduceSum(local);
    if (threadIdx.x == 0) d_part_conv[blockIdx.x] = tot;
}

// ---------------- K4: GEMM2  dbc[l,j] = sum_ch xs[l,ch]*xpw[j,ch] ------------
// 32 l-rows per block, 80 j; 256 threads = 16(tx over j) x 16(ty over 2 l)
__global__ void k_gemm2(const float* __restrict__ xpw) {
    __shared__ __align__(16) float sx[32][64];
    __shared__ __align__(16) float sw[80][64];
    int t  = threadIdx.x;
    int l0 = blockIdx.x * 32;
    int tx = t & 15;       // j lane: j = tx + 16*jj
    int ty = t >> 4;       // l pair: l = ty*2 + i
    float acc[2][5];
    #pragma unroll
    for (int i = 0; i < 2; i++)
        #pragma unroll
        for (int j = 0; j < 5; j++) acc[i][j] = 0.0f;

    for (int k0 = 0; k0 < DIN; k0 += 64) {
        #pragma unroll
        for (int p = t; p < 512; p += 256) {          // 32x64 = 512 float4
            int li = p >> 4;
            int kv = (p & 15) * 4;
            *(float4*)&sx[li][kv] = *(const float4*)&d_xs[(l0 + li) * DIN + k0 + kv];
        }
        for (int p = t; p < 1280; p += 256) {         // 80x64 = 1280 float4
            int j  = p >> 4;
            int kv = (p & 15) * 4;
            *(float4*)&sw[j][kv] = *(const float4*)&xpw[j * DIN + k0 + kv];
        }
        __syncthreads();
        #pragma unroll
        for (int k4 = 0; k4 < 16; k4++) {
            float4 a0 = *(float4*)&sx[ty * 2][k4 * 4];
            float4 a1 = *(float4*)&sx[ty * 2 + 1][k4 * 4];
            #pragma unroll
            for (int jj = 0; jj < 5; jj++) {
                float4 w = *(float4*)&sw[tx + 16 * jj][k4 * 4];
                acc[0][jj] += a0.x * w.x + a0.y * w.y + a0.z * w.z + a0.w * w.w;
                acc[1][jj] += a1.x * w.x + a1.y * w.y + a1.z * w.z + a1.w * w.w;
            }
        }
        __syncthreads();
    }
    #pragma unroll
    for (int i = 0; i < 2; i++)
        #pragma unroll
        for (int jj = 0; jj < 5; jj++)
            d_dbc[(l0 + ty * 2 + i) * NCOL + tx + 16 * jj] = acc[i][jj];
}

// ---------------- K5: dt = softplus(dbc[:, :48] @ dtw^T + b) -----------------
// block: 128 threads (one d each), 128 l per block. dtw row cached in regs.
__global__ void k_dt(const float* __restrict__ dtw,
                     const float* __restrict__ dtb) {
    __shared__ float sdbc[128][48];
    int t  = threadIdx.x;
    int d  = blockIdx.x * 128 + t;
    int l0 = blockIdx.y * 128;
    float wr[48];
    #pragma unroll
    for (int r = 0; r < 48; r++) wr[r] = dtw[d * 48 + r];
    float bias = dtb[d];
    for (int p = t; p < 128 * 48; p += 128) {
        int li = p / 48;
        int r  = p - li * 48;
        sdbc[li][r] = d_dbc[(l0 + li) * NCOL + r];
    }
    __syncthreads();
    for (int li = 0; li < 128; li++) {
        float s = bias;
        #pragma unroll
        for (int r = 0; r < 48; r++) s += wr[r] * sdbc[li][r];
        float sp = (s > 20.0f) ? s : log1pf(__expf(s));
        d_dt[(l0 + li) * DIN + d] = sp;
    }
}

// ---------------- K6: scan pass 1 (chunked, per (chunk,d,s) thread) ----------
__global__ void k_scan1(const float* __restrict__ A_log) {
    int t    = threadIdx.x;
    int s    = t & 15;
    int dloc = t >> 4;
    int d    = blockIdx.x * 16 + dloc;
    int c    = blockIdx.y;
    float Av = -__expf(A_log[d * DST + s]);
    float h = 0.0f, cp = 1.0f, acc = 0.0f, Kacc = 0.0f;
    int base = c * CHLEN;
    #pragma unroll 4
    for (int i = 0; i < CHLEN; i++) {
        int l = base + i;
        float dtv = d_dt[l * DIN + d];
        float xsv = d_xs[l * DIN + d];
        float gv  = d_g [l * DIN + d];
        float Bv  = d_dbc[l * NCOL + RNK + s];
        float Cv  = d_dbc[l * NCOL + RNK + DST + s];
        float dA  = __expf(dtv * Av);
        cp *= dA;
        h = dA * h + dtv * Bv * xsv;
        float cg = Cv * gv;
        acc  += h  * cg;
        Kacc += cp * cg;
    }
    int off = (c * DIN + d) * DST + s;
    d_P[off]  = cp;
    d_E[off]  = h;
    d_Kc[off] = Kacc;
    float tot = blockReduceSum(acc);
    if (t == 0) d_part_scan[blockIdx.y * 96 + blockIdx.x] = tot;
}

// ---------------- K7: scan pass 2 (chunk combine) ----------------------------
__global__ void k_scan2() {
    int gid = blockIdx.x * 256 + threadIdx.x;   // 0..24575 == d*16+s
    float h = 0.0f, St = 0.0f;
    for (int c = 0; c < NCHUNK; c++) {
        int off = c * (DIN * DST) + gid;
        St += d_Kc[off] * h;
        h   = d_P[off] * h + d_E[off];
    }
    float tot = blockReduceSum(St);
    if (threadIdx.x == 0) d_part_p2[blockIdx.x] = tot;
}

// ---------------- K8: deterministic final reduce -----------------------------
__global__ void k_final(float* __restrict__ out) {
    int t = threadIdx.x;
    float v = 0.0f;
    for (int i = t; i < 1024; i += 256)         v += d_part_conv[i];
    for (int i = t; i < NCHUNK * 96; i += 256)  v += d_part_scan[i];
    for (int i = t; i < 96; i += 256)           v += d_part_p2[i];
    float tot = blockReduceSum(v);
    if (t == 0) out[0] = tot;
}

// ---------------- launch -----------------------------------------------------
extern "C" void kernel_launch(void* const* d_in, const int* in_sizes, int n_in,
                              void* d_out, int out_size) {
    const float* x     = (const float*)d_in[0];
    const float* w_in  = (const float*)d_in[1];
    const float* convw = (const float*)d_in[2];
    const float* convb = (const float*)d_in[3];
    const float* xpw   = (const float*)d_in[4];
    const float* dtw   = (const float*)d_in[5];
    const float* dtb   = (const float*)d_in[6];
    const float* A_log = (const float*)d_in[7];
    const float* Dvec  = (const float*)d_in[8];
    const float* opw   = (const float*)d_in[9];
    float* out = (float*)d_out;

    k_colsum<<<6, 256>>>(opw);
    k_patchify<<<(DMOD * LSEQ) / 256, 256>>>(x);
    k_gemm1<<<dim3(2 * DIN / BN, LSEQ / BM), 256>>>(w_in);
    k_conv<<<1024, 256>>>(convw, convb, Dvec);
    k_gemm2<<<LSEQ / 32, 256>>>(xpw);
    k_dt<<<dim3(DIN / 128, LSEQ / 128), 128>>>(dtw, dtb);
    k_scan1<<<dim3(DIN / 16, NCHUNK), 256>>>(A_log);
    k_scan2<<<96, 256>>>();
    k_final<<<1, 256>>>(out);
}

// round 3
// speedup vs baseline: 1.3125x; 1.3125x over previous
#include <cuda_runtime.h>
#include <cuda_bf16.h>
#include <math.h>
#include <stdint.h>

#define LSEQ 4096
#define DMOD 768
#define DIN  1536
#define DST  16
#define RNK  48
#define NCOL 80
#define NCHUNK 32
#define CHLEN  128
#define INV_LM (1.0f / (4096.0f * 768.0f))

// ---------------- scratch ----------------------------------------------------
__device__ float d_wsum[DIN];
__device__ __nv_bfloat16 d_uhi[LSEQ * DMOD];
__device__ __nv_bfloat16 d_ulo[LSEQ * DMOD];
__device__ __nv_bfloat16 d_whi[2 * DIN * DMOD];
__device__ __nv_bfloat16 d_wlo[2 * DIN * DMOD];
__device__ float d_xz[LSEQ * 2 * DIN];
__device__ float d_xs[LSEQ * DIN];
__device__ float d_g [LSEQ * DIN];
__device__ float d_dt[LSEQ * DIN];
__device__ float d_dbc[LSEQ * NCOL];
__device__ float d_P [NCHUNK * DIN * DST];
__device__ float d_E [NCHUNK * DIN * DST];
__device__ float d_Kc[NCHUNK * DIN * DST];
__device__ float d_part_conv[1024];
__device__ float d_part_scan[NCHUNK * 96];
__device__ float d_part_p2[96];

__device__ __forceinline__ float siluf(float x) { return x / (1.0f + __expf(-x)); }

__device__ __forceinline__ float blockReduceSum(float v) {
    __shared__ float sh[32];
    int lane = threadIdx.x & 31;
    int w    = threadIdx.x >> 5;
    #pragma unroll
    for (int o = 16; o > 0; o >>= 1) v += __shfl_down_sync(0xffffffffu, v, o);
    if (lane == 0) sh[w] = v;
    __syncthreads();
    int nw = blockDim.x >> 5;
    v = (threadIdx.x < nw) ? sh[threadIdx.x] : 0.0f;
    if (w == 0) {
        #pragma unroll
        for (int o = 16; o > 0; o >>= 1) v += __shfl_down_sync(0xffffffffu, v, o);
    }
    return v;
}

// ---------------- asm helpers (all sm_80-baseline features) ------------------
__device__ __forceinline__ uint32_t smem_to_u32(const void* p) {
    uint32_t a;
    asm("{ .reg .u64 t; cvta.to.shared.u64 t, %1; cvt.u32.u64 %0, t; }" : "=r"(a) : "l"(p));
    return a;
}
#define CP16(sm, gp) \
    asm volatile("cp.async.cg.shared.global [%0], [%1], 16;" :: "r"(sm), "l"(gp))
#define CP_COMMIT() asm volatile("cp.async.commit_group;" ::: "memory")
#define CP_WAIT1()  asm volatile("cp.async.wait_group 1;" ::: "memory")

__device__ __forceinline__ void ldsm_x4(uint32_t& r0, uint32_t& r1, uint32_t& r2,
                                        uint32_t& r3, uint32_t addr) {
    asm volatile("ldmatrix.sync.aligned.m8n8.x4.shared.b16 {%0,%1,%2,%3}, [%4];"
                 : "=r"(r0), "=r"(r1), "=r"(r2), "=r"(r3) : "r"(addr));
}
__device__ __forceinline__ void mma16816(float* c, const uint32_t* a, const uint32_t* b) {
    asm volatile("mma.sync.aligned.m16n8k16.row.col.f32.bf16.bf16.f32 "
                 "{%0,%1,%2,%3}, {%4,%5,%6,%7}, {%8,%9}, {%0,%1,%2,%3};"
                 : "+f"(c[0]), "+f"(c[1]), "+f"(c[2]), "+f"(c[3])
                 : "r"(a[0]), "r"(a[1]), "r"(a[2]), "r"(a[3]), "r"(b[0]), "r"(b[1]));
}

// ---------------- K0: column sums of out_proj_w ------------------------------
__global__ void k_colsum(const float* __restrict__ opw) {
    int d = blockIdx.x * blockDim.x + threadIdx.x;
    if (d >= DIN) return;
    float s = 0.0f;
    for (int m = 0; m < DMOD; m++) s += opw[m * DIN + d];
    d_wsum[d] = s;
}

// ---------------- K1: patchify -> u[l][k], split to bf16 hi/lo ---------------
__global__ void k_patchify(const float* __restrict__ x) {
    int idx = blockIdx.x * blockDim.x + threadIdx.x;  // l*768 + d
    if (idx >= DMOD * LSEQ) return;
    int l = idx / DMOD;
    int d = idx - l * DMOD;
    int c   = d >> 8;
    int r   = d & 255;
    int ih  = r >> 2;
    int iwq = r & 3;
    int iwr = l >> 8;
    int rest = l & 255;
    int a = rest >> 4;
    int b = rest & 15;
    int iw = iwq * 16 + iwr;
    float v = x[c * 1048576 + (ih * 16 + a) * 1024 + iw * 16 + b];
    __nv_bfloat16 hi = __float2bfloat16(v);
    __nv_bfloat16 lo = __float2bfloat16(v - __bfloat162float(hi));
    d_uhi[idx] = hi;
    d_ulo[idx] = lo;
}

// ---------------- K1b: split in_proj_w to bf16 hi/lo -------------------------
__global__ void k_wsplit(const float* __restrict__ w) {
    int idx = blockIdx.x * blockDim.x + threadIdx.x;
    if (idx >= 2 * DIN * DMOD) return;
    float v = w[idx];
    __nv_bfloat16 hi = __float2bfloat16(v);
    __nv_bfloat16 lo = __float2bfloat16(v - __bfloat162float(hi));
    d_whi[idx] = hi;
    d_wlo[idx] = lo;
}

// ---------------- K2: GEMM1 via mma.sync bf16 (3-term split) -----------------
// C[4096x3072] = u[4096x768] * W^T, both K-major. CTA 128x128, 8 warps 2x4,
// warp tile 64x32. BK=32, double-buffered cp.async. SMEM row stride 80B.
#define G1_TILE   10240                 // 128 rows * 80 B
#define G1_STAGE  (4 * G1_TILE)         // Ahi, Alo, Bhi, Blo
#define G1_SMEM   (2 * G1_STAGE)        // 81920 B
#define G1_ITERS  24                    // 768 / 32

__global__ void __launch_bounds__(256, 1) k_gemm1_mma() {
    extern __shared__ char smem[];
    const uint32_t sbase = smem_to_u32(smem);
    const int t    = threadIdx.x;
    const int lane = t & 31;
    const int wid  = t >> 5;
    const int wm   = wid >> 2;      // 0..1
    const int wn   = wid & 3;       // 0..3
    const int n0   = blockIdx.x * 128;
    const int l0   = blockIdx.y * 128;

    float acc[4][4][4];
    #pragma unroll
    for (int i = 0; i < 4; i++)
        #pragma unroll
        for (int j = 0; j < 4; j++)
            #pragma unroll
            for (int q = 0; q < 4; q++) acc[i][j][q] = 0.0f;

    const int prow = t >> 2;        // 0..63
    const int pq   = t & 3;

    // prefetch stage 0
    {
        const int k0 = 0;
        const uint32_t so = sbase;
        #pragma unroll
        for (int rep = 0; rep < 2; rep++) {
            int row = prow + rep * 64;
            uint32_t soff = (uint32_t)(row * 80 + pq * 16);
            long ga = (long)(l0 + row) * DMOD + k0 + pq * 8;
            long gb = (long)(n0 + row) * DMOD + k0 + pq * 8;
            CP16(so + soff,                 (const void*)(d_uhi + ga));
            CP16(so + G1_TILE + soff,       (const void*)(d_ulo + ga));
            CP16(so + 2 * G1_TILE + soff,   (const void*)(d_whi + gb));
            CP16(so + 3 * G1_TILE + soff,   (const void*)(d_wlo + gb));
        }
    }
    CP_COMMIT();

    for (int c = 0; c < G1_ITERS; c++) {
        if (c + 1 < G1_ITERS) {
            const int k0 = (c + 1) * 32;
            const uint32_t so = sbase + ((c + 1) & 1) * G1_STAGE;
            #pragma unroll
            for (int rep = 0; rep < 2; rep++) {
                int row = prow + rep * 64;
                uint32_t soff = (uint32_t)(row * 80 + pq * 16);
                long ga = (long)(l0 + row) * DMOD + k0 + pq * 8;
                long gb = (long)(n0 + row) * DMOD + k0 + pq * 8;
                CP16(so + soff,               (const void*)(d_uhi + ga));
                CP16(so + G1_TILE + soff,     (const void*)(d_ulo + ga));
                CP16(so + 2 * G1_TILE + soff, (const void*)(d_whi + gb));
                CP16(so + 3 * G1_TILE + soff, (const void*)(d_wlo + gb));
            }
        }
        CP_COMMIT();
        CP_WAIT1();
        __syncthreads();

        const uint32_t so = sbase + (c & 1) * G1_STAGE;
        #pragma unroll
        for (int kk = 0; kk < 2; kk++) {
            // A fragments
            uint32_t a_hi[4][4], a_lo[4][4];
            const int arow = wm * 64 + (lane & 15);
            const int acol = kk * 16 + ((lane >> 4) << 3);
            #pragma unroll
            for (int mt = 0; mt < 4; mt++) {
                uint32_t addr = so + (uint32_t)((arow + mt * 16) * 80 + acol * 2);
                ldsm_x4(a_hi[mt][0], a_hi[mt][1], a_hi[mt][2], a_hi[mt][3], addr);
                ldsm_x4(a_lo[mt][0], a_lo[mt][1], a_lo[mt][2], a_lo[mt][3], addr + G1_TILE);
            }
            // B fragments (x4 covers two n-tiles)
            uint32_t b_hi[4][2], b_lo[4][2];
            const int g = lane >> 3;
            const int brow = wn * 32 + ((g >> 1) << 3) + (lane & 7);
            const int bcol = kk * 16 + ((g & 1) << 3);
            #pragma unroll
            for (int np = 0; np < 2; np++) {
                uint32_t addr = so + 2 * G1_TILE
                              + (uint32_t)((brow + np * 16) * 80 + bcol * 2);
                ldsm_x4(b_hi[2 * np][0], b_hi[2 * np][1],
                        b_hi[2 * np + 1][0], b_hi[2 * np + 1][1], addr);
                ldsm_x4(b_lo[2 * np][0], b_lo[2 * np][1],
                        b_lo[2 * np + 1][0], b_lo[2 * np + 1][1], addr + G1_TILE);
            }
            #pragma unroll
            for (int mt = 0; mt < 4; mt++)
                #pragma unroll
                for (int nt = 0; nt < 4; nt++) {
                    mma16816(acc[mt][nt], a_hi[mt], b_hi[nt]);
                    mma16816(acc[mt][nt], a_lo[mt], b_hi[nt]);
                    mma16816(acc[mt][nt], a_hi[mt], b_lo[nt]);
                }
        }
        __syncthreads();
    }

    // epilogue: write fp32 C
    #pragma unroll
    for (int mt = 0; mt < 4; mt++) {
        int r0 = l0 + wm * 64 + mt * 16 + (lane >> 2);
        #pragma unroll
        for (int nt = 0; nt < 4; nt++) {
            int cc = n0 + wn * 32 + nt * 8 + 2 * (lane & 3);
            float2 v0 = {acc[mt][nt][0], acc[mt][nt][1]};
            float2 v1 = {acc[mt][nt][2], acc[mt][nt][3]};
            *(float2*)&d_xz[(long)r0 * (2 * DIN) + cc]       = v0;
            *(float2*)&d_xz[(long)(r0 + 8) * (2 * DIN) + cc] = v1;
        }
    }
}

// -------- K3: causal depthwise conv(4) + silu, g = silu(z)*w*inv -------------
__global__ void k_conv(const float* __restrict__ convw,
                       const float* __restrict__ convb,
                       const float* __restrict__ Dvec) {
    float local = 0.0f;
    int total = LSEQ * DIN;
    for (int idx = blockIdx.x * blockDim.x + threadIdx.x; idx < total;
         idx += gridDim.x * blockDim.x) {
        int l  = idx / DIN;
        int ch = idx - l * DIN;
        float s = convb[ch];
        #pragma unroll
        for (int k = 0; k < 4; k++) {
            int lk = l - 3 + k;
            if (lk >= 0) s += convw[ch * 4 + k] * d_xz[lk * (2 * DIN) + ch];
        }
        float xsv = siluf(s);
        float zv  = d_xz[l * (2 * DIN) + DIN + ch];
        float gv  = siluf(zv) * d_wsum[ch] * INV_LM;
        d_xs[idx] = xsv;
        d_g[idx]  = gv;
        local += xsv * Dvec[ch] * gv;
    }
    float tot = blockReduceSum(local);
    if (threadIdx.x == 0) d_part_conv[blockIdx.x] = tot;
}

// ---------------- K4: GEMM2  dbc[l,j] = sum_ch xs[l,ch]*xpw[j,ch] ------------
__global__ void k_gemm2(const float* __restrict__ xpw) {
    __shared__ __align__(16) float sx[32][64];
    __shared__ __align__(16) float sw[80][64];
    int t  = threadIdx.x;
    int l0 = blockIdx.x * 32;
    int tx = t & 15;
    int ty = t >> 4;
    float acc[2][5];
    #pragma unroll
    for (int i = 0; i < 2; i++)
        #pragma unroll
        for (int j = 0; j < 5; j++) acc[i][j] = 0.0f;

    for (int k0 = 0; k0 < DIN; k0 += 64) {
        #pragma unroll
        for (int p = t; p < 512; p += 256) {
            int li = p >> 4;
            int kv = (p & 15) * 4;
            *(float4*)&sx[li][kv] = *(const float4*)&d_xs[(l0 + li) * DIN + k0 + kv];
        }
        for (int p = t; p < 1280; p += 256) {
            int j  = p >> 4;
            int kv = (p & 15) * 4;
            *(float4*)&sw[j][kv] = *(const float4*)&xpw[j * DIN + k0 + kv];
        }
        __syncthreads();
        #pragma unroll
        for (int k4 = 0; k4 < 16; k4++) {
            float4 a0 = *(float4*)&sx[ty * 2][k4 * 4];
            float4 a1 = *(float4*)&sx[ty * 2 + 1][k4 * 4];
            #pragma unroll
            for (int jj = 0; jj < 5; jj++) {
                float4 w = *(float4*)&sw[tx + 16 * jj][k4 * 4];
                acc[0][jj] += a0.x * w.x + a0.y * w.y + a0.z * w.z + a0.w * w.w;
                acc[1][jj] += a1.x * w.x + a1.y * w.y + a1.z * w.z + a1.w * w.w;
            }
        }
        __syncthreads();
    }
    #pragma unroll
    for (int i = 0; i < 2; i++)
        #pragma unroll
        for (int jj = 0; jj < 5; jj++)
            d_dbc[(l0 + ty * 2 + i) * NCOL + tx + 16 * jj] = acc[i][jj];
}

// ---------------- K5: dt = softplus(dbc[:, :48] @ dtw^T + b) -----------------
__global__ void k_dt(const float* __restrict__ dtw,
                     const float* __restrict__ dtb) {
    __shared__ float sdbc[128][48];
    int t  = threadIdx.x;
    int d  = blockIdx.x * 128 + t;
    int l0 = blockIdx.y * 128;
    float wr[48];
    #pragma unroll
    for (int r = 0; r < 48; r++) wr[r] = dtw[d * 48 + r];
    float bias = dtb[d];
    for (int p = t; p < 128 * 48; p += 128) {
        int li = p / 48;
        int r  = p - li * 48;
        sdbc[li][r] = d_dbc[(l0 + li) * NCOL + r];
    }
    __syncthreads();
    for (int li = 0; li < 128; li++) {
        float s = bias;
        #pragma unroll
        for (int r = 0; r < 48; r++) s += wr[r] * sdbc[li][r];
        float sp = (s > 20.0f) ? s : log1pf(__expf(s));
        d_dt[(l0 + li) * DIN + d] = sp;
    }
}

// ---------------- K6: scan pass 1 -------------------------------------------
__global__ void k_scan1(const float* __restrict__ A_log) {
    int t    = threadIdx.x;
    int s    = t & 15;
    int dloc = t >> 4;
    int d    = blockIdx.x * 16 + dloc;
    int c    = blockIdx.y;
    float Av = -__expf(A_log[d * DST + s]);
    float h = 0.0f, cp = 1.0f, acc = 0.0f, Kacc = 0.0f;
    int base = c * CHLEN;
    #pragma unroll 4
    for (int i = 0; i < CHLEN; i++) {
        int l = base + i;
        float dtv = d_dt[l * DIN + d];
        float xsv = d_xs[l * DIN + d];
        float gv  = d_g [l * DIN + d];
        float Bv  = d_dbc[l * NCOL + RNK + s];
        float Cv  = d_dbc[l * NCOL + RNK + DST + s];
        float dA  = __expf(dtv * Av);
        cp *= dA;
        h = dA * h + dtv * Bv * xsv;
        float cg = Cv * gv;
        acc  += h  * cg;
        Kacc += cp * cg;
    }
    int off = (c * DIN + d) * DST + s;
    d_P[off]  = cp;
    d_E[off]  = h;
    d_Kc[off] = Kacc;
    float tot = blockReduceSum(acc);
    if (t == 0) d_part_scan[blockIdx.y * 96 + blockIdx.x] = tot;
}

// ---------------- K7: scan pass 2 -------------------------------------------
__global__ void k_scan2() {
    int gid = blockIdx.x * 256 + threadIdx.x;
    float h = 0.0f, St = 0.0f;
    for (int c = 0; c < NCHUNK; c++) {
        int off = c * (DIN * DST) + gid;
        St += d_Kc[off] * h;
        h   = d_P[off] * h + d_E[off];
    }
    float tot = blockReduceSum(St);
    if (threadIdx.x == 0) d_part_p2[blockIdx.x] = tot;
}

// ---------------- K8: final reduce ------------------------------------------
__global__ void k_final(float* __restrict__ out) {
    int t = threadIdx.x;
    float v = 0.0f;
    for (int i = t; i < 1024; i += 256)         v += d_part_conv[i];
    for (int i = t; i < NCHUNK * 96; i += 256)  v += d_part_scan[i];
    for (int i = t; i < 96; i += 256)           v += d_part_p2[i];
    float tot = blockReduceSum(v);
    if (t == 0) out[0] = tot;
}

// ---------------- launch -----------------------------------------------------
extern "C" void kernel_launch(void* const* d_in, const int* in_sizes, int n_in,
                              void* d_out, int out_size) {
    const float* x     = (const float*)d_in[0];
    const float* w_in  = (const float*)d_in[1];
    const float* convw = (const float*)d_in[2];
    const float* convb = (const float*)d_in[3];
    const float* xpw   = (const float*)d_in[4];
    const float* dtw   = (const float*)d_in[5];
    const float* dtb   = (const float*)d_in[6];
    const float* A_log = (const float*)d_in[7];
    const float* Dvec  = (const float*)d_in[8];
    const float* opw   = (const float*)d_in[9];
    float* out = (float*)d_out;

    static int configured = 0;
    if (!configured) {
        cudaFuncSetAttribute(k_gemm1_mma, cudaFuncAttributeMaxDynamicSharedMemorySize, G1_SMEM);
        configured = 1;
    }

    k_colsum<<<6, 256>>>(opw);
    k_patchify<<<(DMOD * LSEQ) / 256, 256>>>(x);
    k_wsplit<<<(2 * DIN * DMOD) / 256, 256>>>(w_in);
    k_gemm1_mma<<<dim3(2 * DIN / 128, LSEQ / 128), 256, G1_SMEM>>>();
    k_conv<<<1024, 256>>>(convw, convb, Dvec);
    k_gemm2<<<LSEQ / 32, 256>>>(xpw);
    k_dt<<<dim3(DIN / 128, LSEQ / 128), 128>>>(dtw, dtb);
    k_scan1<<<dim3(DIN / 16, NCHUNK), 256>>>(A_log);
    k_scan2<<<96, 256>>>();
    k_final<<<1, 256>>>(out);
}

// round 4
// speedup vs baseline: 1.8238x; 1.3896x over previous
#include <cuda_runtime.h>
#include <cuda_bf16.h>
#include <math.h>
#include <stdint.h>

#define LSEQ 4096
#define DMOD 768
#define DIN  1536
#define DST  16
#define RNK  48
#define NCOL 80
#define NCHUNK 64
#define CHLEN  64
#define INV_LM (1.0f / (4096.0f * 768.0f))

// ---------------- scratch ----------------------------------------------------
__device__ float d_wsum[DIN];
__device__ __nv_bfloat16 d_uhi[LSEQ * DMOD];
__device__ __nv_bfloat16 d_ulo[LSEQ * DMOD];
__device__ __nv_bfloat16 d_whi[2 * DIN * DMOD];
__device__ __nv_bfloat16 d_wlo[2 * DIN * DMOD];
__device__ float d_xz[LSEQ * 2 * DIN];
__device__ float d_xs[LSEQ * DIN];
__device__ float d_g [LSEQ * DIN];
__device__ float d_dt[LSEQ * DIN];
__device__ float d_dbc[LSEQ * NCOL];
__device__ float d_P [NCHUNK * DIN * DST];
__device__ float d_E [NCHUNK * DIN * DST];
__device__ float d_Kc[NCHUNK * DIN * DST];
__device__ float d_part_conv[1024];
__device__ float d_part_scan[NCHUNK * 6];
__device__ float d_part_p2[96];

__device__ __forceinline__ float siluf(float x) { return x / (1.0f + __expf(-x)); }

__device__ __forceinline__ float blockReduceSum(float v) {
    __shared__ float sh[32];
    int lane = threadIdx.x & 31;
    int w    = threadIdx.x >> 5;
    #pragma unroll
    for (int o = 16; o > 0; o >>= 1) v += __shfl_down_sync(0xffffffffu, v, o);
    if (lane == 0) sh[w] = v;
    __syncthreads();
    int nw = blockDim.x >> 5;
    v = (threadIdx.x < nw) ? sh[threadIdx.x] : 0.0f;
    if (w == 0) {
        #pragma unroll
        for (int o = 16; o > 0; o >>= 1) v += __shfl_down_sync(0xffffffffu, v, o);
    }
    return v;
}

// ---------------- asm helpers (sm_80-baseline) -------------------------------
__device__ __forceinline__ uint32_t smem_to_u32(const void* p) {
    uint32_t a;
    asm("{ .reg .u64 t; cvta.to.shared.u64 t, %1; cvt.u32.u64 %0, t; }" : "=r"(a) : "l"(p));
    return a;
}
#define CP16(sm, gp) \
    asm volatile("cp.async.cg.shared.global [%0], [%1], 16;" :: "r"(sm), "l"(gp))
#define CP_COMMIT() asm volatile("cp.async.commit_group;" ::: "memory")
#define CP_WAIT1()  asm volatile("cp.async.wait_group 1;" ::: "memory")

__device__ __forceinline__ void ldsm_x4(uint32_t& r0, uint32_t& r1, uint32_t& r2,
                                        uint32_t& r3, uint32_t addr) {
    asm volatile("ldmatrix.sync.aligned.m8n8.x4.shared.b16 {%0,%1,%2,%3}, [%4];"
                 : "=r"(r0), "=r"(r1), "=r"(r2), "=r"(r3) : "r"(addr));
}
__device__ __forceinline__ void mma16816(float* c, const uint32_t* a, const uint32_t* b) {
    asm volatile("mma.sync.aligned.m16n8k16.row.col.f32.bf16.bf16.f32 "
                 "{%0,%1,%2,%3}, {%4,%5,%6,%7}, {%8,%9}, {%0,%1,%2,%3};"
                 : "+f"(c[0]), "+f"(c[1]), "+f"(c[2]), "+f"(c[3])
                 : "r"(a[0]), "r"(a[1]), "r"(a[2]), "r"(a[3]), "r"(b[0]), "r"(b[1]));
}

// ---------------- K0: column sums of out_proj_w (parallel, deterministic) ----
__global__ void k_colsum(const float* __restrict__ opw) {
    __shared__ float sh[16][17];
    int t  = threadIdx.x;
    int dl = t & 15;
    int mg = t >> 4;           // 16 groups x 48 rows
    int d  = blockIdx.x * 16 + dl;
    float s = 0.0f;
    for (int m = mg * 48; m < mg * 48 + 48; m++) s += opw[m * DIN + d];
    sh[dl][mg] = s;
    __syncthreads();
    if (t < 16) {
        float tot = 0.0f;
        #pragma unroll
        for (int g = 0; g < 16; g++) tot += sh[t][g];
        d_wsum[blockIdx.x * 16 + t] = tot;
    }
}

// ---------------- K1: patchify -> u[l][k], split to bf16 hi/lo ---------------
__global__ void k_patchify(const float* __restrict__ x) {
    int idx = blockIdx.x * blockDim.x + threadIdx.x;  // l*768 + d
    if (idx >= DMOD * LSEQ) return;
    int l = idx / DMOD;
    int d = idx - l * DMOD;
    int c   = d >> 8;
    int r   = d & 255;
    int ih  = r >> 2;
    int iwq = r & 3;
    int iwr = l >> 8;
    int rest = l & 255;
    int a = rest >> 4;
    int b = rest & 15;
    int iw = iwq * 16 + iwr;
    float v = x[c * 1048576 + (ih * 16 + a) * 1024 + iw * 16 + b];
    __nv_bfloat16 hi = __float2bfloat16(v);
    __nv_bfloat16 lo = __float2bfloat16(v - __bfloat162float(hi));
    d_uhi[idx] = hi;
    d_ulo[idx] = lo;
}

// ---------------- K1b: split in_proj_w to bf16 hi/lo -------------------------
__global__ void k_wsplit(const float* __restrict__ w) {
    int idx = blockIdx.x * blockDim.x + threadIdx.x;
    if (idx >= 2 * DIN * DMOD) return;
    float v = w[idx];
    __nv_bfloat16 hi = __float2bfloat16(v);
    __nv_bfloat16 lo = __float2bfloat16(v - __bfloat162float(hi));
    d_whi[idx] = hi;
    d_wlo[idx] = lo;
}

// ---------------- K2: GEMM1 via mma.sync bf16, 3-stage pipeline --------------
#define G1_TILE   10240                 // 128 rows * 80 B
#define G1_STAGE  (4 * G1_TILE)         // Ahi, Alo, Bhi, Blo = 40960 B
#define G1_SMEM   (3 * G1_STAGE)        // 122880 B
#define G1_ITERS  24                    // 768 / 32

__device__ __forceinline__ void g1_prefetch(uint32_t sbase, int stage, int k0,
                                            int l0, int n0, int t) {
    const uint32_t so = sbase + stage * G1_STAGE;
    const int prow = t >> 2;
    const int pq   = t & 3;
    #pragma unroll
    for (int rep = 0; rep < 2; rep++) {
        int row = prow + rep * 64;
        uint32_t soff = (uint32_t)(row * 80 + pq * 16);
        long ga = (long)(l0 + row) * DMOD + k0 + pq * 8;
        long gb = (long)(n0 + row) * DMOD + k0 + pq * 8;
        CP16(so + soff,               (const void*)(d_uhi + ga));
        CP16(so + G1_TILE + soff,     (const void*)(d_ulo + ga));
        CP16(so + 2 * G1_TILE + soff, (const void*)(d_whi + gb));
        CP16(so + 3 * G1_TILE + soff, (const void*)(d_wlo + gb));
    }
}

__global__ void __launch_bounds__(256, 1) k_gemm1_mma() {
    extern __shared__ char smem[];
    const uint32_t sbase = smem_to_u32(smem);
    const int t    = threadIdx.x;
    const int lane = t & 31;
    const int wid  = t >> 5;
    const int wm   = wid >> 2;      // 0..1
    const int wn   = wid & 3;       // 0..3
    const int n0   = blockIdx.x * 128;
    const int l0   = blockIdx.y * 128;

    float acc[4][4][4];
    #pragma unroll
    for (int i = 0; i < 4; i++)
        #pragma unroll
        for (int j = 0; j < 4; j++)
            #pragma unroll
            for (int q = 0; q < 4; q++) acc[i][j][q] = 0.0f;

    g1_prefetch(sbase, 0, 0, l0, n0, t);
    CP_COMMIT();
    g1_prefetch(sbase, 1, 32, l0, n0, t);
    CP_COMMIT();

    for (int c = 0; c < G1_ITERS; c++) {
        CP_WAIT1();
        __syncthreads();
        if (c + 2 < G1_ITERS)
            g1_prefetch(sbase, (c + 2) % 3, (c + 2) * 32, l0, n0, t);
        CP_COMMIT();

        const uint32_t so = sbase + (c % 3) * G1_STAGE;
        #pragma unroll
        for (int kk = 0; kk < 2; kk++) {
            uint32_t a_hi[4][4], a_lo[4][4];
            const int arow = wm * 64 + (lane & 15);
            const int acol = kk * 16 + ((lane >> 4) << 3);
            #pragma unroll
            for (int mt = 0; mt < 4; mt++) {
                uint32_t addr = so + (uint32_t)((arow + mt * 16) * 80 + acol * 2);
                ldsm_x4(a_hi[mt][0], a_hi[mt][1], a_hi[mt][2], a_hi[mt][3], addr);
                ldsm_x4(a_lo[mt][0], a_lo[mt][1], a_lo[mt][2], a_lo[mt][3], addr + G1_TILE);
            }
            uint32_t b_hi[4][2], b_lo[4][2];
            const int g = lane >> 3;
            const int brow = wn * 32 + ((g >> 1) << 3) + (lane & 7);
            const int bcol = kk * 16 + ((g & 1) << 3);
            #pragma unroll
            for (int np = 0; np < 2; np++) {
                uint32_t addr = so + 2 * G1_TILE
                              + (uint32_t)((brow + np * 16) * 80 + bcol * 2);
                ldsm_x4(b_hi[2 * np][0], b_hi[2 * np][1],
                        b_hi[2 * np + 1][0], b_hi[2 * np + 1][1], addr);
                ldsm_x4(b_lo[2 * np][0], b_lo[2 * np][1],
                        b_lo[2 * np + 1][0], b_lo[2 * np + 1][1], addr + G1_TILE);
            }
            #pragma unroll
            for (int mt = 0; mt < 4; mt++)
                #pragma unroll
                for (int nt = 0; nt < 4; nt++) {
                    mma16816(acc[mt][nt], a_hi[mt], b_hi[nt]);
                    mma16816(acc[mt][nt], a_lo[mt], b_hi[nt]);
                    mma16816(acc[mt][nt], a_hi[mt], b_lo[nt]);
                }
        }
    }

    #pragma unroll
    for (int mt = 0; mt < 4; mt++) {
        int r0 = l0 + wm * 64 + mt * 16 + (lane >> 2);
        #pragma unroll
        for (int nt = 0; nt < 4; nt++) {
            int cc = n0 + wn * 32 + nt * 8 + 2 * (lane & 3);
            float2 v0 = {acc[mt][nt][0], acc[mt][nt][1]};
            float2 v1 = {acc[mt][nt][2], acc[mt][nt][3]};
            *(float2*)&d_xz[(long)r0 * (2 * DIN) + cc]       = v0;
            *(float2*)&d_xz[(long)(r0 + 8) * (2 * DIN) + cc] = v1;
        }
    }
}

// -------- K3: causal depthwise conv(4) + silu (x4-channel vectorized) --------
__global__ void k_conv(const float* __restrict__ convw,
                       const float* __restrict__ convb,
                       const float* __restrict__ Dvec) {
    float local = 0.0f;
    const int total4 = LSEQ * (DIN / 4);
    for (int idx = blockIdx.x * blockDim.x + threadIdx.x; idx < total4;
         idx += gridDim.x * blockDim.x) {
        int l   = idx / (DIN / 4);
        int q   = idx - l * (DIN / 4);
        int ch0 = q * 4;
        float4 bia = *(const float4*)&convb[ch0];
        float s[4] = {bia.x, bia.y, bia.z, bia.w};
        float w4[4][4];
        #pragma unroll
        for (int j = 0; j < 4; j++) {
            float4 w = *(const float4*)&convw[(ch0 + j) * 4];
            w4[j][0] = w.x; w4[j][1] = w.y; w4[j][2] = w.z; w4[j][3] = w.w;
        }
        #pragma unroll
        for (int k = 0; k < 4; k++) {
            int lk = l - 3 + k;
            if (lk >= 0) {
                float4 v = *(const float4*)&d_xz[(long)lk * (2 * DIN) + ch0];
                s[0] += w4[0][k] * v.x;
                s[1] += w4[1][k] * v.y;
                s[2] += w4[2][k] * v.z;
                s[3] += w4[3][k] * v.w;
            }
        }
        float4 zv = *(const float4*)&d_xz[(long)l * (2 * DIN) + DIN + ch0];
        float4 ws = *(const float4*)&d_wsum[ch0];
        float4 Dv = *(const float4*)&Dvec[ch0];
        float xs0 = siluf(s[0]), xs1 = siluf(s[1]), xs2 = siluf(s[2]), xs3 = siluf(s[3]);
        float g0 = siluf(zv.x) * ws.x * INV_LM;
        float g1 = siluf(zv.y) * ws.y * INV_LM;
        float g2 = siluf(zv.z) * ws.z * INV_LM;
        float g3 = siluf(zv.w) * ws.w * INV_LM;
        float4 xso = {xs0, xs1, xs2, xs3};
        float4 go  = {g0, g1, g2, g3};
        *(float4*)&d_xs[(long)l * DIN + ch0] = xso;
        *(float4*)&d_g [(long)l * DIN + ch0] = go;
        local += xs0 * Dv.x * g0 + xs1 * Dv.y * g1 + xs2 * Dv.z * g2 + xs3 * Dv.w * g3;
    }
    float tot = blockReduceSum(local);
    if (threadIdx.x == 0) d_part_conv[blockIdx.x] = tot;
}

// ---------------- K4: GEMM2  dbc[l,j] = sum_ch xs[l,ch]*xpw[j,ch] ------------
// 32 l per block, 128 threads: tx(16 j-lanes) x ty(8): thread tile 4l x 5j
__global__ void k_gemm2(const float* __restrict__ xpw) {
    __shared__ __align__(16) float sx[32][68];
    __shared__ __align__(16) float sw[80][68];
    int t  = threadIdx.x;
    int l0 = blockIdx.x * 32;
    int tx = t & 15;
    int ty = t >> 4;       // 0..7 -> l = ty*4 + i
    float acc[4][5];
    #pragma unroll
    for (int i = 0; i < 4; i++)
        #pragma unroll
        for (int j = 0; j < 5; j++) acc[i][j] = 0.0f;

    for (int k0 = 0; k0 < DIN; k0 += 64) {
        #pragma unroll
        for (int p = t; p < 512; p += 128) {           // 32 x 16 float4
            int li = p >> 4;
            int kv = (p & 15) * 4;
            *(float4*)&sx[li][kv] = *(const float4*)&d_xs[(l0 + li) * DIN + k0 + kv];
        }
        #pragma unroll
        for (int p = t; p < 1280; p += 128) {          // 80 x 16 float4
            int j  = p >> 4;
            int kv = (p & 15) * 4;
            *(float4*)&sw[j][kv] = *(const float4*)&xpw[j * DIN + k0 + kv];
        }
        __syncthreads();
        #pragma unroll
        for (int k4 = 0; k4 < 16; k4++) {
            float4 a[4];
            #pragma unroll
            for (int i = 0; i < 4; i++) a[i] = *(float4*)&sx[ty * 4 + i][k4 * 4];
            #pragma unroll
            for (int jj = 0; jj < 5; jj++) {
                float4 w = *(float4*)&sw[tx + 16 * jj][k4 * 4];
                #pragma unroll
                for (int i = 0; i < 4; i++)
                    acc[i][jj] += a[i].x * w.x + a[i].y * w.y + a[i].z * w.z + a[i].w * w.w;
            }
        }
        __syncthreads();
    }
    #pragma unroll
    for (int i = 0; i < 4; i++)
        #pragma unroll
        for (int jj = 0; jj < 5; jj++)
            d_dbc[(l0 + ty * 4 + i) * NCOL + tx + 16 * jj] = acc[i][jj];
}

// ---------------- K5: dt = softplus(dbc[:, :48] @ dtw^T + b) -----------------
__global__ void k_dt(const float* __restrict__ dtw,
                     const float* __restrict__ dtb) {
    __shared__ float sdbc[128][48];
    int t  = threadIdx.x;
    int d  = blockIdx.x * 128 + t;
    int l0 = blockIdx.y * 128;
    float wr[48];
    #pragma unroll
    for (int r = 0; r < 48; r++) wr[r] = dtw[d * 48 + r];
    float bias = dtb[d];
    for (int p = t; p < 128 * 48; p += 128) {
        int li = p / 48;
        int r  = p - li * 48;
        sdbc[li][r] = d_dbc[(l0 + li) * NCOL + r];
    }
    __syncthreads();
    for (int li = 0; li < 128; li++) {
        float s = bias;
        #pragma unroll
        for (int r = 0; r < 48; r++) s += wr[r] * sdbc[li][r];
        float sp = (s > 20.0f) ? s : log1pf(__expf(s));
        d_dt[(l0 + li) * DIN + d] = sp;
    }
}

// ---------------- K6: scan pass 1 — one thread owns all 16 states of one d ---
__global__ void k_scan1(const float* __restrict__ A_log) {
    __shared__ __align__(16) float sB[CHLEN][DST];
    __shared__ __align__(16) float sC[CHLEN][DST];
    int t = threadIdx.x;
    int d = blockIdx.x * 256 + t;
    int c = blockIdx.y;
    int base = c * CHLEN;
    for (int p = t; p < CHLEN * DST; p += 256) {
        int r = p >> 4, s = p & 15;
        sB[r][s] = d_dbc[(base + r) * NCOL + RNK + s];
        sC[r][s] = d_dbc[(base + r) * NCOL + RNK + DST + s];
    }
    __syncthreads();

    float Av[DST];
    #pragma unroll
    for (int s = 0; s < DST; s++) Av[s] = -__expf(A_log[d * DST + s]);
    bool fast = true;
    #pragma unroll
    for (int s = 1; s < DST; s++) {
        float r = Av[s] / Av[0];
        fast = fast && (fabsf(r - (float)(s + 1)) < 1e-3f);
    }

    float h[DST], cp[DST], K[DST];
    #pragma unroll
    for (int s = 0; s < DST; s++) { h[s] = 0.0f; cp[s] = 1.0f; K[s] = 0.0f; }
    float acc = 0.0f;

    for (int i = 0; i < CHLEN; i++) {
        int l = base + i;
        float dtv = d_dt[(long)l * DIN + d];
        float xsv = d_xs[(long)l * DIN + d];
        float gv  = d_g [(long)l * DIN + d];
        float dtx = dtv * xsv;
        float E = __expf(dtv * Av[0]);
        float p = 1.0f;
        #pragma unroll
        for (int s = 0; s < DST; s++) {
            float dA;
            if (fast) { p *= E; dA = p; }
            else      { dA = __expf(dtv * Av[s]); }
            cp[s] *= dA;
            h[s] = dA * h[s] + dtx * sB[i][s];
            float cg = sC[i][s] * gv;
            acc  += h[s] * cg;
            K[s] += cp[s] * cg;
        }
    }
    long off = ((long)c * DIN + d) * DST;
    #pragma unroll
    for (int s = 0; s < DST; s++) {
        d_P [off + s] = cp[s];
        d_E [off + s] = h[s];
        d_Kc[off + s] = K[s];
    }
    float tot = blockReduceSum(acc);
    if (t == 0) d_part_scan[c * 6 + blockIdx.x] = tot;
}

// ---------------- K7: scan pass 2 (chunk combine) ----------------------------
__global__ void k_scan2() {
    int gid = blockIdx.x * 256 + threadIdx.x;   // d*16+s
    float h = 0.0f, St = 0.0f;
    for (int c = 0; c < NCHUNK; c++) {
        long off = (long)c * (DIN * DST) + gid;
        St += d_Kc[off] * h;
        h   = d_P[off] * h + d_E[off];
    }
    float tot = blockReduceSum(St);
    if (threadIdx.x == 0) d_part_p2[blockIdx.x] = tot;
}

// ---------------- K8: deterministic final reduce -----------------------------
__global__ void k_final(float* __restrict__ out) {
    int t = threadIdx.x;
    float v = 0.0f;
    for (int i = t; i < 1024; i += 256)          v += d_part_conv[i];
    for (int i = t; i < NCHUNK * 6; i += 256)    v += d_part_scan[i];
    for (int i = t; i < 96; i += 256)            v += d_part_p2[i];
    float tot = blockReduceSum(v);
    if (t == 0) out[0] = tot;
}

// ---------------- launch -----------------------------------------------------
extern "C" void kernel_launch(void* const* d_in, const int* in_sizes, int n_in,
                              void* d_out, int out_size) {
    const float* x     = (const float*)d_in[0];
    const float* w_in  = (const float*)d_in[1];
    const float* convw = (const float*)d_in[2];
    const float* convb = (const float*)d_in[3];
    const float* xpw   = (const float*)d_in[4];
    const float* dtw   = (const float*)d_in[5];
    const float* dtb   = (const float*)d_in[6];
    const float* A_log = (const float*)d_in[7];
    const float* Dvec  = (const float*)d_in[8];
    const float* opw   = (const float*)d_in[9];
    float* out = (float*)d_out;

    static int configured = 0;
    if (!configured) {
        cudaFuncSetAttribute(k_gemm1_mma, cudaFuncAttributeMaxDynamicSharedMemorySize, G1_SMEM);
        configured = 1;
    }

    k_colsum<<<DIN / 16, 256>>>(opw);
    k_patchify<<<(DMOD * LSEQ) / 256, 256>>>(x);
    k_wsplit<<<(2 * DIN * DMOD) / 256, 256>>>(w_in);
    k_gemm1_mma<<<dim3(2 * DIN / 128, LSEQ / 128), 256, G1_SMEM>>>();
    k_conv<<<1024, 256>>>(convw, convb, Dvec);
    k_gemm2<<<LSEQ / 32, 128>>>(xpw);
    k_dt<<<dim3(DIN / 128, LSEQ / 128), 128>>>(dtw, dtb);
    k_scan1<<<dim3(DIN / 256, NCHUNK), 256>>>(A_log);
    k_scan2<<<96, 256>>>();
    k_final<<<1, 256>>>(out);
}

// round 5
// speedup vs baseline: 2.0298x; 1.1129x over previous
#include <cuda_runtime.h>
#include <cuda_bf16.h>
#include <math.h>
#include <stdint.h>

#define LSEQ 4096
#define DMOD 768
#define DIN  1536
#define DST  16
#define RNK  48
#define NCOL 80
#define NCHUNK 64
#define CHLEN  64
#define INV_LM (1.0f / (4096.0f * 768.0f))

// ---------------- scratch ----------------------------------------------------
__device__ float d_wsum[DIN];
__device__ __nv_bfloat16 d_uhi[LSEQ * DMOD];
__device__ __nv_bfloat16 d_ulo[LSEQ * DMOD];
__device__ __nv_bfloat16 d_whi[2 * DIN * DMOD];
__device__ __nv_bfloat16 d_wlo[2 * DIN * DMOD];
__device__ float d_xz[LSEQ * 2 * DIN];
__device__ float d_xs[LSEQ * DIN];
__device__ float d_g [LSEQ * DIN];
__device__ float d_dt[LSEQ * DIN];
__device__ float d_dbc[LSEQ * NCOL];
__device__ float d_P [NCHUNK * DIN * DST];
__device__ float d_E [NCHUNK * DIN * DST];
__device__ float d_Kc[NCHUNK * DIN * DST];
__device__ float d_part_conv[1536];
__device__ float d_part_scan[NCHUNK * 6];
__device__ float d_part_p2[96];

__device__ __forceinline__ float siluf(float x) { return x / (1.0f + __expf(-x)); }

__device__ __forceinline__ float blockReduceSum(float v) {
    __shared__ float sh[32];
    int lane = threadIdx.x & 31;
    int w    = threadIdx.x >> 5;
    #pragma unroll
    for (int o = 16; o > 0; o >>= 1) v += __shfl_down_sync(0xffffffffu, v, o);
    if (lane == 0) sh[w] = v;
    __syncthreads();
    int nw = blockDim.x >> 5;
    v = (threadIdx.x < nw) ? sh[threadIdx.x] : 0.0f;
    if (w == 0) {
        #pragma unroll
        for (int o = 16; o > 0; o >>= 1) v += __shfl_down_sync(0xffffffffu, v, o);
    }
    return v;
}

// ---------------- asm helpers (sm_80-baseline) -------------------------------
__device__ __forceinline__ uint32_t smem_to_u32(const void* p) {
    uint32_t a;
    asm("{ .reg .u64 t; cvta.to.shared.u64 t, %1; cvt.u32.u64 %0, t; }" : "=r"(a) : "l"(p));
    return a;
}
#define CP16(sm, gp) \
    asm volatile("cp.async.cg.shared.global [%0], [%1], 16;" :: "r"(sm), "l"(gp))
#define CP_COMMIT() asm volatile("cp.async.commit_group;" ::: "memory")
#define CP_WAIT1()  asm volatile("cp.async.wait_group 1;" ::: "memory")

__device__ __forceinline__ void ldsm_x4(uint32_t& r0, uint32_t& r1, uint32_t& r2,
                                        uint32_t& r3, uint32_t addr) {
    asm volatile("ldmatrix.sync.aligned.m8n8.x4.shared.b16 {%0,%1,%2,%3}, [%4];"
                 : "=r"(r0), "=r"(r1), "=r"(r2), "=r"(r3) : "r"(addr));
}
__device__ __forceinline__ void mma16816(float* c, const uint32_t* a, const uint32_t* b) {
    asm volatile("mma.sync.aligned.m16n8k16.row.col.f32.bf16.bf16.f32 "
                 "{%0,%1,%2,%3}, {%4,%5,%6,%7}, {%8,%9}, {%0,%1,%2,%3};"
                 : "+f"(c[0]), "+f"(c[1]), "+f"(c[2]), "+f"(c[3])
                 : "r"(a[0]), "r"(a[1]), "r"(a[2]), "r"(a[3]), "r"(b[0]), "r"(b[1]));
}

// ---------------- K0: column sums of out_proj_w ------------------------------
__global__ void k_colsum(const float* __restrict__ opw) {
    __shared__ float sh[16][17];
    int t  = threadIdx.x;
    int dl = t & 15;
    int mg = t >> 4;
    int d  = blockIdx.x * 16 + dl;
    float s = 0.0f;
    for (int m = mg * 48; m < mg * 48 + 48; m++) s += opw[m * DIN + d];
    sh[dl][mg] = s;
    __syncthreads();
    if (t < 16) {
        float tot = 0.0f;
        #pragma unroll
        for (int g = 0; g < 16; g++) tot += sh[t][g];
        d_wsum[blockIdx.x * 16 + t] = tot;
    }
}

// ---------------- K1: patchify -> u[l][k], split to bf16 hi/lo ---------------
__global__ void k_patchify(const float* __restrict__ x) {
    int idx = blockIdx.x * blockDim.x + threadIdx.x;
    if (idx >= DMOD * LSEQ) return;
    int l = idx / DMOD;
    int d = idx - l * DMOD;
    int c   = d >> 8;
    int r   = d & 255;
    int ih  = r >> 2;
    int iwq = r & 3;
    int iwr = l >> 8;
    int rest = l & 255;
    int a = rest >> 4;
    int b = rest & 15;
    int iw = iwq * 16 + iwr;
    float v = x[c * 1048576 + (ih * 16 + a) * 1024 + iw * 16 + b];
    __nv_bfloat16 hi = __float2bfloat16(v);
    __nv_bfloat16 lo = __float2bfloat16(v - __bfloat162float(hi));
    d_uhi[idx] = hi;
    d_ulo[idx] = lo;
}

// ---------------- K1b: split in_proj_w ---------------------------------------
__global__ void k_wsplit(const float* __restrict__ w) {
    int idx = blockIdx.x * blockDim.x + threadIdx.x;
    if (idx >= 2 * DIN * DMOD) return;
    float v = w[idx];
    __nv_bfloat16 hi = __float2bfloat16(v);
    __nv_bfloat16 lo = __float2bfloat16(v - __bfloat162float(hi));
    d_whi[idx] = hi;
    d_wlo[idx] = lo;
}

// ---------------- K2: GEMM1 via mma.sync bf16, 2-stage, 2 CTA/SM -------------
#define G1_TILE   10240                 // 128 rows * 80 B
#define G1_STAGE  (4 * G1_TILE)         // Ahi, Alo, Bhi, Blo = 40960 B
#define G1_SMEM   (2 * G1_STAGE)        // 81920 B
#define G1_ITERS  24                    // 768 / 32

__device__ __forceinline__ void g1_prefetch(uint32_t sbase, int stage, int k0,
                                            int l0, int n0, int t) {
    const uint32_t so = sbase + stage * G1_STAGE;
    const int prow = t >> 2;
    const int pq   = t & 3;
    #pragma unroll
    for (int rep = 0; rep < 2; rep++) {
        int row = prow + rep * 64;
        uint32_t soff = (uint32_t)(row * 80 + pq * 16);
        long ga = (long)(l0 + row) * DMOD + k0 + pq * 8;
        long gb = (long)(n0 + row) * DMOD + k0 + pq * 8;
        CP16(so + soff,               (const void*)(d_uhi + ga));
        CP16(so + G1_TILE + soff,     (const void*)(d_ulo + ga));
        CP16(so + 2 * G1_TILE + soff, (const void*)(d_whi + gb));
        CP16(so + 3 * G1_TILE + soff, (const void*)(d_wlo + gb));
    }
}

__global__ void __launch_bounds__(256, 2) k_gemm1_mma() {
    extern __shared__ char smem[];
    const uint32_t sbase = smem_to_u32(smem);
    const int t    = threadIdx.x;
    const int lane = t & 31;
    const int wid  = t >> 5;
    const int wm   = wid >> 2;      // 0..1
    const int wn   = wid & 3;       // 0..3
    const int n0   = blockIdx.x * 128;
    const int l0   = blockIdx.y * 128;

    float acc[4][4][4];
    #pragma unroll
    for (int i = 0; i < 4; i++)
        #pragma unroll
        for (int j = 0; j < 4; j++)
            #pragma unroll
            for (int q = 0; q < 4; q++) acc[i][j][q] = 0.0f;

    g1_prefetch(sbase, 0, 0, l0, n0, t);
    CP_COMMIT();

    for (int c = 0; c < G1_ITERS; c++) {
        // prefetch next stage (buffer was consumed in iter c-1; sync at end of
        // prev iteration protects it)
        if (c + 1 < G1_ITERS)
            g1_prefetch(sbase, (c + 1) & 1, (c + 1) * 32, l0, n0, t);
        CP_COMMIT();
        CP_WAIT1();            // group c complete, group c+1 may be in flight
        __syncthreads();

        const uint32_t so = sbase + (c & 1) * G1_STAGE;
        #pragma unroll
        for (int kk = 0; kk < 2; kk++) {
            const int arow = wm * 64 + (lane & 15);
            const int acol = kk * 16 + ((lane >> 4) << 3);
            const int g = lane >> 3;
            const int brow = wn * 32 + ((g >> 1) << 3) + (lane & 7);
            const int bcol = kk * 16 + ((g & 1) << 3);

            uint32_t a_hi[4][4];
            #pragma unroll
            for (int mt = 0; mt < 4; mt++) {
                uint32_t addr = so + (uint32_t)((arow + mt * 16) * 80 + acol * 2);
                ldsm_x4(a_hi[mt][0], a_hi[mt][1], a_hi[mt][2], a_hi[mt][3], addr);
            }
            uint32_t b_hi[4][2], b_lo[4][2];
            #pragma unroll
            for (int np = 0; np < 2; np++) {
                uint32_t addr = so + 2 * G1_TILE
                              + (uint32_t)((brow + np * 16) * 80 + bcol * 2);
                ldsm_x4(b_hi[2 * np][0], b_hi[2 * np][1],
                        b_hi[2 * np + 1][0], b_hi[2 * np + 1][1], addr);
                ldsm_x4(b_lo[2 * np][0], b_lo[2 * np][1],
                        b_lo[2 * np + 1][0], b_lo[2 * np + 1][1], addr + G1_TILE);
            }
            // term 1: Ahi * Bhi — 16 independent MMAs
            #pragma unroll
            for (int mt = 0; mt < 4; mt++)
                #pragma unroll
                for (int nt = 0; nt < 4; nt++)
                    mma16816(acc[mt][nt], a_hi[mt], b_hi[nt]);
            // term 2: Ahi * Blo
            #pragma unroll
            for (int mt = 0; mt < 4; mt++)
                #pragma unroll
                for (int nt = 0; nt < 4; nt++)
                    mma16816(acc[mt][nt], a_hi[mt], b_lo[nt]);
            // term 3: Alo * Bhi (a_hi dead, b_lo dead -> low liveness)
            uint32_t a_lo[4][4];
            #pragma unroll
            for (int mt = 0; mt < 4; mt++) {
                uint32_t addr = so + G1_TILE
                              + (uint32_t)((arow + mt * 16) * 80 + acol * 2);
                ldsm_x4(a_lo[mt][0], a_lo[mt][1], a_lo[mt][2], a_lo[mt][3], addr);
            }
            #pragma unroll
            for (int mt = 0; mt < 4; mt++)
                #pragma unroll
                for (int nt = 0; nt < 4; nt++)
                    mma16816(acc[mt][nt], a_lo[mt], b_hi[nt]);
        }
        __syncthreads();   // all warps done reading stage c before it is refilled
    }

    #pragma unroll
    for (int mt = 0; mt < 4; mt++) {
        int r0 = l0 + wm * 64 + mt * 16 + (lane >> 2);
        #pragma unroll
        for (int nt = 0; nt < 4; nt++) {
            int cc = n0 + wn * 32 + nt * 8 + 2 * (lane & 3);
            float2 v0 = {acc[mt][nt][0], acc[mt][nt][1]};
            float2 v1 = {acc[mt][nt][2], acc[mt][nt][3]};
            *(float2*)&d_xz[(long)r0 * (2 * DIN) + cc]       = v0;
            *(float2*)&d_xz[(long)(r0 + 8) * (2 * DIN) + cc] = v1;
        }
    }
}

// -------- K3: causal depthwise conv(4) + silu, 4l x 4ch tile per thread ------
__global__ void k_conv(const float* __restrict__ convw,
                       const float* __restrict__ convb,
                       const float* __restrict__ Dvec) {
    int idx = blockIdx.x * blockDim.x + threadIdx.x;   // (LSEQ/4)*(DIN/4)
    int lq  = idx / (DIN / 4);
    int q   = idx - lq * (DIN / 4);
    int ch0 = q * 4;
    int l0  = lq * 4;

    float4 bia = *(const float4*)&convb[ch0];
    float w4[4][4];
    #pragma unroll
    for (int j = 0; j < 4; j++) {
        float4 w = *(const float4*)&convw[(ch0 + j) * 4];
        w4[j][0] = w.x; w4[j][1] = w.y; w4[j][2] = w.z; w4[j][3] = w.w;
    }
    float4 ws = *(const float4*)&d_wsum[ch0];
    float4 Dv = *(const float4*)&Dvec[ch0];

    float4 r[7];
    #pragma unroll
    for (int k = 0; k < 7; k++) {
        int lk = l0 - 3 + k;
        if (lk >= 0) r[k] = *(const float4*)&d_xz[(long)lk * (2 * DIN) + ch0];
        else         r[k] = make_float4(0.f, 0.f, 0.f, 0.f);
    }
    float local = 0.0f;
    #pragma unroll
    for (int i = 0; i < 4; i++) {
        int l = l0 + i;
        float s0 = bia.x, s1 = bia.y, s2 = bia.z, s3 = bia.w;
        #pragma unroll
        for (int k = 0; k < 4; k++) {
            float4 v = r[i + k];
            s0 += w4[0][k] * v.x;
            s1 += w4[1][k] * v.y;
            s2 += w4[2][k] * v.z;
            s3 += w4[3][k] * v.w;
        }
        float4 zv = *(const float4*)&d_xz[(long)l * (2 * DIN) + DIN + ch0];
        float xs0 = siluf(s0), xs1 = siluf(s1), xs2 = siluf(s2), xs3 = siluf(s3);
        float g0 = siluf(zv.x) * ws.x * INV_LM;
        float g1 = siluf(zv.y) * ws.y * INV_LM;
        float g2 = siluf(zv.z) * ws.z * INV_LM;
        float g3 = siluf(zv.w) * ws.w * INV_LM;
        float4 xso = {xs0, xs1, xs2, xs3};
        float4 go  = {g0, g1, g2, g3};
        *(float4*)&d_xs[(long)l * DIN + ch0] = xso;
        *(float4*)&d_g [(long)l * DIN + ch0] = go;
        local += xs0 * Dv.x * g0 + xs1 * Dv.y * g1 + xs2 * Dv.z * g2 + xs3 * Dv.w * g3;
    }
    float tot = blockReduceSum(local);
    if (threadIdx.x == 0) d_part_conv[blockIdx.x] = tot;
}

// ---------------- K4: GEMM2  dbc[l,j] = sum_ch xs[l,ch]*xpw[j,ch] ------------
__global__ void k_gemm2(const float* __restrict__ xpw) {
    __shared__ __align__(16) float sx[32][68];
    __shared__ __align__(16) float sw[80][68];
    int t  = threadIdx.x;
    int l0 = blockIdx.x * 32;
    int tx = t & 15;
    int ty = t >> 4;
    float acc[4][5];
    #pragma unroll
    for (int i = 0; i < 4; i++)
        #pragma unroll
        for (int j = 0; j < 5; j++) acc[i][j] = 0.0f;

    for (int k0 = 0; k0 < DIN; k0 += 64) {
        #pragma unroll
        for (int p = t; p < 512; p += 128) {
            int li = p >> 4;
            int kv = (p & 15) * 4;
            *(float4*)&sx[li][kv] = *(const float4*)&d_xs[(l0 + li) * DIN + k0 + kv];
        }
        #pragma unroll
        for (int p = t; p < 1280; p += 128) {
            int j  = p >> 4;
            int kv = (p & 15) * 4;
            *(float4*)&sw[j][kv] = *(const float4*)&xpw[j * DIN + k0 + kv];
        }
        __syncthreads();
        #pragma unroll
        for (int k4 = 0; k4 < 16; k4++) {
            float4 a[4];
            #pragma unroll
            for (int i = 0; i < 4; i++) a[i] = *(float4*)&sx[ty * 4 + i][k4 * 4];
            #pragma unroll
            for (int jj = 0; jj < 5; jj++) {
                float4 w = *(float4*)&sw[tx + 16 * jj][k4 * 4];
                #pragma unroll
                for (int i = 0; i < 4; i++)
                    acc[i][jj] += a[i].x * w.x + a[i].y * w.y + a[i].z * w.z + a[i].w * w.w;
            }
        }
        __syncthreads();
    }
    #pragma unroll
    for (int i = 0; i < 4; i++)
        #pragma unroll
        for (int jj = 0; jj < 5; jj++)
            d_dbc[(l0 + ty * 4 + i) * NCOL + tx + 16 * jj] = acc[i][jj];
}

// ---------------- K5: dt = softplus(dbc[:, :48] @ dtw^T + b) -----------------
__global__ void k_dt(const float* __restrict__ dtw,
                     const float* __restrict__ dtb) {
    __shared__ float sdbc[128][48];
    int t  = threadIdx.x;
    int d  = blockIdx.x * 128 + t;
    int l0 = blockIdx.y * 128;
    float wr[48];
    #pragma unroll
    for (int r = 0; r < 48; r++) wr[r] = dtw[d * 48 + r];
    float bias = dtb[d];
    for (int p = t; p < 128 * 48; p += 128) {
        int li = p / 48;
        int r  = p - li * 48;
        sdbc[li][r] = d_dbc[(l0 + li) * NCOL + r];
    }
    __syncthreads();
    for (int li = 0; li < 128; li++) {
        float s = bias;
        #pragma unroll
        for (int r = 0; r < 48; r++) s += wr[r] * sdbc[li][r];
        float sp = (s > 20.0f) ? s : log1pf(__expf(s));
        d_dt[(l0 + li) * DIN + d] = sp;
    }
}

// ---------------- K6: scan pass 1 — one thread owns 16 states of one d -------
__global__ void k_scan1(const float* __restrict__ A_log) {
    __shared__ __align__(16) float sB[CHLEN][DST];
    __shared__ __align__(16) float sC[CHLEN][DST];
    int t = threadIdx.x;
    int d = blockIdx.x * 256 + t;
    int c = blockIdx.y;
    int base = c * CHLEN;
    for (int p = t; p < CHLEN * DST; p += 256) {
        int r = p >> 4, s = p & 15;
        sB[r][s] = d_dbc[(base + r) * NCOL + RNK + s];
        sC[r][s] = d_dbc[(base + r) * NCOL + RNK + DST + s];
    }
    __syncthreads();

    float Av[DST];
    #pragma unroll
    for (int s = 0; s < DST; s++) Av[s] = -__expf(A_log[d * DST + s]);
    bool fast = true;
    #pragma unroll
    for (int s = 1; s < DST; s++) {
        float r = Av[s] / Av[0];
        fast = fast && (fabsf(r - (float)(s + 1)) < 1e-3f);
    }

    float h[DST], cp[DST], K[DST];
    #pragma unroll
    for (int s = 0; s < DST; s++) { h[s] = 0.0f; cp[s] = 1.0f; K[s] = 0.0f; }
    float acc = 0.0f;

    for (int i = 0; i < CHLEN; i++) {
        int l = base + i;
        float dtv = d_dt[(long)l * DIN + d];
        float xsv = d_xs[(long)l * DIN + d];
        float gv  = d_g [(long)l * DIN + d];
        float dtx = dtv * xsv;
        float dAv[DST];
        if (fast) {
            float E  = __expf(dtv * Av[0]);
            float p2 = E * E, p4 = p2 * p2, p8 = p4 * p4;
            dAv[0] = E;        dAv[1] = p2;       dAv[2] = p2 * E;
            dAv[3] = p4;       dAv[4] = p4 * E;   dAv[5] = p4 * p2;
            dAv[6] = p4 * dAv[2]; dAv[7] = p8;
            dAv[8] = p8 * E;   dAv[9] = p8 * p2;  dAv[10] = p8 * dAv[2];
            dAv[11] = p8 * p4; dAv[12] = p8 * dAv[4]; dAv[13] = p8 * dAv[5];
            dAv[14] = p8 * dAv[6]; dAv[15] = p8 * p8;
        } else {
            #pragma unroll
            for (int s = 0; s < DST; s++) dAv[s] = __expf(dtv * Av[s]);
        }
        #pragma unroll
        for (int s = 0; s < DST; s++) {
            float dA = dAv[s];
            cp[s] *= dA;
            h[s] = dA * h[s] + dtx * sB[i][s];
            float cg = sC[i][s] * gv;
            acc  += h[s] * cg;
            K[s] += cp[s] * cg;
        }
    }
    long off = ((long)c * DIN + d) * DST;
    #pragma unroll
    for (int s = 0; s < DST; s++) {
        d_P [off + s] = cp[s];
        d_E [off + s] = h[s];
        d_Kc[off + s] = K[s];
    }
    float tot = blockReduceSum(acc);
    if (t == 0) d_part_scan[c * 6 + blockIdx.x] = tot;
}

// ---------------- K7: scan pass 2 (chunk combine) ----------------------------
__global__ void k_scan2() {
    int gid = blockIdx.x * 256 + threadIdx.x;
    float h = 0.0f, St = 0.0f;
    for (int c = 0; c < NCHUNK; c++) {
        long off = (long)c * (DIN * DST) + gid;
        St += d_Kc[off] * h;
        h   = d_P[off] * h + d_E[off];
    }
    float tot = blockReduceSum(St);
    if (threadIdx.x == 0) d_part_p2[blockIdx.x] = tot;
}

// ---------------- K8: deterministic final reduce -----------------------------
__global__ void k_final(float* __restrict__ out) {
    int t = threadIdx.x;
    float v = 0.0f;
    for (int i = t; i < 1536; i += 256)          v += d_part_conv[i];
    for (int i = t; i < NCHUNK * 6; i += 256)    v += d_part_scan[i];
    for (int i = t; i < 96; i += 256)            v += d_part_p2[i];
    float tot = blockReduceSum(v);
    if (t == 0) out[0] = tot;
}

// ---------------- launch -----------------------------------------------------
extern "C" void kernel_launch(void* const* d_in, const int* in_sizes, int n_in,
                              void* d_out, int out_size) {
    const float* x     = (const float*)d_in[0];
    const float* w_in  = (const float*)d_in[1];
    const float* convw = (const float*)d_in[2];
    const float* convb = (const float*)d_in[3];
    const float* xpw   = (const float*)d_in[4];
    const float* dtw   = (const float*)d_in[5];
    const float* dtb   = (const float*)d_in[6];
    const float* A_log = (const float*)d_in[7];
    const float* Dvec  = (const float*)d_in[8];
    const float* opw   = (const float*)d_in[9];
    float* out = (float*)d_out;

    static int configured = 0;
    if (!configured) {
        cudaFuncSetAttribute(k_gemm1_mma, cudaFuncAttributeMaxDynamicSharedMemorySize, G1_SMEM);
        configured = 1;
    }

    k_colsum<<<DIN / 16, 256>>>(opw);
    k_patchify<<<(DMOD * LSEQ) / 256, 256>>>(x);
    k_wsplit<<<(2 * DIN * DMOD) / 256, 256>>>(w_in);
    k_gemm1_mma<<<dim3(2 * DIN / 128, LSEQ / 128), 256, G1_SMEM>>>();
    k_conv<<<(LSEQ / 4) * (DIN / 4) / 256, 256>>>(convw, convb, Dvec);
    k_gemm2<<<LSEQ / 32, 128>>>(xpw);
    k_dt<<<dim3(DIN / 128, LSEQ / 128), 128>>>(dtw, dtb);
    k_scan1<<<dim3(DIN / 256, NCHUNK), 256>>>(A_log);
    k_scan2<<<96, 256>>>();
    k_final<<<1, 256>>>(out);
}

// round 6
// speedup vs baseline: 2.0779x; 1.0237x over previous
#include <cuda_runtime.h>
#include <cuda_bf16.h>
#include <math.h>
#include <stdint.h>

#define LSEQ 4096
#define DMOD 768
#define DIN  1536
#define DST  16
#define RNK  48
#define NCOL 80
#define NCHUNK 128
#define CHLEN  32
#define INV_LM (1.0f / (4096.0f * 768.0f))

// ---------------- scratch ----------------------------------------------------
__device__ float d_wsum[DIN];
__device__ __nv_bfloat16 d_uhi[LSEQ * DMOD];
__device__ __nv_bfloat16 d_ulo[LSEQ * DMOD];
__device__ __nv_bfloat16 d_whi[2 * DIN * DMOD];
__device__ __nv_bfloat16 d_wlo[2 * DIN * DMOD];
__device__ float d_xz[LSEQ * 2 * DIN];
__device__ float d_xs[LSEQ * DIN];
__device__ float d_g [LSEQ * DIN];
__device__ float d_dt[LSEQ * DIN];
__device__ float d_dbc[LSEQ * NCOL];
__device__ float d_P [NCHUNK * DIN * DST];
__device__ float d_E [NCHUNK * DIN * DST];
__device__ float d_Kc[NCHUNK * DIN * DST];
__device__ float d_part_conv[1536];
__device__ float d_part_scan[NCHUNK * 6];
__device__ float d_part_p2[96];

__device__ __forceinline__ float siluf(float x) { return x / (1.0f + __expf(-x)); }

__device__ __forceinline__ float blockReduceSum(float v) {
    __shared__ float sh[32];
    int lane = threadIdx.x & 31;
    int w    = threadIdx.x >> 5;
    #pragma unroll
    for (int o = 16; o > 0; o >>= 1) v += __shfl_down_sync(0xffffffffu, v, o);
    if (lane == 0) sh[w] = v;
    __syncthreads();
    int nw = blockDim.x >> 5;
    v = (threadIdx.x < nw) ? sh[threadIdx.x] : 0.0f;
    if (w == 0) {
        #pragma unroll
        for (int o = 16; o > 0; o >>= 1) v += __shfl_down_sync(0xffffffffu, v, o);
    }
    return v;
}

// ---------------- asm helpers (sm_80-baseline) -------------------------------
__device__ __forceinline__ uint32_t smem_to_u32(const void* p) {
    uint32_t a;
    asm("{ .reg .u64 t; cvta.to.shared.u64 t, %1; cvt.u32.u64 %0, t; }" : "=r"(a) : "l"(p));
    return a;
}
#define CP16(sm, gp) \
    asm volatile("cp.async.cg.shared.global [%0], [%1], 16;" :: "r"(sm), "l"(gp))
#define CP_COMMIT() asm volatile("cp.async.commit_group;" ::: "memory")
#define CP_WAIT1()  asm volatile("cp.async.wait_group 1;" ::: "memory")

__device__ __forceinline__ void ldsm_x4(uint32_t& r0, uint32_t& r1, uint32_t& r2,
                                        uint32_t& r3, uint32_t addr) {
    asm volatile("ldmatrix.sync.aligned.m8n8.x4.shared.b16 {%0,%1,%2,%3}, [%4];"
                 : "=r"(r0), "=r"(r1), "=r"(r2), "=r"(r3) : "r"(addr));
}
__device__ __forceinline__ void mma16816(float* c, const uint32_t* a, const uint32_t* b) {
    asm volatile("mma.sync.aligned.m16n8k16.row.col.f32.bf16.bf16.f32 "
                 "{%0,%1,%2,%3}, {%4,%5,%6,%7}, {%8,%9}, {%0,%1,%2,%3};"
                 : "+f"(c[0]), "+f"(c[1]), "+f"(c[2]), "+f"(c[3])
                 : "r"(a[0]), "r"(a[1]), "r"(a[2]), "r"(a[3]), "r"(b[0]), "r"(b[1]));
}

// swizzled 64B-row addressing: row r, 16B slot s -> conflict-free ldmatrix
__device__ __forceinline__ uint32_t swz(uint32_t row, uint32_t slot) {
    return row * 64u + ((slot ^ ((row >> 1) & 3u)) << 4);
}

// ---------------- K_prep: colsum + patchify + wsplit (one launch) ------------
#define PB_PATCH  ((DMOD * LSEQ) / 256)          // 12288
#define PB_WSPLIT ((2 * DIN * DMOD) / 256)       // 9216
#define PB_COLSUM (DIN / 16)                     // 96
__global__ void k_prep(const float* __restrict__ x,
                       const float* __restrict__ w,
                       const float* __restrict__ opw) {
    int bid = blockIdx.x;
    int t = threadIdx.x;
    if (bid < PB_PATCH) {
        int idx = bid * 256 + t;                 // l*768 + d
        int l = idx / DMOD;
        int d = idx - l * DMOD;
        int c   = d >> 8;
        int r   = d & 255;
        int ih  = r >> 2;
        int iwq = r & 3;
        int iwr = l >> 8;
        int rest = l & 255;
        int a = rest >> 4;
        int b = rest & 15;
        int iw = iwq * 16 + iwr;
        float v = x[c * 1048576 + (ih * 16 + a) * 1024 + iw * 16 + b];
        __nv_bfloat16 hi = __float2bfloat16(v);
        __nv_bfloat16 lo = __float2bfloat16(v - __bfloat162float(hi));
        d_uhi[idx] = hi;
        d_ulo[idx] = lo;
    } else if (bid < PB_PATCH + PB_WSPLIT) {
        int idx = (bid - PB_PATCH) * 256 + t;
        float v = w[idx];
        __nv_bfloat16 hi = __float2bfloat16(v);
        __nv_bfloat16 lo = __float2bfloat16(v - __bfloat162float(hi));
        d_whi[idx] = hi;
        d_wlo[idx] = lo;
    } else {
        int cb = bid - PB_PATCH - PB_WSPLIT;
        __shared__ float sh[16][17];
        int dl = t & 15;
        int mg = t >> 4;
        int d  = cb * 16 + dl;
        float s = 0.0f;
        for (int m = mg * 48; m < mg * 48 + 48; m++) s += opw[m * DIN + d];
        sh[dl][mg] = s;
        __syncthreads();
        if (t < 16) {
            float tot = 0.0f;
            #pragma unroll
            for (int g = 0; g < 16; g++) tot += sh[t][g];
            d_wsum[cb * 16 + t] = tot;
        }
    }
}

// ---------------- K2: GEMM1 via mma.sync bf16, 3-stage swizzled, 2 CTA/SM ----
#define G1_TILE   8192                  // 128 rows * 64 B
#define G1_STAGE  (4 * G1_TILE)         // Ahi, Alo, Bhi, Blo = 32768 B
#define G1_SMEM   (3 * G1_STAGE)        // 98304 B
#define G1_ITERS  24                    // 768 / 32

__device__ __forceinline__ void g1_prefetch(uint32_t sbase, int stage, int k0,
                                            int l0, int n0, int t) {
    const uint32_t so = sbase + stage * G1_STAGE;
    const int prow = t >> 2;
    const int pq   = t & 3;
    #pragma unroll
    for (int rep = 0; rep < 2; rep++) {
        int row = prow + rep * 64;
        uint32_t soff = swz((uint32_t)row, (uint32_t)pq);
        long ga = (long)(l0 + row) * DMOD + k0 + pq * 8;
        long gb = (long)(n0 + row) * DMOD + k0 + pq * 8;
        CP16(so + soff,               (const void*)(d_uhi + ga));
        CP16(so + G1_TILE + soff,     (const void*)(d_ulo + ga));
        CP16(so + 2 * G1_TILE + soff, (const void*)(d_whi + gb));
        CP16(so + 3 * G1_TILE + soff, (const void*)(d_wlo + gb));
    }
}

__global__ void __launch_bounds__(256, 2) k_gemm1_mma() {
    extern __shared__ char smem[];
    const uint32_t sbase = smem_to_u32(smem);
    const int t    = threadIdx.x;
    const int lane = t & 31;
    const int wid  = t >> 5;
    const int wm   = wid >> 2;      // 0..1
    const int wn   = wid & 3;       // 0..3
    const int n0   = blockIdx.x * 128;
    const int l0   = blockIdx.y * 128;

    float acc[4][4][4];
    #pragma unroll
    for (int i = 0; i < 4; i++)
        #pragma unroll
        for (int j = 0; j < 4; j++)
            #pragma unroll
            for (int q = 0; q < 4; q++) acc[i][j][q] = 0.0f;

    g1_prefetch(sbase, 0, 0, l0, n0, t);
    CP_COMMIT();
    g1_prefetch(sbase, 1, 32, l0, n0, t);
    CP_COMMIT();

    for (int c = 0; c < G1_ITERS; c++) {
        CP_WAIT1();            // own groups: group c complete (c+1 in flight)
        __syncthreads();       // everyone's group-c data visible; stage (c+2)%3 free
        if (c + 2 < G1_ITERS)
            g1_prefetch(sbase, (c + 2) % 3, (c + 2) * 32, l0, n0, t);
        CP_COMMIT();           // always commit (possibly empty) to keep counts aligned

        const uint32_t so = sbase + (c % 3) * G1_STAGE;
        #pragma unroll
        for (int kk = 0; kk < 2; kk++) {
            const uint32_t arow = (uint32_t)(wm * 64 + (lane & 15));
            const uint32_t aslot = (uint32_t)(kk * 2 + (lane >> 4));      // 16B slot
            const int g = lane >> 3;
            const uint32_t brow = (uint32_t)(wn * 32 + ((g >> 1) << 3) + (lane & 7));
            const uint32_t bslot = (uint32_t)(kk * 2 + (g & 1));

            uint32_t a_hi[4][4];
            #pragma unroll
            for (int mt = 0; mt < 4; mt++) {
                uint32_t addr = so + swz(arow + mt * 16, aslot);
                ldsm_x4(a_hi[mt][0], a_hi[mt][1], a_hi[mt][2], a_hi[mt][3], addr);
            }
            uint32_t b_hi[4][2], b_lo[4][2];
            #pragma unroll
            for (int np = 0; np < 2; np++) {
                uint32_t addr = so + 2 * G1_TILE + swz(brow + np * 16, bslot);
                ldsm_x4(b_hi[2 * np][0], b_hi[2 * np][1],
                        b_hi[2 * np + 1][0], b_hi[2 * np + 1][1], addr);
                ldsm_x4(b_lo[2 * np][0], b_lo[2 * np][1],
                        b_lo[2 * np + 1][0], b_lo[2 * np + 1][1], addr + G1_TILE);
            }
            #pragma unroll
            for (int mt = 0; mt < 4; mt++)
                #pragma unroll
                for (int nt = 0; nt < 4; nt++)
                    mma16816(acc[mt][nt], a_hi[mt], b_hi[nt]);
            #pragma unroll
            for (int mt = 0; mt < 4; mt++)
                #pragma unroll
                for (int nt = 0; nt < 4; nt++)
                    mma16816(acc[mt][nt], a_hi[mt], b_lo[nt]);
            uint32_t a_lo[4][4];
            #pragma unroll
            for (int mt = 0; mt < 4; mt++) {
                uint32_t addr = so + G1_TILE + swz(arow + mt * 16, aslot);
                ldsm_x4(a_lo[mt][0], a_lo[mt][1], a_lo[mt][2], a_lo[mt][3], addr);
            }
            #pragma unroll
            for (int mt = 0; mt < 4; mt++)
                #pragma unroll
                for (int nt = 0; nt < 4; nt++)
                    mma16816(acc[mt][nt], a_lo[mt], b_hi[nt]);
        }
    }

    #pragma unroll
    for (int mt = 0; mt < 4; mt++) {
        int r0 = l0 + wm * 64 + mt * 16 + (lane >> 2);
        #pragma unroll
        for (int nt = 0; nt < 4; nt++) {
            int cc = n0 + wn * 32 + nt * 8 + 2 * (lane & 3);
            float2 v0 = {acc[mt][nt][0], acc[mt][nt][1]};
            float2 v1 = {acc[mt][nt][2], acc[mt][nt][3]};
            *(float2*)&d_xz[(long)r0 * (2 * DIN) + cc]       = v0;
            *(float2*)&d_xz[(long)(r0 + 8) * (2 * DIN) + cc] = v1;
        }
    }
}

// -------- K3: causal depthwise conv(4) + silu, 4l x 4ch tile per thread ------
__global__ void k_conv(const float* __restrict__ convw,
                       const float* __restrict__ convb,
                       const float* __restrict__ Dvec) {
    int idx = blockIdx.x * blockDim.x + threadIdx.x;
    int lq  = idx / (DIN / 4);
    int q   = idx - lq * (DIN / 4);
    int ch0 = q * 4;
    int l0  = lq * 4;

    float4 bia = *(const float4*)&convb[ch0];
    float w4[4][4];
    #pragma unroll
    for (int j = 0; j < 4; j++) {
        float4 w = *(const float4*)&convw[(ch0 + j) * 4];
        w4[j][0] = w.x; w4[j][1] = w.y; w4[j][2] = w.z; w4[j][3] = w.w;
    }
    float4 ws = *(const float4*)&d_wsum[ch0];
    float4 Dv = *(const float4*)&Dvec[ch0];

    float4 r[7];
    #pragma unroll
    for (int k = 0; k < 7; k++) {
        int lk = l0 - 3 + k;
        if (lk >= 0) r[k] = *(const float4*)&d_xz[(long)lk * (2 * DIN) + ch0];
        else         r[k] = make_float4(0.f, 0.f, 0.f, 0.f);
    }
    float local = 0.0f;
    #pragma unroll
    for (int i = 0; i < 4; i++) {
        int l = l0 + i;
        float s0 = bia.x, s1 = bia.y, s2 = bia.z, s3 = bia.w;
        #pragma unroll
        for (int k = 0; k < 4; k++) {
            float4 v = r[i + k];
            s0 += w4[0][k] * v.x;
            s1 += w4[1][k] * v.y;
            s2 += w4[2][k] * v.z;
            s3 += w4[3][k] * v.w;
        }
        float4 zv = *(const float4*)&d_xz[(long)l * (2 * DIN) + DIN + ch0];
        float xs0 = siluf(s0), xs1 = siluf(s1), xs2 = siluf(s2), xs3 = siluf(s3);
        float g0 = siluf(zv.x) * ws.x * INV_LM;
        float g1 = siluf(zv.y) * ws.y * INV_LM;
        float g2 = siluf(zv.z) * ws.z * INV_LM;
        float g3 = siluf(zv.w) * ws.w * INV_LM;
        float4 xso = {xs0, xs1, xs2, xs3};
        float4 go  = {g0, g1, g2, g3};
        *(float4*)&d_xs[(long)l * DIN + ch0] = xso;
        *(float4*)&d_g [(long)l * DIN + ch0] = go;
        local += xs0 * Dv.x * g0 + xs1 * Dv.y * g1 + xs2 * Dv.z * g2 + xs3 * Dv.w * g3;
    }
    float tot = blockReduceSum(local);
    if (threadIdx.x == 0) d_part_conv[blockIdx.x] = tot;
}

// ---------------- K4: GEMM2  dbc[l,j] = sum_ch xs[l,ch]*xpw[j,ch] ------------
__global__ void k_gemm2(const float* __restrict__ xpw) {
    __shared__ __align__(16) float sx[32][68];
    __shared__ __align__(16) float sw[80][68];
    int t  = threadIdx.x;
    int l0 = blockIdx.x * 32;
    int tx = t & 15;
    int ty = t >> 4;
    float acc[4][5];
    #pragma unroll
    for (int i = 0; i < 4; i++)
        #pragma unroll
        for (int j = 0; j < 5; j++) acc[i][j] = 0.0f;

    for (int k0 = 0; k0 < DIN; k0 += 64) {
        #pragma unroll
        for (int p = t; p < 512; p += 128) {
            int li = p >> 4;
            int kv = (p & 15) * 4;
            *(float4*)&sx[li][kv] = *(const float4*)&d_xs[(l0 + li) * DIN + k0 + kv];
        }
        #pragma unroll
        for (int p = t; p < 1280; p += 128) {
            int j  = p >> 4;
            int kv = (p & 15) * 4;
            *(float4*)&sw[j][kv] = *(const float4*)&xpw[j * DIN + k0 + kv];
        }
        __syncthreads();
        #pragma unroll
        for (int k4 = 0; k4 < 16; k4++) {
            float4 a[4];
            #pragma unroll
            for (int i = 0; i < 4; i++) a[i] = *(float4*)&sx[ty * 4 + i][k4 * 4];
            #pragma unroll
            for (int jj = 0; jj < 5; jj++) {
                float4 w = *(float4*)&sw[tx + 16 * jj][k4 * 4];
                #pragma unroll
                for (int i = 0; i < 4; i++)
                    acc[i][jj] += a[i].x * w.x + a[i].y * w.y + a[i].z * w.z + a[i].w * w.w;
            }
        }
        __syncthreads();
    }
    #pragma unroll
    for (int i = 0; i < 4; i++)
        #pragma unroll
        for (int jj = 0; jj < 5; jj++)
            d_dbc[(l0 + ty * 4 + i) * NCOL + tx + 16 * jj] = acc[i][jj];
}

// ---------------- K5: dt = softplus(dbc[:, :48] @ dtw^T + b) -----------------
__global__ void k_dt(const float* __restrict__ dtw,
                     const float* __restrict__ dtb) {
    __shared__ __align__(16) float4 sdbc[128][12];
    int t  = threadIdx.x;
    int d  = blockIdx.x * 128 + t;
    int l0 = blockIdx.y * 128;
    float4 wr[12];
    #pragma unroll
    for (int r4 = 0; r4 < 12; r4++) wr[r4] = *(const float4*)&dtw[d * 48 + r4 * 4];
    float bias = dtb[d];
    for (int p = t; p < 128 * 12; p += 128) {
        int li = p / 12;
        int r4 = p - li * 12;
        sdbc[li][r4] = *(const float4*)&d_dbc[(l0 + li) * NCOL + r4 * 4];
    }
    __syncthreads();
    for (int li = 0; li < 128; li++) {
        float s = bias;
        #pragma unroll
        for (int r4 = 0; r4 < 12; r4++) {
            float4 v = sdbc[li][r4];
            s += wr[r4].x * v.x + wr[r4].y * v.y + wr[r4].z * v.z + wr[r4].w * v.w;
        }
        float sp = (s > 20.0f) ? s : __logf(1.0f + __expf(s));
        d_dt[(l0 + li) * DIN + d] = sp;
    }
}

// ---------------- K6: scan pass 1 — one thread owns 16 states of one d -------
__global__ void k_scan1(const float* __restrict__ A_log) {
    __shared__ __align__(16) float sB[CHLEN][DST];
    __shared__ __align__(16) float sC[CHLEN][DST];
    int t = threadIdx.x;
    int d = blockIdx.x * 256 + t;
    int c = blockIdx.y;
    int base = c * CHLEN;
    for (int p = t; p < CHLEN * DST; p += 256) {
        int r = p >> 4, s = p & 15;
        sB[r][s] = d_dbc[(base + r) * NCOL + RNK + s];
        sC[r][s] = d_dbc[(base + r) * NCOL + RNK + DST + s];
    }
    __syncthreads();

    float Av[DST];
    #pragma unroll
    for (int s = 0; s < DST; s++) Av[s] = -__expf(A_log[d * DST + s]);
    bool fast = true;
    #pragma unroll
    for (int s = 1; s < DST; s++) {
        float r = Av[s] / Av[0];
        fast = fast && (fabsf(r - (float)(s + 1)) < 1e-3f);
    }

    float h[DST], cp[DST], K[DST];
    #pragma unroll
    for (int s = 0; s < DST; s++) { h[s] = 0.0f; cp[s] = 1.0f; K[s] = 0.0f; }
    float acc = 0.0f;

    for (int i = 0; i < CHLEN; i++) {
        int l = base + i;
        float dtv = d_dt[(long)l * DIN + d];
        float xsv = d_xs[(long)l * DIN + d];
        float gv  = d_g [(long)l * DIN + d];
        float dtx = dtv * xsv;
        float dAv[DST];
        if (fast) {
            float E  = __expf(dtv * Av[0]);
            float p2 = E * E, p4 = p2 * p2, p8 = p4 * p4;
            dAv[0] = E;        dAv[1] = p2;       dAv[2] = p2 * E;
            dAv[3] = p4;       dAv[4] = p4 * E;   dAv[5] = p4 * p2;
            dAv[6] = p4 * dAv[2]; dAv[7] = p8;
            dAv[8] = p8 * E;   dAv[9] = p8 * p2;  dAv[10] = p8 * dAv[2];
            dAv[11] = p8 * p4; dAv[12] = p8 * dAv[4]; dAv[13] = p8 * dAv[5];
            dAv[14] = p8 * dAv[6]; dAv[15] = p8 * p8;
        } else {
            #pragma unroll
            for (int s = 0; s < DST; s++) dAv[s] = __expf(dtv * Av[s]);
        }
        #pragma unroll
        for (int s = 0; s < DST; s++) {
            float dA = dAv[s];
            cp[s] *= dA;
            h[s] = dA * h[s] + dtx * sB[i][s];
            float cg = sC[i][s] * gv;
            acc  += h[s] * cg;
            K[s] += cp[s] * cg;
        }
    }
    long off = ((long)c * DIN + d) * DST;
    #pragma unroll
    for (int s = 0; s < DST; s++) {
        d_P [off + s] = cp[s];
        d_E [off + s] = h[s];
        d_Kc[off + s] = K[s];
    }
    float tot = blockReduceSum(acc);
    if (t == 0) d_part_scan[c * 6 + blockIdx.x] = tot;
}

// ---------------- K7: scan pass 2 (chunk combine) ----------------------------
__global__ void k_scan2() {
    int gid = blockIdx.x * 256 + threadIdx.x;
    float h = 0.0f, St = 0.0f;
    for (int c = 0; c < NCHUNK; c++) {
        long off = (long)c * (DIN * DST) + gid;
        St += d_Kc[off] * h;
        h   = d_P[off] * h + d_E[off];
    }
    float tot = blockReduceSum(St);
    if (threadIdx.x == 0) d_part_p2[blockIdx.x] = tot;
}

// ---------------- K8: deterministic final reduce -----------------------------
__global__ void k_final(float* __restrict__ out) {
    int t = threadIdx.x;
    float v = 0.0f;
    for (int i = t; i < 1536; i += 256)          v += d_part_conv[i];
    for (int i = t; i < NCHUNK * 6; i += 256)    v += d_part_scan[i];
    for (int i = t; i < 96; i += 256)            v += d_part_p2[i];
    float tot = blockReduceSum(v);
    if (t == 0) out[0] = tot;
}

// ---------------- launch -----------------------------------------------------
extern "C" void kernel_launch(void* const* d_in, const int* in_sizes, int n_in,
                              void* d_out, int out_size) {
    const float* x     = (const float*)d_in[0];
    const float* w_in  = (const float*)d_in[1];
    const float* convw = (const float*)d_in[2];
    const float* convb = (const float*)d_in[3];
    const float* xpw   = (const float*)d_in[4];
    const float* dtw   = (const float*)d_in[5];
    const float* dtb   = (const float*)d_in[6];
    const float* A_log = (const float*)d_in[7];
    const float* Dvec  = (const float*)d_in[8];
    const float* opw   = (const float*)d_in[9];
    float* out = (float*)d_out;

    static int configured = 0;
    if (!configured) {
        cudaFuncSetAttribute(k_gemm1_mma, cudaFuncAttributeMaxDynamicSharedMemorySize, G1_SMEM);
        configured = 1;
    }

    k_prep<<<PB_PATCH + PB_WSPLIT + PB_COLSUM, 256>>>(x, w_in, opw);
    k_gemm1_mma<<<dim3(2 * DIN / 128, LSEQ / 128), 256, G1_SMEM>>>();
    k_conv<<<(LSEQ / 4) * (DIN / 4) / 256, 256>>>(convw, convb, Dvec);
    k_gemm2<<<LSEQ / 32, 128>>>(xpw);
    k_dt<<<dim3(DIN / 128, LSEQ / 128), 128>>>(dtw, dtb);
    k_scan1<<<dim3(DIN / 256, NCHUNK), 256>>>(A_log);
    k_scan2<<<96, 256>>>();
    k_final<<<1, 256>>>(out);
}

// round 7
// speedup vs baseline: 2.4560x; 1.1820x over previous
#include <cuda_runtime.h>
#include <cuda_bf16.h>
#include <math.h>
#include <stdint.h>

#define LSEQ 4096
#define DMOD 768
#define DIN  1536
#define DST  16
#define RNK  48
#define NCOL 80
#define NCHUNK 128
#define CHLEN  32
#define INV_LM (1.0f / (4096.0f * 768.0f))

// ---------------- scratch ----------------------------------------------------
__device__ float d_wsum[DIN];
__device__ __nv_bfloat16 d_uhi[LSEQ * DMOD];
__device__ __nv_bfloat16 d_ulo[LSEQ * DMOD];
__device__ __nv_bfloat16 d_whi[2 * DIN * DMOD];
__device__ __nv_bfloat16 d_wlo[2 * DIN * DMOD];
__device__ float d_xz[LSEQ * 2 * DIN];
__device__ float d_xs[LSEQ * DIN];
__device__ float d_g [LSEQ * DIN];
__device__ float d_dt[LSEQ * DIN];
__device__ float d_dbc[LSEQ * NCOL];
#define G2_KSPLIT 8
__device__ float d_dbc_part[G2_KSPLIT][LSEQ * NCOL];
__device__ float d_P [NCHUNK * DIN * DST];
__device__ float d_E [NCHUNK * DIN * DST];
__device__ float d_Kc[NCHUNK * DIN * DST];
__device__ float d_part_conv[1536];
__device__ float d_part_scan[NCHUNK * 6];
__device__ float d_part_p2[96];

__device__ __forceinline__ float siluf(float x) { return x / (1.0f + __expf(-x)); }

__device__ __forceinline__ float blockReduceSum(float v) {
    __shared__ float sh[32];
    int lane = threadIdx.x & 31;
    int w    = threadIdx.x >> 5;
    #pragma unroll
    for (int o = 16; o > 0; o >>= 1) v += __shfl_down_sync(0xffffffffu, v, o);
    if (lane == 0) sh[w] = v;
    __syncthreads();
    int nw = blockDim.x >> 5;
    v = (threadIdx.x < nw) ? sh[threadIdx.x] : 0.0f;
    if (w == 0) {
        #pragma unroll
        for (int o = 16; o > 0; o >>= 1) v += __shfl_down_sync(0xffffffffu, v, o);
    }
    return v;
}

// ---------------- asm helpers (sm_80-baseline) -------------------------------
__device__ __forceinline__ uint32_t smem_to_u32(const void* p) {
    uint32_t a;
    asm("{ .reg .u64 t; cvta.to.shared.u64 t, %1; cvt.u32.u64 %0, t; }" : "=r"(a) : "l"(p));
    return a;
}
#define CP16(sm, gp) \
    asm volatile("cp.async.cg.shared.global [%0], [%1], 16;" :: "r"(sm), "l"(gp))
#define CP_COMMIT() asm volatile("cp.async.commit_group;" ::: "memory")
#define CP_WAIT1()  asm volatile("cp.async.wait_group 1;" ::: "memory")

__device__ __forceinline__ void ldsm_x4(uint32_t& r0, uint32_t& r1, uint32_t& r2,
                                        uint32_t& r3, uint32_t addr) {
    asm volatile("ldmatrix.sync.aligned.m8n8.x4.shared.b16 {%0,%1,%2,%3}, [%4];"
                 : "=r"(r0), "=r"(r1), "=r"(r2), "=r"(r3) : "r"(addr));
}
__device__ __forceinline__ void mma16816(float* c, const uint32_t* a, const uint32_t* b) {
    asm volatile("mma.sync.aligned.m16n8k16.row.col.f32.bf16.bf16.f32 "
                 "{%0,%1,%2,%3}, {%4,%5,%6,%7}, {%8,%9}, {%0,%1,%2,%3};"
                 : "+f"(c[0]), "+f"(c[1]), "+f"(c[2]), "+f"(c[3])
                 : "r"(a[0]), "r"(a[1]), "r"(a[2]), "r"(a[3]), "r"(b[0]), "r"(b[1]));
}

// swizzled 64B-row addressing: row r, 16B slot s -> conflict-free ldmatrix
__device__ __forceinline__ uint32_t swz(uint32_t row, uint32_t slot) {
    return row * 64u + ((slot ^ ((row >> 1) & 3u)) << 4);
}

// ---------------- K_prep: colsum + patchify + wsplit (one launch) ------------
#define PB_PATCH  ((DMOD * LSEQ) / 256)          // 12288
#define PB_WSPLIT ((2 * DIN * DMOD) / 256)       // 9216
#define PB_COLSUM (DIN / 16)                     // 96
__global__ void k_prep(const float* __restrict__ x,
                       const float* __restrict__ w,
                       const float* __restrict__ opw) {
    int bid = blockIdx.x;
    int t = threadIdx.x;
    if (bid < PB_PATCH) {
        int idx = bid * 256 + t;                 // l*768 + d
        int l = idx / DMOD;
        int d = idx - l * DMOD;
        int c   = d >> 8;
        int r   = d & 255;
        int ih  = r >> 2;
        int iwq = r & 3;
        int iwr = l >> 8;
        int rest = l & 255;
        int a = rest >> 4;
        int b = rest & 15;
        int iw = iwq * 16 + iwr;
        float v = x[c * 1048576 + (ih * 16 + a) * 1024 + iw * 16 + b];
        __nv_bfloat16 hi = __float2bfloat16(v);
        __nv_bfloat16 lo = __float2bfloat16(v - __bfloat162float(hi));
        d_uhi[idx] = hi;
        d_ulo[idx] = lo;
    } else if (bid < PB_PATCH + PB_WSPLIT) {
        int idx = (bid - PB_PATCH) * 256 + t;
        float v = w[idx];
        __nv_bfloat16 hi = __float2bfloat16(v);
        __nv_bfloat16 lo = __float2bfloat16(v - __bfloat162float(hi));
        d_whi[idx] = hi;
        d_wlo[idx] = lo;
    } else {
        int cb = bid - PB_PATCH - PB_WSPLIT;
        __shared__ float sh[16][17];
        int dl = t & 15;
        int mg = t >> 4;
        int d  = cb * 16 + dl;
        float s = 0.0f;
        for (int m = mg * 48; m < mg * 48 + 48; m++) s += opw[m * DIN + d];
        sh[dl][mg] = s;
        __syncthreads();
        if (t < 16) {
            float tot = 0.0f;
            #pragma unroll
            for (int g = 0; g < 16; g++) tot += sh[t][g];
            d_wsum[cb * 16 + t] = tot;
        }
    }
}

// ---------------- K2: GEMM1 via mma.sync bf16, 3-stage swizzled, 2 CTA/SM ----
#define G1_TILE   8192                  // 128 rows * 64 B
#define G1_STAGE  (4 * G1_TILE)         // Ahi, Alo, Bhi, Blo = 32768 B
#define G1_SMEM   (3 * G1_STAGE)        // 98304 B
#define G1_ITERS  24                    // 768 / 32

__device__ __forceinline__ void g1_prefetch(uint32_t sbase, int stage, int k0,
                                            int l0, int n0, int t) {
    const uint32_t so = sbase + stage * G1_STAGE;
    const int prow = t >> 2;
    const int pq   = t & 3;
    #pragma unroll
    for (int rep = 0; rep < 2; rep++) {
        int row = prow + rep * 64;
        uint32_t soff = swz((uint32_t)row, (uint32_t)pq);
        long ga = (long)(l0 + row) * DMOD + k0 + pq * 8;
        long gb = (long)(n0 + row) * DMOD + k0 + pq * 8;
        CP16(so + soff,               (const void*)(d_uhi + ga));
        CP16(so + G1_TILE + soff,     (const void*)(d_ulo + ga));
        CP16(so + 2 * G1_TILE + soff, (const void*)(d_whi + gb));
        CP16(so + 3 * G1_TILE + soff, (const void*)(d_wlo + gb));
    }
}

__global__ void __launch_bounds__(256, 2) k_gemm1_mma() {
    extern __shared__ char smem[];
    const uint32_t sbase = smem_to_u32(smem);
    const int t    = threadIdx.x;
    const int lane = t & 31;
    const int wid  = t >> 5;
    const int wm   = wid >> 2;      // 0..1
    const int wn   = wid & 3;       // 0..3
    const int n0   = blockIdx.x * 128;
    const int l0   = blockIdx.y * 128;

    float acc[4][4][4];
    #pragma unroll
    for (int i = 0; i < 4; i++)
        #pragma unroll
        for (int j = 0; j < 4; j++)
            #pragma unroll
            for (int q = 0; q < 4; q++) acc[i][j][q] = 0.0f;

    g1_prefetch(sbase, 0, 0, l0, n0, t);
    CP_COMMIT();
    g1_prefetch(sbase, 1, 32, l0, n0, t);
    CP_COMMIT();

    for (int c = 0; c < G1_ITERS; c++) {
        CP_WAIT1();
        __syncthreads();
        if (c + 2 < G1_ITERS)
            g1_prefetch(sbase, (c + 2) % 3, (c + 2) * 32, l0, n0, t);
        CP_COMMIT();

        const uint32_t so = sbase + (c % 3) * G1_STAGE;
        #pragma unroll
        for (int kk = 0; kk < 2; kk++) {
            const uint32_t arow = (uint32_t)(wm * 64 + (lane & 15));
            const uint32_t aslot = (uint32_t)(kk * 2 + (lane >> 4));
            const int g = lane >> 3;
            const uint32_t brow = (uint32_t)(wn * 32 + ((g >> 1) << 3) + (lane & 7));
            const uint32_t bslot = (uint32_t)(kk * 2 + (g & 1));

            uint32_t a_hi[4][4];
            #pragma unroll
            for (int mt = 0; mt < 4; mt++) {
                uint32_t addr = so + swz(arow + mt * 16, aslot);
                ldsm_x4(a_hi[mt][0], a_hi[mt][1], a_hi[mt][2], a_hi[mt][3], addr);
            }
            uint32_t b_hi[4][2], b_lo[4][2];
            #pragma unroll
            for (int np = 0; np < 2; np++) {
                uint32_t addr = so + 2 * G1_TILE + swz(brow + np * 16, bslot);
                ldsm_x4(b_hi[2 * np][0], b_hi[2 * np][1],
                        b_hi[2 * np + 1][0], b_hi[2 * np + 1][1], addr);
                ldsm_x4(b_lo[2 * np][0], b_lo[2 * np][1],
                        b_lo[2 * np + 1][0], b_lo[2 * np + 1][1], addr + G1_TILE);
            }
            #pragma unroll
            for (int mt = 0; mt < 4; mt++)
                #pragma unroll
                for (int nt = 0; nt < 4; nt++)
                    mma16816(acc[mt][nt], a_hi[mt], b_hi[nt]);
            #pragma unroll
            for (int mt = 0; mt < 4; mt++)
                #pragma unroll
                for (int nt = 0; nt < 4; nt++)
                    mma16816(acc[mt][nt], a_hi[mt], b_lo[nt]);
            uint32_t a_lo[4][4];
            #pragma unroll
            for (int mt = 0; mt < 4; mt++) {
                uint32_t addr = so + G1_TILE + swz(arow + mt * 16, aslot);
                ldsm_x4(a_lo[mt][0], a_lo[mt][1], a_lo[mt][2], a_lo[mt][3], addr);
            }
            #pragma unroll
            for (int mt = 0; mt < 4; mt++)
                #pragma unroll
                for (int nt = 0; nt < 4; nt++)
                    mma16816(acc[mt][nt], a_lo[mt], b_hi[nt]);
        }
    }

    #pragma unroll
    for (int mt = 0; mt < 4; mt++) {
        int r0 = l0 + wm * 64 + mt * 16 + (lane >> 2);
        #pragma unroll
        for (int nt = 0; nt < 4; nt++) {
            int cc = n0 + wn * 32 + nt * 8 + 2 * (lane & 3);
            float2 v0 = {acc[mt][nt][0], acc[mt][nt][1]};
            float2 v1 = {acc[mt][nt][2], acc[mt][nt][3]};
            *(float2*)&d_xz[(long)r0 * (2 * DIN) + cc]       = v0;
            *(float2*)&d_xz[(long)(r0 + 8) * (2 * DIN) + cc] = v1;
        }
    }
}

// -------- K3: causal depthwise conv(4) + silu, 4l x 4ch tile per thread ------
__global__ void k_conv(const float* __restrict__ convw,
                       const float* __restrict__ convb,
                       const float* __restrict__ Dvec) {
    int idx = blockIdx.x * blockDim.x + threadIdx.x;
    int lq  = idx / (DIN / 4);
    int q   = idx - lq * (DIN / 4);
    int ch0 = q * 4;
    int l0  = lq * 4;

    float4 bia = *(const float4*)&convb[ch0];
    float w4[4][4];
    #pragma unroll
    for (int j = 0; j < 4; j++) {
        float4 w = *(const float4*)&convw[(ch0 + j) * 4];
        w4[j][0] = w.x; w4[j][1] = w.y; w4[j][2] = w.z; w4[j][3] = w.w;
    }
    float4 ws = *(const float4*)&d_wsum[ch0];
    float4 Dv = *(const float4*)&Dvec[ch0];

    float4 r[7];
    #pragma unroll
    for (int k = 0; k < 7; k++) {
        int lk = l0 - 3 + k;
        if (lk >= 0) r[k] = *(const float4*)&d_xz[(long)lk * (2 * DIN) + ch0];
        else         r[k] = make_float4(0.f, 0.f, 0.f, 0.f);
    }
    float local = 0.0f;
    #pragma unroll
    for (int i = 0; i < 4; i++) {
        int l = l0 + i;
        float s0 = bia.x, s1 = bia.y, s2 = bia.z, s3 = bia.w;
        #pragma unroll
        for (int k = 0; k < 4; k++) {
            float4 v = r[i + k];
            s0 += w4[0][k] * v.x;
            s1 += w4[1][k] * v.y;
            s2 += w4[2][k] * v.z;
            s3 += w4[3][k] * v.w;
        }
        float4 zv = *(const float4*)&d_xz[(long)l * (2 * DIN) + DIN + ch0];
        float xs0 = siluf(s0), xs1 = siluf(s1), xs2 = siluf(s2), xs3 = siluf(s3);
        float g0 = siluf(zv.x) * ws.x * INV_LM;
        float g1 = siluf(zv.y) * ws.y * INV_LM;
        float g2 = siluf(zv.z) * ws.z * INV_LM;
        float g3 = siluf(zv.w) * ws.w * INV_LM;
        float4 xso = {xs0, xs1, xs2, xs3};
        float4 go  = {g0, g1, g2, g3};
        *(float4*)&d_xs[(long)l * DIN + ch0] = xso;
        *(float4*)&d_g [(long)l * DIN + ch0] = go;
        local += xs0 * Dv.x * g0 + xs1 * Dv.y * g1 + xs2 * Dv.z * g2 + xs3 * Dv.w * g3;
    }
    float tot = blockReduceSum(local);
    if (threadIdx.x == 0) d_part_conv[blockIdx.x] = tot;
}

// ---------------- K4: GEMM2 split-K: dbc_part[kz] = xs[:,kz] @ xpw[:,kz]^T ---
// grid (LSEQ/32, G2_KSPLIT), block 128. Each block: 32 l x 80 j x 192 k.
#define G2_KLEN (DIN / G2_KSPLIT)     // 192
__global__ void k_gemm2(const float* __restrict__ xpw) {
    __shared__ __align__(16) float sx[32][68];
    __shared__ __align__(16) float sw[80][68];
    int t  = threadIdx.x;
    int l0 = blockIdx.x * 32;
    int kz = blockIdx.y;
    int kbase = kz * G2_KLEN;
    int tx = t & 15;
    int ty = t >> 4;
    float acc[4][5];
    #pragma unroll
    for (int i = 0; i < 4; i++)
        #pragma unroll
        for (int j = 0; j < 5; j++) acc[i][j] = 0.0f;

    for (int kc = 0; kc < G2_KLEN; kc += 64) {
        int k0 = kbase + kc;
        #pragma unroll
        for (int p = t; p < 512; p += 128) {
            int li = p >> 4;
            int kv = (p & 15) * 4;
            *(float4*)&sx[li][kv] = *(const float4*)&d_xs[(l0 + li) * DIN + k0 + kv];
        }
        #pragma unroll
        for (int p = t; p < 1280; p += 128) {
            int j  = p >> 4;
            int kv = (p & 15) * 4;
            *(float4*)&sw[j][kv] = *(const float4*)&xpw[j * DIN + k0 + kv];
        }
        __syncthreads();
        #pragma unroll
        for (int k4 = 0; k4 < 16; k4++) {
            float4 a[4];
            #pragma unroll
            for (int i = 0; i < 4; i++) a[i] = *(float4*)&sx[ty * 4 + i][k4 * 4];
            #pragma unroll
            for (int jj = 0; jj < 5; jj++) {
                float4 w = *(float4*)&sw[tx + 16 * jj][k4 * 4];
                #pragma unroll
                for (int i = 0; i < 4; i++)
                    acc[i][jj] += a[i].x * w.x + a[i].y * w.y + a[i].z * w.z + a[i].w * w.w;
            }
        }
        __syncthreads();
    }
    #pragma unroll
    for (int i = 0; i < 4; i++)
        #pragma unroll
        for (int jj = 0; jj < 5; jj++)
            d_dbc_part[kz][(l0 + ty * 4 + i) * NCOL + tx + 16 * jj] = acc[i][jj];
}

// ---------------- K4b: reduce split-K partials -------------------------------
__global__ void k_g2red() {
    int idx = blockIdx.x * 256 + threadIdx.x;   // < LSEQ*NCOL
    float s = 0.0f;
    #pragma unroll
    for (int kz = 0; kz < G2_KSPLIT; kz++) s += d_dbc_part[kz][idx];
    d_dbc[idx] = s;
}

// ---------------- K5: dt = softplus(dbc[:, :48] @ dtw^T + b) -----------------
__global__ void k_dt(const float* __restrict__ dtw,
                     const float* __restrict__ dtb) {
    __shared__ __align__(16) float4 sdbc[128][12];
    int t  = threadIdx.x;
    int d  = blockIdx.x * 128 + t;
    int l0 = blockIdx.y * 128;
    float4 wr[12];
    #pragma unroll
    for (int r4 = 0; r4 < 12; r4++) wr[r4] = *(const float4*)&dtw[d * 48 + r4 * 4];
    float bias = dtb[d];
    for (int p = t; p < 128 * 12; p += 128) {
        int li = p / 12;
        int r4 = p - li * 12;
        sdbc[li][r4] = *(const float4*)&d_dbc[(l0 + li) * NCOL + r4 * 4];
    }
    __syncthreads();
    for (int li = 0; li < 128; li++) {
        float s = bias;
        #pragma unroll
        for (int r4 = 0; r4 < 12; r4++) {
            float4 v = sdbc[li][r4];
            s += wr[r4].x * v.x + wr[r4].y * v.y + wr[r4].z * v.z + wr[r4].w * v.w;
        }
        float sp = (s > 20.0f) ? s : __logf(1.0f + __expf(s));
        d_dt[(l0 + li) * DIN + d] = sp;
    }
}

// ---------------- K6: scan pass 1 — one thread owns 16 states of one d -------
__global__ void k_scan1(const float* __restrict__ A_log) {
    __shared__ __align__(16) float sB[CHLEN][DST];
    __shared__ __align__(16) float sC[CHLEN][DST];
    int t = threadIdx.x;
    int d = blockIdx.x * 256 + t;
    int c = blockIdx.y;
    int base = c * CHLEN;
    for (int p = t; p < CHLEN * DST; p += 256) {
        int r = p >> 4, s = p & 15;
        sB[r][s] = d_dbc[(base + r) * NCOL + RNK + s];
        sC[r][s] = d_dbc[(base + r) * NCOL + RNK + DST + s];
    }
    __syncthreads();

    float Av[DST];
    #pragma unroll
    for (int s = 0; s < DST; s++) Av[s] = -__expf(A_log[d * DST + s]);
    bool fast = true;
    #pragma unroll
    for (int s = 1; s < DST; s++) {
        float r = Av[s] / Av[0];
        fast = fast && (fabsf(r - (float)(s + 1)) < 1e-3f);
    }

    float h[DST], cp[DST], K[DST];
    #pragma unroll
    for (int s = 0; s < DST; s++) { h[s] = 0.0f; cp[s] = 1.0f; K[s] = 0.0f; }
    float acc = 0.0f;

    for (int i = 0; i < CHLEN; i++) {
        int l = base + i;
        float dtv = d_dt[(long)l * DIN + d];
        float xsv = d_xs[(long)l * DIN + d];
        float gv  = d_g [(long)l * DIN + d];
        float dtx = dtv * xsv;
        float dAv[DST];
        if (fast) {
            float E  = __expf(dtv * Av[0]);
            float p2 = E * E, p4 = p2 * p2, p8 = p4 * p4;
            dAv[0] = E;        dAv[1] = p2;       dAv[2] = p2 * E;
            dAv[3] = p4;       dAv[4] = p4 * E;   dAv[5] = p4 * p2;
            dAv[6] = p4 * dAv[2]; dAv[7] = p8;
            dAv[8] = p8 * E;   dAv[9] = p8 * p2;  dAv[10] = p8 * dAv[2];
            dAv[11] = p8 * p4; dAv[12] = p8 * dAv[4]; dAv[13] = p8 * dAv[5];
            dAv[14] = p8 * dAv[6]; dAv[15] = p8 * p8;
        } else {
            #pragma unroll
            for (int s = 0; s < DST; s++) dAv[s] = __expf(dtv * Av[s]);
        }
        #pragma unroll
        for (int s = 0; s < DST; s++) {
            float dA = dAv[s];
            cp[s] *= dA;
            h[s] = dA * h[s] + dtx * sB[i][s];
            float cg = sC[i][s] * gv;
            acc  += h[s] * cg;
            K[s] += cp[s] * cg;
        }
    }
    long off = ((long)c * DIN + d) * DST;
    #pragma unroll
    for (int s = 0; s < DST; s++) {
        d_P [off + s] = cp[s];
        d_E [off + s] = h[s];
        d_Kc[off + s] = K[s];
    }
    float tot = blockReduceSum(acc);
    if (t == 0) d_part_scan[c * 6 + blockIdx.x] = tot;
}

// ---------------- K7: scan pass 2 (chunk combine) ----------------------------
__global__ void k_scan2() {
    int gid = blockIdx.x * 256 + threadIdx.x;
    float h = 0.0f, St = 0.0f;
    for (int c = 0; c < NCHUNK; c++) {
        long off = (long)c * (DIN * DST) + gid;
        St += d_Kc[off] * h;
        h   = d_P[off] * h + d_E[off];
    }
    float tot = blockReduceSum(St);
    if (threadIdx.x == 0) d_part_p2[blockIdx.x] = tot;
}

// ---------------- K8: deterministic final reduce -----------------------------
__global__ void k_final(float* __restrict__ out) {
    int t = threadIdx.x;
    float v = 0.0f;
    for (int i = t; i < 1536; i += 256)          v += d_part_conv[i];
    for (int i = t; i < NCHUNK * 6; i += 256)    v += d_part_scan[i];
    for (int i = t; i < 96; i += 256)            v += d_part_p2[i];
    float tot = blockReduceSum(v);
    if (t == 0) out[0] = tot;
}

// ---------------- launch -----------------------------------------------------
extern "C" void kernel_launch(void* const* d_in, const int* in_sizes, int n_in,
                              void* d_out, int out_size) {
    const float* x     = (const float*)d_in[0];
    const float* w_in  = (const float*)d_in[1];
    const float* convw = (const float*)d_in[2];
    const float* convb = (const float*)d_in[3];
    const float* xpw   = (const float*)d_in[4];
    const float* dtw   = (const float*)d_in[5];
    const float* dtb   = (const float*)d_in[6];
    const float* A_log = (const float*)d_in[7];
    const float* Dvec  = (const float*)d_in[8];
    const float* opw   = (const float*)d_in[9];
    float* out = (float*)d_out;

    static int configured = 0;
    if (!configured) {
        cudaFuncSetAttribute(k_gemm1_mma, cudaFuncAttributeMaxDynamicSharedMemorySize, G1_SMEM);
        configured = 1;
    }

    k_prep<<<PB_PATCH + PB_WSPLIT + PB_COLSUM, 256>>>(x, w_in, opw);
    k_gemm1_mma<<<dim3(2 * DIN / 128, LSEQ / 128), 256, G1_SMEM>>>();
    k_conv<<<(LSEQ / 4) * (DIN / 4) / 256, 256>>>(convw, convb, Dvec);
    k_gemm2<<<dim3(LSEQ / 32, G2_KSPLIT), 128>>>(xpw);
    k_g2red<<<(LSEQ * NCOL) / 256, 256>>>();
    k_dt<<<dim3(DIN / 128, LSEQ / 128), 128>>>(dtw, dtb);
    k_scan1<<<dim3(DIN / 256, NCHUNK), 256>>>(A_log);
    k_scan2<<<96, 256>>>();
    k_final<<<1, 256>>>(out);
}

// round 8
// speedup vs baseline: 2.6107x; 1.0630x over previous
#include <cuda_runtime.h>
#include <cuda_bf16.h>
#include <math.h>
#include <stdint.h>

#define LSEQ 4096
#define DMOD 768
#define DIN  1536
#define DST  16
#define RNK  48
#define NCOL 80
#define NCHUNK 128
#define CHLEN  32
#define INV_LM (1.0f / (4096.0f * 768.0f))

// ---------------- scratch ----------------------------------------------------
__device__ float d_wsum[DIN];
__device__ __nv_bfloat16 d_uhi[LSEQ * DMOD];
__device__ __nv_bfloat16 d_ulo[LSEQ * DMOD];
__device__ __nv_bfloat16 d_whi[2 * DIN * DMOD];
__device__ __nv_bfloat16 d_wlo[2 * DIN * DMOD];
__device__ __nv_bfloat16 d_xshi[LSEQ * DIN];
__device__ __nv_bfloat16 d_xslo[LSEQ * DIN];
__device__ __nv_bfloat16 d_xpwhi[128 * DIN];   // padded x_proj_w (rows 80..127 = 0)
__device__ __nv_bfloat16 d_xpwlo[128 * DIN];
__device__ float d_xz[LSEQ * 2 * DIN];
__device__ float d_xs[LSEQ * DIN];
__device__ float d_g [LSEQ * DIN];
__device__ float d_dt[LSEQ * DIN];
__device__ float d_dbc[LSEQ * NCOL];
#define G2_KSPLIT 8
__device__ float d_dbc_part[G2_KSPLIT][LSEQ * NCOL];
__device__ float d_P [NCHUNK * DIN * DST];
__device__ float d_E [NCHUNK * DIN * DST];
__device__ float d_Kc[NCHUNK * DIN * DST];
__device__ float d_part_conv[1536];
__device__ float d_part_scan[NCHUNK * 6];
__device__ float d_part_p2[96];

__device__ __forceinline__ float siluf(float x) { return x / (1.0f + __expf(-x)); }

__device__ __forceinline__ float blockReduceSum(float v) {
    __shared__ float sh[32];
    int lane = threadIdx.x & 31;
    int w    = threadIdx.x >> 5;
    #pragma unroll
    for (int o = 16; o > 0; o >>= 1) v += __shfl_down_sync(0xffffffffu, v, o);
    if (lane == 0) sh[w] = v;
    __syncthreads();
    int nw = blockDim.x >> 5;
    v = (threadIdx.x < nw) ? sh[threadIdx.x] : 0.0f;
    if (w == 0) {
        #pragma unroll
        for (int o = 16; o > 0; o >>= 1) v += __shfl_down_sync(0xffffffffu, v, o);
    }
    return v;
}

// ---------------- asm helpers (sm_80-baseline) -------------------------------
__device__ __forceinline__ uint32_t smem_to_u32(const void* p) {
    uint32_t a;
    asm("{ .reg .u64 t; cvta.to.shared.u64 t, %1; cvt.u32.u64 %0, t; }" : "=r"(a) : "l"(p));
    return a;
}
#define CP16(sm, gp) \
    asm volatile("cp.async.cg.shared.global [%0], [%1], 16;" :: "r"(sm), "l"(gp))
#define CP_COMMIT() asm volatile("cp.async.commit_group;" ::: "memory")
#define CP_WAIT1()  asm volatile("cp.async.wait_group 1;" ::: "memory")

__device__ __forceinline__ void ldsm_x4(uint32_t& r0, uint32_t& r1, uint32_t& r2,
                                        uint32_t& r3, uint32_t addr) {
    asm volatile("ldmatrix.sync.aligned.m8n8.x4.shared.b16 {%0,%1,%2,%3}, [%4];"
                 : "=r"(r0), "=r"(r1), "=r"(r2), "=r"(r3) : "r"(addr));
}
__device__ __forceinline__ void mma16816(float* c, const uint32_t* a, const uint32_t* b) {
    asm volatile("mma.sync.aligned.m16n8k16.row.col.f32.bf16.bf16.f32 "
                 "{%0,%1,%2,%3}, {%4,%5,%6,%7}, {%8,%9}, {%0,%1,%2,%3};"
                 : "+f"(c[0]), "+f"(c[1]), "+f"(c[2]), "+f"(c[3])
                 : "r"(a[0]), "r"(a[1]), "r"(a[2]), "r"(a[3]), "r"(b[0]), "r"(b[1]));
}

// swizzled 64B-row addressing: row r, 16B slot s -> conflict-free ldmatrix
__device__ __forceinline__ uint32_t swz(uint32_t row, uint32_t slot) {
    return row * 64u + ((slot ^ ((row >> 1) & 3u)) << 4);
}

// ---------------- K_prep: colsum + patchify + wsplit + xpw pad ---------------
#define PB_PATCH  ((DMOD * LSEQ) / 256)          // 12288
#define PB_WSPLIT ((2 * DIN * DMOD) / 256)       // 9216
#define PB_XPAD   ((128 * DIN) / 256)            // 768
#define PB_COLSUM (DIN / 16)                     // 96
__global__ void k_prep(const float* __restrict__ x,
                       const float* __restrict__ w,
                       const float* __restrict__ xpw,
                       const float* __restrict__ opw) {
    int bid = blockIdx.x;
    int t = threadIdx.x;
    if (bid < PB_PATCH) {
        int idx = bid * 256 + t;                 // l*768 + d
        int l = idx / DMOD;
        int d = idx - l * DMOD;
        int c   = d >> 8;
        int r   = d & 255;
        int ih  = r >> 2;
        int iwq = r & 3;
        int iwr = l >> 8;
        int rest = l & 255;
        int a = rest >> 4;
        int b = rest & 15;
        int iw = iwq * 16 + iwr;
        float v = x[c * 1048576 + (ih * 16 + a) * 1024 + iw * 16 + b];
        __nv_bfloat16 hi = __float2bfloat16(v);
        __nv_bfloat16 lo = __float2bfloat16(v - __bfloat162float(hi));
        d_uhi[idx] = hi;
        d_ulo[idx] = lo;
    } else if (bid < PB_PATCH + PB_WSPLIT) {
        int idx = (bid - PB_PATCH) * 256 + t;
        float v = w[idx];
        __nv_bfloat16 hi = __float2bfloat16(v);
        __nv_bfloat16 lo = __float2bfloat16(v - __bfloat162float(hi));
        d_whi[idx] = hi;
        d_wlo[idx] = lo;
    } else if (bid < PB_PATCH + PB_WSPLIT + PB_XPAD) {
        int idx = (bid - PB_PATCH - PB_WSPLIT) * 256 + t;   // row*1536 + k
        int row = idx / DIN;
        float v = (row < NCOL) ? xpw[idx] : 0.0f;
        __nv_bfloat16 hi = __float2bfloat16(v);
        __nv_bfloat16 lo = __float2bfloat16(v - __bfloat162float(hi));
        d_xpwhi[idx] = hi;
        d_xpwlo[idx] = lo;
    } else {
        int cb = bid - PB_PATCH - PB_WSPLIT - PB_XPAD;
        __shared__ float sh[16][17];
        int dl = t & 15;
        int mg = t >> 4;
        int d  = cb * 16 + dl;
        float s = 0.0f;
        for (int m = mg * 48; m < mg * 48 + 48; m++) s += opw[m * DIN + d];
        sh[dl][mg] = s;
        __syncthreads();
        if (t < 16) {
            float tot = 0.0f;
            #pragma unroll
            for (int g = 0; g < 16; g++) tot += sh[t][g];
            d_wsum[cb * 16 + t] = tot;
        }
    }
}

// ---------------- shared GEMM machinery --------------------------------------
#define G1_TILE   8192                  // 128 rows * 64 B
#define G1_STAGE  (4 * G1_TILE)         // Ahi, Alo, Bhi, Blo = 32768 B
#define G1_SMEM   (3 * G1_STAGE)        // 98304 B
#define G1_ITERS  24                    // 768 / 32

__device__ __forceinline__ void gx_prefetch(
        uint32_t sbase, int stage, int k0, int l0, int n0, int t,
        const __nv_bfloat16* Ahi, const __nv_bfloat16* Alo,
        const __nv_bfloat16* Bhi, const __nv_bfloat16* Blo, int kstride) {
    const uint32_t so = sbase + stage * G1_STAGE;
    const int prow = t >> 2;
    const int pq   = t & 3;
    #pragma unroll
    for (int rep = 0; rep < 2; rep++) {
        int row = prow + rep * 64;
        uint32_t soff = swz((uint32_t)row, (uint32_t)pq);
        long ga = (long)(l0 + row) * kstride + k0 + pq * 8;
        long gb = (long)(n0 + row) * kstride + k0 + pq * 8;
        CP16(so + soff,               (const void*)(Ahi + ga));
        CP16(so + G1_TILE + soff,     (const void*)(Alo + ga));
        CP16(so + 2 * G1_TILE + soff, (const void*)(Bhi + gb));
        CP16(so + 3 * G1_TILE + soff, (const void*)(Blo + gb));
    }
}

__device__ __forceinline__ void gx_mainloop_iter(uint32_t so, int lane, int wm, int wn,
                                                 float acc[4][4][4]) {
    #pragma unroll
    for (int kk = 0; kk < 2; kk++) {
        const uint32_t arow = (uint32_t)(wm * 64 + (lane & 15));
        const uint32_t aslot = (uint32_t)(kk * 2 + (lane >> 4));
        const int g = lane >> 3;
        const uint32_t brow = (uint32_t)(wn * 32 + ((g >> 1) << 3) + (lane & 7));
        const uint32_t bslot = (uint32_t)(kk * 2 + (g & 1));

        uint32_t a_hi[4][4];
        #pragma unroll
        for (int mt = 0; mt < 4; mt++) {
            uint32_t addr = so + swz(arow + mt * 16, aslot);
            ldsm_x4(a_hi[mt][0], a_hi[mt][1], a_hi[mt][2], a_hi[mt][3], addr);
        }
        uint32_t b_hi[4][2], b_lo[4][2];
        #pragma unroll
        for (int np = 0; np < 2; np++) {
            uint32_t addr = so + 2 * G1_TILE + swz(brow + np * 16, bslot);
            ldsm_x4(b_hi[2 * np][0], b_hi[2 * np][1],
                    b_hi[2 * np + 1][0], b_hi[2 * np + 1][1], addr);
            ldsm_x4(b_lo[2 * np][0], b_lo[2 * np][1],
                    b_lo[2 * np + 1][0], b_lo[2 * np + 1][1], addr + G1_TILE);
        }
        #pragma unroll
        for (int mt = 0; mt < 4; mt++)
            #pragma unroll
            for (int nt = 0; nt < 4; nt++)
                mma16816(acc[mt][nt], a_hi[mt], b_hi[nt]);
        #pragma unroll
        for (int mt = 0; mt < 4; mt++)
            #pragma unroll
            for (int nt = 0; nt < 4; nt++)
                mma16816(acc[mt][nt], a_hi[mt], b_lo[nt]);
        uint32_t a_lo[4][4];
        #pragma unroll
        for (int mt = 0; mt < 4; mt++) {
            uint32_t addr = so + G1_TILE + swz(arow + mt * 16, aslot);
            ldsm_x4(a_lo[mt][0], a_lo[mt][1], a_lo[mt][2], a_lo[mt][3], addr);
        }
        #pragma unroll
        for (int mt = 0; mt < 4; mt++)
            #pragma unroll
            for (int nt = 0; nt < 4; nt++)
                mma16816(acc[mt][nt], a_lo[mt], b_hi[nt]);
    }
}

// ---------------- K2: GEMM1 --------------------------------------------------
__global__ void __launch_bounds__(256, 2) k_gemm1_mma() {
    extern __shared__ char smem[];
    const uint32_t sbase = smem_to_u32(smem);
    const int t    = threadIdx.x;
    const int lane = t & 31;
    const int wid  = t >> 5;
    const int wm   = wid >> 2;
    const int wn   = wid & 3;
    const int n0   = blockIdx.x * 128;
    const int l0   = blockIdx.y * 128;

    float acc[4][4][4];
    #pragma unroll
    for (int i = 0; i < 4; i++)
        #pragma unroll
        for (int j = 0; j < 4; j++)
            #pragma unroll
            for (int q = 0; q < 4; q++) acc[i][j][q] = 0.0f;

    gx_prefetch(sbase, 0, 0, l0, n0, t, d_uhi, d_ulo, d_whi, d_wlo, DMOD);
    CP_COMMIT();
    gx_prefetch(sbase, 1, 32, l0, n0, t, d_uhi, d_ulo, d_whi, d_wlo, DMOD);
    CP_COMMIT();

    for (int c = 0; c < G1_ITERS; c++) {
        CP_WAIT1();
        __syncthreads();
        if (c + 2 < G1_ITERS)
            gx_prefetch(sbase, (c + 2) % 3, (c + 2) * 32, l0, n0, t,
                        d_uhi, d_ulo, d_whi, d_wlo, DMOD);
        CP_COMMIT();
        gx_mainloop_iter(sbase + (c % 3) * G1_STAGE, lane, wm, wn, acc);
    }

    #pragma unroll
    for (int mt = 0; mt < 4; mt++) {
        int r0 = l0 + wm * 64 + mt * 16 + (lane >> 2);
        #pragma unroll
        for (int nt = 0; nt < 4; nt++) {
            int cc = n0 + wn * 32 + nt * 8 + 2 * (lane & 3);
            float2 v0 = {acc[mt][nt][0], acc[mt][nt][1]};
            float2 v1 = {acc[mt][nt][2], acc[mt][nt][3]};
            *(float2*)&d_xz[(long)r0 * (2 * DIN) + cc]       = v0;
            *(float2*)&d_xz[(long)(r0 + 8) * (2 * DIN) + cc] = v1;
        }
    }
}

// -------- K3: causal depthwise conv(4) + silu, emits fp32 + bf16 hi/lo -------
__global__ void k_conv(const float* __restrict__ convw,
                       const float* __restrict__ convb,
                       const float* __restrict__ Dvec) {
    int idx = blockIdx.x * blockDim.x + threadIdx.x;
    int lq  = idx / (DIN / 4);
    int q   = idx - lq * (DIN / 4);
    int ch0 = q * 4;
    int l0  = lq * 4;

    float4 bia = *(const float4*)&convb[ch0];
    float w4[4][4];
    #pragma unroll
    for (int j = 0; j < 4; j++) {
        float4 w = *(const float4*)&convw[(ch0 + j) * 4];
        w4[j][0] = w.x; w4[j][1] = w.y; w4[j][2] = w.z; w4[j][3] = w.w;
    }
    float4 ws = *(const float4*)&d_wsum[ch0];
    float4 Dv = *(const float4*)&Dvec[ch0];

    float4 r[7];
    #pragma unroll
    for (int k = 0; k < 7; k++) {
        int lk = l0 - 3 + k;
        if (lk >= 0) r[k] = *(const float4*)&d_xz[(long)lk * (2 * DIN) + ch0];
        else         r[k] = make_float4(0.f, 0.f, 0.f, 0.f);
    }
    float local = 0.0f;
    #pragma unroll
    for (int i = 0; i < 4; i++) {
        int l = l0 + i;
        float s0 = bia.x, s1 = bia.y, s2 = bia.z, s3 = bia.w;
        #pragma unroll
        for (int k = 0; k < 4; k++) {
            float4 v = r[i + k];
            s0 += w4[0][k] * v.x;
            s1 += w4[1][k] * v.y;
            s2 += w4[2][k] * v.z;
            s3 += w4[3][k] * v.w;
        }
        float4 zv = *(const float4*)&d_xz[(long)l * (2 * DIN) + DIN + ch0];
        float xs0 = siluf(s0), xs1 = siluf(s1), xs2 = siluf(s2), xs3 = siluf(s3);
        float g0 = siluf(zv.x) * ws.x * INV_LM;
        float g1 = siluf(zv.y) * ws.y * INV_LM;
        float g2 = siluf(zv.z) * ws.z * INV_LM;
        float g3 = siluf(zv.w) * ws.w * INV_LM;
        float4 xso = {xs0, xs1, xs2, xs3};
        float4 go  = {g0, g1, g2, g3};
        *(float4*)&d_xs[(long)l * DIN + ch0] = xso;
        *(float4*)&d_g [(long)l * DIN + ch0] = go;
        // bf16 hi/lo split of xs for the tensor-core GEMM2
        __nv_bfloat16 h0 = __float2bfloat16(xs0);
        __nv_bfloat16 h1 = __float2bfloat16(xs1);
        __nv_bfloat16 h2 = __float2bfloat16(xs2);
        __nv_bfloat16 h3 = __float2bfloat16(xs3);
        __nv_bfloat16 e0 = __float2bfloat16(xs0 - __bfloat162float(h0));
        __nv_bfloat16 e1 = __float2bfloat16(xs1 - __bfloat162float(h1));
        __nv_bfloat16 e2 = __float2bfloat16(xs2 - __bfloat162float(h2));
        __nv_bfloat16 e3 = __float2bfloat16(xs3 - __bfloat162float(h3));
        __nv_bfloat162 hp0 = {h0, h1}, hp1 = {h2, h3};
        __nv_bfloat162 ep0 = {e0, e1}, ep1 = {e2, e3};
        uint2 hv = {*(uint32_t*)&hp0, *(uint32_t*)&hp1};
        uint2 ev = {*(uint32_t*)&ep0, *(uint32_t*)&ep1};
        *(uint2*)&d_xshi[(long)l * DIN + ch0] = hv;
        *(uint2*)&d_xslo[(long)l * DIN + ch0] = ev;
        local += xs0 * Dv.x * g0 + xs1 * Dv.y * g1 + xs2 * Dv.z * g2 + xs3 * Dv.w * g3;
    }
    float tot = blockReduceSum(local);
    if (threadIdx.x == 0) d_part_conv[blockIdx.x] = tot;
}

// ---------------- K4: GEMM2 via mma.sync, split-K 8 --------------------------
#define G2_KLEN  (DIN / G2_KSPLIT)     // 192
#define G2_ITERS (G2_KLEN / 32)        // 6
__global__ void __launch_bounds__(256, 2) k_gemm2_mma() {
    extern __shared__ char smem[];
    const uint32_t sbase = smem_to_u32(smem);
    const int t    = threadIdx.x;
    const int lane = t & 31;
    const int wid  = t >> 5;
    const int wm   = wid >> 2;
    const int wn   = wid & 3;
    const int l0   = blockIdx.x * 128;
    const int kz   = blockIdx.y;
    const int kbase = kz * G2_KLEN;

    float acc[4][4][4];
    #pragma unroll
    for (int i = 0; i < 4; i++)
        #pragma unroll
        for (int j = 0; j < 4; j++)
            #pragma unroll
            for (int q = 0; q < 4; q++) acc[i][j][q] = 0.0f;

    gx_prefetch(sbase, 0, kbase, l0, 0, t, d_xshi, d_xslo, d_xpwhi, d_xpwlo, DIN);
    CP_COMMIT();
    gx_prefetch(sbase, 1, kbase + 32, l0, 0, t, d_xshi, d_xslo, d_xpwhi, d_xpwlo, DIN);
    CP_COMMIT();

    for (int c = 0; c < G2_ITERS; c++) {
        CP_WAIT1();
        __syncthreads();
        if (c + 2 < G2_ITERS)
            gx_prefetch(sbase, (c + 2) % 3, kbase + (c + 2) * 32, l0, 0, t,
                        d_xshi, d_xslo, d_xpwhi, d_xpwlo, DIN);
        CP_COMMIT();
        gx_mainloop_iter(sbase + (c % 3) * G1_STAGE, lane, wm, wn, acc);
    }

    #pragma unroll
    for (int mt = 0; mt < 4; mt++) {
        int r0 = l0 + wm * 64 + mt * 16 + (lane >> 2);
        #pragma unroll
        for (int nt = 0; nt < 4; nt++) {
            int cc = wn * 32 + nt * 8 + 2 * (lane & 3);
            if (cc + 1 < NCOL) {
                float2 v0 = {acc[mt][nt][0], acc[mt][nt][1]};
                float2 v1 = {acc[mt][nt][2], acc[mt][nt][3]};
                *(float2*)&d_dbc_part[kz][(long)r0 * NCOL + cc]       = v0;
                *(float2*)&d_dbc_part[kz][(long)(r0 + 8) * NCOL + cc] = v1;
            }
        }
    }
}

// ---------------- K4b: reduce split-K partials -------------------------------
__global__ void k_g2red() {
    int idx = blockIdx.x * 256 + threadIdx.x;   // < LSEQ*NCOL
    float s = 0.0f;
    #pragma unroll
    for (int kz = 0; kz < G2_KSPLIT; kz++) s += d_dbc_part[kz][idx];
    d_dbc[idx] = s;
}

// ---------------- K5: dt = softplus(dbc[:, :48] @ dtw^T + b) -----------------
__global__ void k_dt(const float* __restrict__ dtw,
                     const float* __restrict__ dtb) {
    __shared__ __align__(16) float4 sdbc[128][12];
    int t  = threadIdx.x;
    int d  = blockIdx.x * 128 + t;
    int l0 = blockIdx.y * 128;
    float4 wr[12];
    #pragma unroll
    for (int r4 = 0; r4 < 12; r4++) wr[r4] = *(const float4*)&dtw[d * 48 + r4 * 4];
    float bias = dtb[d];
    for (int p = t; p < 128 * 12; p += 128) {
        int li = p / 12;
        int r4 = p - li * 12;
        sdbc[li][r4] = *(const float4*)&d_dbc[(l0 + li) * NCOL + r4 * 4];
    }
    __syncthreads();
    for (int li = 0; li < 128; li++) {
        float s = bias;
        #pragma unroll
        for (int r4 = 0; r4 < 12; r4++) {
            float4 v = sdbc[li][r4];
            s += wr[r4].x * v.x + wr[r4].y * v.y + wr[r4].z * v.z + wr[r4].w * v.w;
        }
        float sp = (s > 20.0f) ? s : __logf(1.0f + __expf(s));
        d_dt[(l0 + li) * DIN + d] = sp;
    }
}

// ---------------- K6: scan pass 1 — one thread owns 16 states of one d -------
__global__ void k_scan1(const float* __restrict__ A_log) {
    __shared__ __align__(16) float sB[CHLEN][DST];
    __shared__ __align__(16) float sC[CHLEN][DST];
    int t = threadIdx.x;
    int d = blockIdx.x * 256 + t;
    int c = blockIdx.y;
    int base = c * CHLEN;
    for (int p = t; p < CHLEN * DST; p += 256) {
        int r = p >> 4, s = p & 15;
        sB[r][s] = d_dbc[(base + r) * NCOL + RNK + s];
        sC[r][s] = d_dbc[(base + r) * NCOL + RNK + DST + s];
    }
    __syncthreads();

    float Av[DST];
    #pragma unroll
    for (int s = 0; s < DST; s++) Av[s] = -__expf(A_log[d * DST + s]);
    bool fast = true;
    #pragma unroll
    for (int s = 1; s < DST; s++) {
        float r = Av[s] / Av[0];
        fast = fast && (fabsf(r - (float)(s + 1)) < 1e-3f);
    }

    float h[DST], cp[DST], K[DST];
    #pragma unroll
    for (int s = 0; s < DST; s++) { h[s] = 0.0f; cp[s] = 1.0f; K[s] = 0.0f; }
    float acc = 0.0f;

    for (int i = 0; i < CHLEN; i++) {
        int l = base + i;
        float dtv = d_dt[(long)l * DIN + d];
        float xsv = d_xs[(long)l * DIN + d];
        float gv  = d_g [(long)l * DIN + d];
        float dtx = dtv * xsv;
        float dAv[DST];
        if (fast) {
            float E  = __expf(dtv * Av[0]);
            float p2 = E * E, p4 = p2 * p2, p8 = p4 * p4;
            dAv[0] = E;        dAv[1] = p2;       dAv[2] = p2 * E;
            dAv[3] = p4;       dAv[4] = p4 * E;   dAv[5] = p4 * p2;
            dAv[6] = p4 * dAv[2]; dAv[7] = p8;
            dAv[8] = p8 * E;   dAv[9] = p8 * p2;  dAv[10] = p8 * dAv[2];
            dAv[11] = p8 * p4; dAv[12] = p8 * dAv[4]; dAv[13] = p8 * dAv[5];
            dAv[14] = p8 * dAv[6]; dAv[15] = p8 * p8;
        } else {
            #pragma unroll
            for (int s = 0; s < DST; s++) dAv[s] = __expf(dtv * Av[s]);
        }
        #pragma unroll
        for (int s = 0; s < DST; s++) {
            float dA = dAv[s];
            cp[s] *= dA;
            h[s] = dA * h[s] + dtx * sB[i][s];
            float cg = sC[i][s] * gv;
            acc  += h[s] * cg;
            K[s] += cp[s] * cg;
        }
    }
    long off = ((long)c * DIN + d) * DST;
    #pragma unroll
    for (int s = 0; s < DST; s++) {
        d_P [off + s] = cp[s];
        d_E [off + s] = h[s];
        d_Kc[off + s] = K[s];
    }
    float tot = blockReduceSum(acc);
    if (t == 0) d_part_scan[c * 6 + blockIdx.x] = tot;
}

// ---------------- K7: scan pass 2 (chunk combine) ----------------------------
__global__ void k_scan2() {
    int gid = blockIdx.x * 256 + threadIdx.x;
    float h = 0.0f, St = 0.0f;
    for (int c = 0; c < NCHUNK; c++) {
        long off = (long)c * (DIN * DST) + gid;
        St += d_Kc[off] * h;
        h   = d_P[off] * h + d_E[off];
    }
    float tot = blockReduceSum(St);
    if (threadIdx.x == 0) d_part_p2[blockIdx.x] = tot;
}

// ---------------- K8: deterministic final reduce -----------------------------
__global__ void k_final(float* __restrict__ out) {
    int t = threadIdx.x;
    float v = 0.0f;
    for (int i = t; i < 1536; i += 256)          v += d_part_conv[i];
    for (int i = t; i < NCHUNK * 6; i += 256)    v += d_part_scan[i];
    for (int i = t; i < 96; i += 256)            v += d_part_p2[i];
    float tot = blockReduceSum(v);
    if (t == 0) out[0] = tot;
}

// ---------------- launch -----------------------------------------------------
extern "C" void kernel_launch(void* const* d_in, const int* in_sizes, int n_in,
                              void* d_out, int out_size) {
    const float* x     = (const float*)d_in[0];
    const float* w_in  = (const float*)d_in[1];
    const float* convw = (const float*)d_in[2];
    const float* convb = (const float*)d_in[3];
    const float* xpw   = (const float*)d_in[4];
    const float* dtw   = (const float*)d_in[5];
    const float* dtb   = (const float*)d_in[6];
    const float* A_log = (const float*)d_in[7];
    const float* Dvec  = (const float*)d_in[8];
    const float* opw   = (const float*)d_in[9];
    float* out = (float*)d_out;

    static int configured = 0;
    if (!configured) {
        cudaFuncSetAttribute(k_gemm1_mma, cudaFuncAttributeMaxDynamicSharedMemorySize, G1_SMEM);
        cudaFuncSetAttribute(k_gemm2_mma, cudaFuncAttributeMaxDynamicSharedMemorySize, G1_SMEM);
        configured = 1;
    }

    k_prep<<<PB_PATCH + PB_WSPLIT + PB_XPAD + PB_COLSUM, 256>>>(x, w_in, xpw, opw);
    k_gemm1_mma<<<dim3(2 * DIN / 128, LSEQ / 128), 256, G1_SMEM>>>();
    k_conv<<<(LSEQ / 4) * (DIN / 4) / 256, 256>>>(convw, convb, Dvec);
    k_gemm2_mma<<<dim3(LSEQ / 128, G2_KSPLIT), 256, G1_SMEM>>>();
    k_g2red<<<(LSEQ * NCOL) / 256, 256>>>();
    k_dt<<<dim3(DIN / 128, LSEQ / 128), 128>>>(dtw, dtb);
    k_scan1<<<dim3(DIN / 256, NCHUNK), 256>>>(A_log);
    k_scan2<<<96, 256>>>();
    k_final<<<1, 256>>>(out);
}

// round 9
// speedup vs baseline: 2.7636x; 1.0586x over previous
#include <cuda_runtime.h>
#include <cuda_bf16.h>
#include <math.h>
#include <stdint.h>

#define LSEQ 4096
#define DMOD 768
#define DIN  1536
#define DST  16
#define RNK  48
#define NCOL 80
#define NCHUNK 128
#define CHLEN  32
#define INV_LM (1.0f / (4096.0f * 768.0f))

// ---------------- scratch ----------------------------------------------------
__device__ float d_wsum[DIN];
__device__ __nv_bfloat16 d_uhi[LSEQ * DMOD];
__device__ __nv_bfloat16 d_ulo[LSEQ * DMOD];
__device__ __nv_bfloat16 d_whi[2 * DIN * DMOD];
__device__ __nv_bfloat16 d_wlo[2 * DIN * DMOD];
__device__ __nv_bfloat16 d_xshi[LSEQ * DIN];
__device__ __nv_bfloat16 d_xslo[LSEQ * DIN];
__device__ __nv_bfloat16 d_xpwhi[128 * DIN];   // padded x_proj_w (rows 80..127 = 0)
__device__ __nv_bfloat16 d_xpwlo[128 * DIN];
__device__ __nv_bfloat16 d_dbchi[LSEQ * 64];   // dbc[:, :48] K-padded to 64
__device__ __nv_bfloat16 d_dbclo[LSEQ * 64];
__device__ __nv_bfloat16 d_dtwhi[DIN * 64];    // dt_proj_w K-padded to 64
__device__ __nv_bfloat16 d_dtwlo[DIN * 64];
__device__ float d_xz[LSEQ * 2 * DIN];
__device__ float d_xs[LSEQ * DIN];
__device__ float d_g [LSEQ * DIN];
__device__ float d_dt[LSEQ * DIN];
__device__ float d_dbc[LSEQ * NCOL];
#define G2_KSPLIT 8
__device__ float d_dbc_part[G2_KSPLIT][LSEQ * NCOL];
__device__ float d_P [NCHUNK * DIN * DST];
__device__ float d_E [NCHUNK * DIN * DST];
__device__ float d_Kc[NCHUNK * DIN * DST];
__device__ float d_part_conv[1536];
__device__ float d_part_scan[NCHUNK * 6];
__device__ float d_part_p2[96];

__device__ __forceinline__ float siluf(float x) { return x / (1.0f + __expf(-x)); }
__device__ __forceinline__ float softplusf(float s) {
    return (s > 20.0f) ? s : __logf(1.0f + __expf(s));
}

__device__ __forceinline__ float blockReduceSum(float v) {
    __shared__ float sh[32];
    int lane = threadIdx.x & 31;
    int w    = threadIdx.x >> 5;
    #pragma unroll
    for (int o = 16; o > 0; o >>= 1) v += __shfl_down_sync(0xffffffffu, v, o);
    if (lane == 0) sh[w] = v;
    __syncthreads();
    int nw = blockDim.x >> 5;
    v = (threadIdx.x < nw) ? sh[threadIdx.x] : 0.0f;
    if (w == 0) {
        #pragma unroll
        for (int o = 16; o > 0; o >>= 1) v += __shfl_down_sync(0xffffffffu, v, o);
    }
    return v;
}

// ---------------- asm helpers (sm_80-baseline) -------------------------------
__device__ __forceinline__ uint32_t smem_to_u32(const void* p) {
    uint32_t a;
    asm("{ .reg .u64 t; cvta.to.shared.u64 t, %1; cvt.u32.u64 %0, t; }" : "=r"(a) : "l"(p));
    return a;
}
#define CP16(sm, gp) \
    asm volatile("cp.async.cg.shared.global [%0], [%1], 16;" :: "r"(sm), "l"(gp))
#define CP_COMMIT() asm volatile("cp.async.commit_group;" ::: "memory")
#define CP_WAIT1()  asm volatile("cp.async.wait_group 1;" ::: "memory")

__device__ __forceinline__ void ldsm_x4(uint32_t& r0, uint32_t& r1, uint32_t& r2,
                                        uint32_t& r3, uint32_t addr) {
    asm volatile("ldmatrix.sync.aligned.m8n8.x4.shared.b16 {%0,%1,%2,%3}, [%4];"
                 : "=r"(r0), "=r"(r1), "=r"(r2), "=r"(r3) : "r"(addr));
}
__device__ __forceinline__ void mma16816(float* c, const uint32_t* a, const uint32_t* b) {
    asm volatile("mma.sync.aligned.m16n8k16.row.col.f32.bf16.bf16.f32 "
                 "{%0,%1,%2,%3}, {%4,%5,%6,%7}, {%8,%9}, {%0,%1,%2,%3};"
                 : "+f"(c[0]), "+f"(c[1]), "+f"(c[2]), "+f"(c[3])
                 : "r"(a[0]), "r"(a[1]), "r"(a[2]), "r"(a[3]), "r"(b[0]), "r"(b[1]));
}

// swizzled 64B-row addressing: row r, 16B slot s -> conflict-free ldmatrix
__device__ __forceinline__ uint32_t swz(uint32_t row, uint32_t slot) {
    return row * 64u + ((slot ^ ((row >> 1) & 3u)) << 4);
}

// ---------------- K_prep: wsplit + xpw pad + dtw pad + colsum ----------------
#define PB_WSPLIT ((2 * DIN * DMOD) / 256)       // 9216
#define PB_XPAD   ((128 * DIN) / 256)            // 768
#define PB_DTW    ((DIN * 64) / 256)             // 384
#define PB_COLSUM (DIN / 16)                     // 96
__global__ void k_prep(const float* __restrict__ w,
                       const float* __restrict__ xpw,
                       const float* __restrict__ dtw,
                       const float* __restrict__ opw) {
    int bid = blockIdx.x;
    int t = threadIdx.x;
    if (bid < PB_WSPLIT) {
        int idx = bid * 256 + t;
        float v = w[idx];
        __nv_bfloat16 hi = __float2bfloat16(v);
        __nv_bfloat16 lo = __float2bfloat16(v - __bfloat162float(hi));
        d_whi[idx] = hi;
        d_wlo[idx] = lo;
    } else if (bid < PB_WSPLIT + PB_XPAD) {
        int idx = (bid - PB_WSPLIT) * 256 + t;   // row*1536 + k
        int row = idx / DIN;
        float v = (row < NCOL) ? xpw[idx] : 0.0f;
        __nv_bfloat16 hi = __float2bfloat16(v);
        __nv_bfloat16 lo = __float2bfloat16(v - __bfloat162float(hi));
        d_xpwhi[idx] = hi;
        d_xpwlo[idx] = lo;
    } else if (bid < PB_WSPLIT + PB_XPAD + PB_DTW) {
        int idx = (bid - PB_WSPLIT - PB_XPAD) * 256 + t;   // row*64 + k
        int row = idx >> 6;
        int k   = idx & 63;
        float v = (k < RNK) ? dtw[row * RNK + k] : 0.0f;
        __nv_bfloat16 hi = __float2bfloat16(v);
        __nv_bfloat16 lo = __float2bfloat16(v - __bfloat162float(hi));
        d_dtwhi[idx] = hi;
        d_dtwlo[idx] = lo;
    } else {
        int cb = bid - PB_WSPLIT - PB_XPAD - PB_DTW;
        __shared__ float sh[16][17];
        int dl = t & 15;
        int mg = t >> 4;
        int d  = cb * 16 + dl;
        float s = 0.0f;
        for (int m = mg * 48; m < mg * 48 + 48; m++) s += opw[m * DIN + d];
        sh[dl][mg] = s;
        __syncthreads();
        if (t < 16) {
            float tot = 0.0f;
            #pragma unroll
            for (int g = 0; g < 16; g++) tot += sh[t][g];
            d_wsum[cb * 16 + t] = tot;
        }
    }
}

// ---------------- K_patchT: coalesced patchify via smem transpose ------------
// u[l][d] = x[c][ih*16+a][iw*16+b];  d = c*256 + ih*4 + iwq;  iw = iwq*16+iwr;
// l = iwr*256 + a*16 + b.  Block = (c, ih-group of 8, a): reads 8 contiguous
// source rows, writes 64B-contiguous [l][d] chunks for 256 l values.
__global__ void k_patchT(const float* __restrict__ x) {
    __shared__ __nv_bfloat16 shi[8][1024];
    __shared__ __nv_bfloat16 slo[8][1024];
    int bid = blockIdx.x;              // 3 * 8 * 16 = 384
    int c   = bid >> 7;                // /128
    int rem = bid & 127;
    int ih0 = (rem >> 4) * 8;
    int a   = rem & 15;
    int t = threadIdx.x;

    // phase 1: coalesced read of 8 source rows (H = (ih0+row)*16 + a)
    #pragma unroll
    for (int rep = 0; rep < 8; rep++) {
        int j    = t + rep * 256;      // float4 index 0..2047
        int row  = j >> 8;
        int col4 = j & 255;
        int H = (ih0 + row) * 16 + a;
        float4 v = *(const float4*)&x[c * 1048576 + H * 1024 + col4 * 4];
        float vv[4] = {v.x, v.y, v.z, v.w};
        #pragma unroll
        for (int i = 0; i < 4; i++) {
            __nv_bfloat16 hi = __float2bfloat16(vv[i]);
            __nv_bfloat16 lo = __float2bfloat16(vv[i] - __bfloat162float(hi));
            shi[row][col4 * 4 + i] = hi;
            slo[row][col4 * 4 + i] = lo;
        }
    }
    __syncthreads();

    // phase 2: each thread owns one l, writes 32 consecutive d (64B/array)
    int iwr = t >> 4, b = t & 15;
    int l  = iwr * 256 + a * 16 + b;
    int d0 = c * 256 + ih0 * 4;        // multiple of 32
    int colbase = iwr * 16 + b;
    uint32_t hv[16], lv[16];
    #pragma unroll
    for (int j = 0; j < 16; j++) {
        int d2 = 2 * j;
        int i0 = d2 >> 2,      q0 = d2 & 3;
        int i1 = (d2 + 1) >> 2, q1 = (d2 + 1) & 3;
        __nv_bfloat162 hp = {shi[i0][q0 * 256 + colbase], shi[i1][q1 * 256 + colbase]};
        __nv_bfloat162 lp = {slo[i0][q0 * 256 + colbase], slo[i1][q1 * 256 + colbase]};
        hv[j] = *(uint32_t*)&hp;
        lv[j] = *(uint32_t*)&lp;
    }
    long base = (long)l * DMOD + d0;
    #pragma unroll
    for (int j = 0; j < 4; j++) {
        uint4 qh = {hv[4 * j], hv[4 * j + 1], hv[4 * j + 2], hv[4 * j + 3]};
        uint4 ql = {lv[4 * j], lv[4 * j + 1], lv[4 * j + 2], lv[4 * j + 3]};
        *(uint4*)&d_uhi[base + j * 8] = qh;
        *(uint4*)&d_ulo[base + j * 8] = ql;
    }
}

// ---------------- shared GEMM machinery --------------------------------------
#define G1_TILE   8192                  // 128 rows * 64 B
#define G1_STAGE  (4 * G1_TILE)         // Ahi, Alo, Bhi, Blo = 32768 B
#define G1_SMEM   (3 * G1_STAGE)        // 98304 B
#define G1_ITERS  24                    // 768 / 32

__device__ __forceinline__ void gx_prefetch(
        uint32_t sbase, int stage, int k0, int l0, int n0, int t,
        const __nv_bfloat16* Ahi, const __nv_bfloat16* Alo,
        const __nv_bfloat16* Bhi, const __nv_bfloat16* Blo, int kstride) {
    const uint32_t so = sbase + stage * G1_STAGE;
    const int prow = t >> 2;
    const int pq   = t & 3;
    #pragma unroll
    for (int rep = 0; rep < 2; rep++) {
        int row = prow + rep * 64;
        uint32_t soff = swz((uint32_t)row, (uint32_t)pq);
        long ga = (long)(l0 + row) * kstride + k0 + pq * 8;
        long gb = (long)(n0 + row) * kstride + k0 + pq * 8;
        CP16(so + soff,               (const void*)(Ahi + ga));
        CP16(so + G1_TILE + soff,     (const void*)(Alo + ga));
        CP16(so + 2 * G1_TILE + soff, (const void*)(Bhi + gb));
        CP16(so + 3 * G1_TILE + soff, (const void*)(Blo + gb));
    }
}

__device__ __forceinline__ void gx_mainloop_iter(uint32_t so, int lane, int wm, int wn,
                                                 float acc[4][4][4]) {
    #pragma unroll
    for (int kk = 0; kk < 2; kk++) {
        const uint32_t arow = (uint32_t)(wm * 64 + (lane & 15));
        const uint32_t aslot = (uint32_t)(kk * 2 + (lane >> 4));
        const int g = lane >> 3;
        const uint32_t brow = (uint32_t)(wn * 32 + ((g >> 1) << 3) + (lane & 7));
        const uint32_t bslot = (uint32_t)(kk * 2 + (g & 1));

        uint32_t a_hi[4][4];
        #pragma unroll
        for (int mt = 0; mt < 4; mt++) {
            uint32_t addr = so + swz(arow + mt * 16, aslot);
            ldsm_x4(a_hi[mt][0], a_hi[mt][1], a_hi[mt][2], a_hi[mt][3], addr);
        }
        uint32_t b_hi[4][2], b_lo[4][2];
        #pragma unroll
        for (int np = 0; np < 2; np++) {
            uint32_t addr = so + 2 * G1_TILE + swz(brow + np * 16, bslot);
            ldsm_x4(b_hi[2 * np][0], b_hi[2 * np][1],
                    b_hi[2 * np + 1][0], b_hi[2 * np + 1][1], addr);
            ldsm_x4(b_lo[2 * np][0], b_lo[2 * np][1],
                    b_lo[2 * np + 1][0], b_lo[2 * np + 1][1], addr + G1_TILE);
        }
        #pragma unroll
        for (int mt = 0; mt < 4; mt++)
            #pragma unroll
            for (int nt = 0; nt < 4; nt++)
                mma16816(acc[mt][nt], a_hi[mt], b_hi[nt]);
        #pragma unroll
        for (int mt = 0; mt < 4; mt++)
            #pragma unroll
            for (int nt = 0; nt < 4; nt++)
                mma16816(acc[mt][nt], a_hi[mt], b_lo[nt]);
        uint32_t a_lo[4][4];
        #pragma unroll
        for (int mt = 0; mt < 4; mt++) {
            uint32_t addr = so + G1_TILE + swz(arow + mt * 16, aslot);
            ldsm_x4(a_lo[mt][0], a_lo[mt][1], a_lo[mt][2], a_lo[mt][3], addr);
        }
        #pragma unroll
        for (int mt = 0; mt < 4; mt++)
            #pragma unroll
            for (int nt = 0; nt < 4; nt++)
                mma16816(acc[mt][nt], a_lo[mt], b_hi[nt]);
    }
}

// ---------------- K2: GEMM1 --------------------------------------------------
__global__ void __launch_bounds__(256, 2) k_gemm1_mma() {
    extern __shared__ char smem[];
    const uint32_t sbase = smem_to_u32(smem);
    const int t    = threadIdx.x;
    const int lane = t & 31;
    const int wid  = t >> 5;
    const int wm   = wid >> 2;
    const int wn   = wid & 3;
    const int n0   = blockIdx.x * 128;
    const int l0   = blockIdx.y * 128;

    float acc[4][4][4];
    #pragma unroll
    for (int i = 0; i < 4; i++)
        #pragma unroll
        for (int j = 0; j < 4; j++)
            #pragma unroll
            for (int q = 0; q < 4; q++) acc[i][j][q] = 0.0f;

    gx_prefetch(sbase, 0, 0, l0, n0, t, d_uhi, d_ulo, d_whi, d_wlo, DMOD);
    CP_COMMIT();
    gx_prefetch(sbase, 1, 32, l0, n0, t, d_uhi, d_ulo, d_whi, d_wlo, DMOD);
    CP_COMMIT();

    for (int c = 0; c < G1_ITERS; c++) {
        CP_WAIT1();
        __syncthreads();
        if (c + 2 < G1_ITERS)
            gx_prefetch(sbase, (c + 2) % 3, (c + 2) * 32, l0, n0, t,
                        d_uhi, d_ulo, d_whi, d_wlo, DMOD);
        CP_COMMIT();
        gx_mainloop_iter(sbase + (c % 3) * G1_STAGE, lane, wm, wn, acc);
    }

    #pragma unroll
    for (int mt = 0; mt < 4; mt++) {
        int r0 = l0 + wm * 64 + mt * 16 + (lane >> 2);
        #pragma unroll
        for (int nt = 0; nt < 4; nt++) {
            int cc = n0 + wn * 32 + nt * 8 + 2 * (lane & 3);
            float2 v0 = {acc[mt][nt][0], acc[mt][nt][1]};
            float2 v1 = {acc[mt][nt][2], acc[mt][nt][3]};
            *(float2*)&d_xz[(long)r0 * (2 * DIN) + cc]       = v0;
            *(float2*)&d_xz[(long)(r0 + 8) * (2 * DIN) + cc] = v1;
        }
    }
}

// -------- K3: causal depthwise conv(4) + silu, emits fp32 + bf16 hi/lo -------
__global__ void k_conv(const float* __restrict__ convw,
                       const float* __restrict__ convb,
                       const float* __restrict__ Dvec) {
    int idx = blockIdx.x * blockDim.x + threadIdx.x;
    int lq  = idx / (DIN / 4);
    int q   = idx - lq * (DIN / 4);
    int ch0 = q * 4;
    int l0  = lq * 4;

    float4 bia = *(const float4*)&convb[ch0];
    float w4[4][4];
    #pragma unroll
    for (int j = 0; j < 4; j++) {
        float4 w = *(const float4*)&convw[(ch0 + j) * 4];
        w4[j][0] = w.x; w4[j][1] = w.y; w4[j][2] = w.z; w4[j][3] = w.w;
    }
    float4 ws = *(const float4*)&d_wsum[ch0];
    float4 Dv = *(const float4*)&Dvec[ch0];

    float4 r[7];
    #pragma unroll
    for (int k = 0; k < 7; k++) {
        int lk = l0 - 3 + k;
        if (lk >= 0) r[k] = *(const float4*)&d_xz[(long)lk * (2 * DIN) + ch0];
        else         r[k] = make_float4(0.f, 0.f, 0.f, 0.f);
    }
    float local = 0.0f;
    #pragma unroll
    for (int i = 0; i < 4; i++) {
        int l = l0 + i;
        float s0 = bia.x, s1 = bia.y, s2 = bia.z, s3 = bia.w;
        #pragma unroll
        for (int k = 0; k < 4; k++) {
            float4 v = r[i + k];
            s0 += w4[0][k] * v.x;
            s1 += w4[1][k] * v.y;
            s2 += w4[2][k] * v.z;
            s3 += w4[3][k] * v.w;
        }
        float4 zv = *(const float4*)&d_xz[(long)l * (2 * DIN) + DIN + ch0];
        float xs0 = siluf(s0), xs1 = siluf(s1), xs2 = siluf(s2), xs3 = siluf(s3);
        float g0 = siluf(zv.x) * ws.x * INV_LM;
        float g1 = siluf(zv.y) * ws.y * INV_LM;
        float g2 = siluf(zv.z) * ws.z * INV_LM;
        float g3 = siluf(zv.w) * ws.w * INV_LM;
        float4 xso = {xs0, xs1, xs2, xs3};
        float4 go  = {g0, g1, g2, g3};
        *(float4*)&d_xs[(long)l * DIN + ch0] = xso;
        *(float4*)&d_g [(long)l * DIN + ch0] = go;
        __nv_bfloat16 h0 = __float2bfloat16(xs0);
        __nv_bfloat16 h1 = __float2bfloat16(xs1);
        __nv_bfloat16 h2 = __float2bfloat16(xs2);
        __nv_bfloat16 h3 = __float2bfloat16(xs3);
        __nv_bfloat16 e0 = __float2bfloat16(xs0 - __bfloat162float(h0));
        __nv_bfloat16 e1 = __float2bfloat16(xs1 - __bfloat162float(h1));
        __nv_bfloat16 e2 = __float2bfloat16(xs2 - __bfloat162float(h2));
        __nv_bfloat16 e3 = __float2bfloat16(xs3 - __bfloat162float(h3));
        __nv_bfloat162 hp0 = {h0, h1}, hp1 = {h2, h3};
        __nv_bfloat162 ep0 = {e0, e1}, ep1 = {e2, e3};
        uint2 hv = {*(uint32_t*)&hp0, *(uint32_t*)&hp1};
        uint2 ev = {*(uint32_t*)&ep0, *(uint32_t*)&ep1};
        *(uint2*)&d_xshi[(long)l * DIN + ch0] = hv;
        *(uint2*)&d_xslo[(long)l * DIN + ch0] = ev;
        local += xs0 * Dv.x * g0 + xs1 * Dv.y * g1 + xs2 * Dv.z * g2 + xs3 * Dv.w * g3;
    }
    float tot = blockReduceSum(local);
    if (threadIdx.x == 0) d_part_conv[blockIdx.x] = tot;
}

// ---------------- K4: GEMM2 via mma.sync, split-K 8 --------------------------
#define G2_KLEN  (DIN / G2_KSPLIT)     // 192
#define G2_ITERS (G2_KLEN / 32)        // 6
__global__ void __launch_bounds__(256, 2) k_gemm2_mma() {
    extern __shared__ char smem[];
    const uint32_t sbase = smem_to_u32(smem);
    const int t    = threadIdx.x;
    const int lane = t & 31;
    const int wid  = t >> 5;
    const int wm   = wid >> 2;
    const int wn   = wid & 3;
    const int l0   = blockIdx.x * 128;
    const int kz   = blockIdx.y;
    const int kbase = kz * G2_KLEN;

    float acc[4][4][4];
    #pragma unroll
    for (int i = 0; i < 4; i++)
        #pragma unroll
        for (int j = 0; j < 4; j++)
            #pragma unroll
            for (int q = 0; q < 4; q++) acc[i][j][q] = 0.0f;

    gx_prefetch(sbase, 0, kbase, l0, 0, t, d_xshi, d_xslo, d_xpwhi, d_xpwlo, DIN);
    CP_COMMIT();
    gx_prefetch(sbase, 1, kbase + 32, l0, 0, t, d_xshi, d_xslo, d_xpwhi, d_xpwlo, DIN);
    CP_COMMIT();

    for (int c = 0; c < G2_ITERS; c++) {
        CP_WAIT1();
        __syncthreads();
        if (c + 2 < G2_ITERS)
            gx_prefetch(sbase, (c + 2) % 3, kbase + (c + 2) * 32, l0, 0, t,
                        d_xshi, d_xslo, d_xpwhi, d_xpwlo, DIN);
        CP_COMMIT();
        gx_mainloop_iter(sbase + (c % 3) * G1_STAGE, lane, wm, wn, acc);
    }

    #pragma unroll
    for (int mt = 0; mt < 4; mt++) {
        int r0 = l0 + wm * 64 + mt * 16 + (lane >> 2);
        #pragma unroll
        for (int nt = 0; nt < 4; nt++) {
            int cc = wn * 32 + nt * 8 + 2 * (lane & 3);
            if (cc + 1 < NCOL) {
                float2 v0 = {acc[mt][nt][0], acc[mt][nt][1]};
                float2 v1 = {acc[mt][nt][2], acc[mt][nt][3]};
                *(float2*)&d_dbc_part[kz][(long)r0 * NCOL + cc]       = v0;
                *(float2*)&d_dbc_part[kz][(long)(r0 + 8) * NCOL + cc] = v1;
            }
        }
    }
}

// ---------------- K4b: reduce split-K partials + emit dbc hi/lo --------------
__global__ void k_g2red() {
    int idx = blockIdx.x * 256 + threadIdx.x;   // < LSEQ*NCOL
    float s = 0.0f;
    #pragma unroll
    for (int kz = 0; kz < G2_KSPLIT; kz++) s += d_dbc_part[kz][idx];
    d_dbc[idx] = s;
    int l   = idx / NCOL;
    int col = idx - l * NCOL;
    if (col < RNK) {
        __nv_bfloat16 hi = __float2bfloat16(s);
        __nv_bfloat16 lo = __float2bfloat16(s - __bfloat162float(hi));
        d_dbchi[l * 64 + col] = hi;
        d_dbclo[l * 64 + col] = lo;
    } else if (col >= 64) {
        // cols 64..79 map to pad slots 48..63
        __nv_bfloat16 z = __float2bfloat16(0.0f);
        d_dbchi[l * 64 + col - 16] = z;
        d_dbclo[l * 64 + col - 16] = z;
    }
}

// ---------------- K5: dt via mma.sync (M=4096, N=1536, K=48->64) -------------
#define DT_ITERS 2
__global__ void __launch_bounds__(256, 2) k_dt_mma(const float* __restrict__ dtb) {
    extern __shared__ char smem[];
    const uint32_t sbase = smem_to_u32(smem);
    const int t    = threadIdx.x;
    const int lane = t & 31;
    const int wid  = t >> 5;
    const int wm   = wid >> 2;
    const int wn   = wid & 3;
    const int l0   = blockIdx.x * 128;
    const int n0   = blockIdx.y * 128;

    float acc[4][4][4];
    #pragma unroll
    for (int i = 0; i < 4; i++)
        #pragma unroll
        for (int j = 0; j < 4; j++)
            #pragma unroll
            for (int q = 0; q < 4; q++) acc[i][j][q] = 0.0f;

    gx_prefetch(sbase, 0, 0, l0, n0, t, d_dbchi, d_dbclo, d_dtwhi, d_dtwlo, 64);
    CP_COMMIT();
    gx_prefetch(sbase, 1, 32, l0, n0, t, d_dbchi, d_dbclo, d_dtwhi, d_dtwlo, 64);
    CP_COMMIT();

    for (int c = 0; c < DT_ITERS; c++) {
        CP_WAIT1();
        __syncthreads();
        CP_COMMIT();
        gx_mainloop_iter(sbase + (c % 3) * G1_STAGE, lane, wm, wn, acc);
    }

    #pragma unroll
    for (int mt = 0; mt < 4; mt++) {
        int r0 = l0 + wm * 64 + mt * 16 + (lane >> 2);
        #pragma unroll
        for (int nt = 0; nt < 4; nt++) {
            int cc = n0 + wn * 32 + nt * 8 + 2 * (lane & 3);
            float b0 = dtb[cc], b1 = dtb[cc + 1];
            float2 v0 = {softplusf(acc[mt][nt][0] + b0), softplusf(acc[mt][nt][1] + b1)};
            float2 v1 = {softplusf(acc[mt][nt][2] + b0), softplusf(acc[mt][nt][3] + b1)};
            *(float2*)&d_dt[(long)r0 * DIN + cc]       = v0;
            *(float2*)&d_dt[(long)(r0 + 8) * DIN + cc] = v1;
        }
    }
}

// ---------------- K6: scan pass 1 — one thread owns 16 states of one d -------
__global__ void k_scan1(const float* __restrict__ A_log) {
    __shared__ __align__(16) float sB[CHLEN][DST];
    __shared__ __align__(16) float sC[CHLEN][DST];
    int t = threadIdx.x;
    int d = blockIdx.x * 256 + t;
    int c = blockIdx.y;
    int base = c * CHLEN;
    for (int p = t; p < CHLEN * DST; p += 256) {
        int r = p >> 4, s = p & 15;
        sB[r][s] = d_dbc[(base + r) * NCOL + RNK + s];
        sC[r][s] = d_dbc[(base + r) * NCOL + RNK + DST + s];
    }
    __syncthreads();

    float Av[DST];
    #pragma unroll
    for (int s = 0; s < DST; s++) Av[s] = -__expf(A_log[d * DST + s]);
    bool fast = true;
    #pragma unroll
    for (int s = 1; s < DST; s++) {
        float r = Av[s] / Av[0];
        fast = fast && (fabsf(r - (float)(s + 1)) < 1e-3f);
    }

    float h[DST], cp[DST], K[DST];
    #pragma unroll
    for (int s = 0; s < DST; s++) { h[s] = 0.0f; cp[s] = 1.0f; K[s] = 0.0f; }
    float acc = 0.0f;

    for (int i = 0; i < CHLEN; i++) {
        int l = base + i;
        float dtv = d_dt[(long)l * DIN + d];
        float xsv = d_xs[(long)l * DIN + d];
        float gv  = d_g [(long)l * DIN + d];
        float dtx = dtv * xsv;
        float dAv[DST];
        if (fast) {
            float E  = __expf(dtv * Av[0]);
            float p2 = E * E, p4 = p2 * p2, p8 = p4 * p4;
            dAv[0] = E;        dAv[1] = p2;       dAv[2] = p2 * E;
            dAv[3] = p4;       dAv[4] = p4 * E;   dAv[5] = p4 * p2;
            dAv[6] = p4 * dAv[2]; dAv[7] = p8;
            dAv[8] = p8 * E;   dAv[9] = p8 * p2;  dAv[10] = p8 * dAv[2];
            dAv[11] = p8 * p4; dAv[12] = p8 * dAv[4]; dAv[13] = p8 * dAv[5];
            dAv[14] = p8 * dAv[6]; dAv[15] = p8 * p8;
        } else {
            #pragma unroll
            for (int s = 0; s < DST; s++) dAv[s] = __expf(dtv * Av[s]);
        }
        #pragma unroll
        for (int s = 0; s < DST; s++) {
            float dA = dAv[s];
            cp[s] *= dA;
            h[s] = dA * h[s] + dtx * sB[i][s];
            float cg = sC[i][s] * gv;
            acc  += h[s] * cg;
            K[s] += cp[s] * cg;
        }
    }
    long off = ((long)c * DIN + d) * DST;
    #pragma unroll
    for (int s = 0; s < DST; s++) {
        d_P [off + s] = cp[s];
        d_E [off + s] = h[s];
        d_Kc[off + s] = K[s];
    }
    float tot = blockReduceSum(acc);
    if (t == 0) d_part_scan[c * 6 + blockIdx.x] = tot;
}

// ---------------- K7: scan pass 2 (chunk combine) ----------------------------
__global__ void k_scan2() {
    int gid = blockIdx.x * 256 + threadIdx.x;
    float h = 0.0f, St = 0.0f;
    for (int c = 0; c < NCHUNK; c++) {
        long off = (long)c * (DIN * DST) + gid;
        St += d_Kc[off] * h;
        h   = d_P[off] * h + d_E[off];
    }
    float tot = blockReduceSum(St);
    if (threadIdx.x == 0) d_part_p2[blockIdx.x] = tot;
}

// ---------------- K8: deterministic final reduce -----------------------------
__global__ void k_final(float* __restrict__ out) {
    int t = threadIdx.x;
    float v = 0.0f;
    for (int i = t; i < 1536; i += 256)          v += d_part_conv[i];
    for (int i = t; i < NCHUNK * 6; i += 256)    v += d_part_scan[i];
    for (int i = t; i < 96; i += 256)            v += d_part_p2[i];
    float tot = blockReduceSum(v);
    if (t == 0) out[0] = tot;
}

// ---------------- launch -----------------------------------------------------
extern "C" void kernel_launch(void* const* d_in, const int* in_sizes, int n_in,
                              void* d_out, int out_size) {
    const float* x     = (const float*)d_in[0];
    const float* w_in  = (const float*)d_in[1];
    const float* convw = (const float*)d_in[2];
    const float* convb = (const float*)d_in[3];
    const float* xpw   = (const float*)d_in[4];
    const float* dtw   = (const float*)d_in[5];
    const float* dtb   = (const float*)d_in[6];
    const float* A_log = (const float*)d_in[7];
    const float* Dvec  = (const float*)d_in[8];
    const float* opw   = (const float*)d_in[9];
    float* out = (float*)d_out;

    static int configured = 0;
    if (!configured) {
        cudaFuncSetAttribute(k_gemm1_mma, cudaFuncAttributeMaxDynamicSharedMemorySize, G1_SMEM);
        cudaFuncSetAttribute(k_gemm2_mma, cudaFuncAttributeMaxDynamicSharedMemorySize, G1_SMEM);
        cudaFuncSetAttribute(k_dt_mma,   cudaFuncAttributeMaxDynamicSharedMemorySize, G1_SMEM);
        configured = 1;
    }

    k_prep<<<PB_WSPLIT + PB_XPAD + PB_DTW + PB_COLSUM, 256>>>(w_in, xpw, dtw, opw);
    k_patchT<<<384, 256>>>(x);
    k_gemm1_mma<<<dim3(2 * DIN / 128, LSEQ / 128), 256, G1_SMEM>>>();
    k_conv<<<(LSEQ / 4) * (DIN / 4) / 256, 256>>>(convw, convb, Dvec);
    k_gemm2_mma<<<dim3(LSEQ / 128, G2_KSPLIT), 256, G1_SMEM>>>();
    k_g2red<<<(LSEQ * NCOL) / 256, 256>>>();
    k_dt_mma<<<dim3(LSEQ / 128, DIN / 128), 256, G1_SMEM>>>(dtb);
    k_scan1<<<dim3(DIN / 256, NCHUNK), 256>>>(A_log);
    k_scan2<<<96, 256>>>();
    k_final<<<1, 256>>>(out);
}

// round 10
// speedup vs baseline: 3.8083x; 1.3780x over previous
#include <cuda_runtime.h>
#include <cuda_bf16.h>
#include <cuda_fp16.h>
#include <math.h>
#include <stdint.h>

#define LSEQ 4096
#define DMOD 768
#define DIN  1536
#define DST  16
#define RNK  48
#define NCOL 80
#define NCHUNK 128
#define CHLEN  32
#define INV_LM (1.0f / (4096.0f * 768.0f))

// ---------------- scratch ----------------------------------------------------
__device__ float d_wsum[DIN];
__device__ __half d_uh [LSEQ * DMOD];
__device__ __half d_wh [2 * DIN * DMOD];
__device__ __half d_xsh[LSEQ * DIN];
__device__ __half d_xpwh[128 * DIN];     // padded x_proj_w (rows 80..127 = 0)
__device__ __half d_dbch[LSEQ * 64];     // dbc[:, :48] K-padded to 64
__device__ __half d_dtwh[DIN * 64];      // dt_proj_w K-padded to 64
__device__ float d_xz[LSEQ * 2 * DIN];
__device__ float d_xs[LSEQ * DIN];
__device__ float d_g [LSEQ * DIN];
__device__ float d_dt[LSEQ * DIN];
__device__ float d_dbc[LSEQ * NCOL];
#define G2_KSPLIT 8
__device__ float d_dbc_part[G2_KSPLIT][LSEQ * NCOL];
__device__ float d_P [NCHUNK * DIN * DST];
__device__ float d_E [NCHUNK * DIN * DST];
__device__ float d_Kc[NCHUNK * DIN * DST];
__device__ float d_part_conv[1536];
__device__ float d_part_scan[NCHUNK * 6];
__device__ float d_part_p2[96];

__device__ __forceinline__ float siluf(float x) { return x / (1.0f + __expf(-x)); }
__device__ __forceinline__ float softplusf(float s) {
    return (s > 20.0f) ? s : __logf(1.0f + __expf(s));
}

__device__ __forceinline__ float blockReduceSum(float v) {
    __shared__ float sh[32];
    int lane = threadIdx.x & 31;
    int w    = threadIdx.x >> 5;
    #pragma unroll
    for (int o = 16; o > 0; o >>= 1) v += __shfl_down_sync(0xffffffffu, v, o);
    if (lane == 0) sh[w] = v;
    __syncthreads();
    int nw = blockDim.x >> 5;
    v = (threadIdx.x < nw) ? sh[threadIdx.x] : 0.0f;
    if (w == 0) {
        #pragma unroll
        for (int o = 16; o > 0; o >>= 1) v += __shfl_down_sync(0xffffffffu, v, o);
    }
    return v;
}

// ---------------- asm helpers (sm_80-baseline) -------------------------------
__device__ __forceinline__ uint32_t smem_to_u32(const void* p) {
    uint32_t a;
    asm("{ .reg .u64 t; cvta.to.shared.u64 t, %1; cvt.u32.u64 %0, t; }" : "=r"(a) : "l"(p));
    return a;
}
#define CP16(sm, gp) \
    asm volatile("cp.async.cg.shared.global [%0], [%1], 16;" :: "r"(sm), "l"(gp))
#define CP_COMMIT() asm volatile("cp.async.commit_group;" ::: "memory")
#define CP_WAIT1()  asm volatile("cp.async.wait_group 1;" ::: "memory")

__device__ __forceinline__ void ldsm_x4(uint32_t& r0, uint32_t& r1, uint32_t& r2,
                                        uint32_t& r3, uint32_t addr) {
    asm volatile("ldmatrix.sync.aligned.m8n8.x4.shared.b16 {%0,%1,%2,%3}, [%4];"
                 : "=r"(r0), "=r"(r1), "=r"(r2), "=r"(r3) : "r"(addr));
}
__device__ __forceinline__ void mma16816(float* c, const uint32_t* a, const uint32_t* b) {
    asm volatile("mma.sync.aligned.m16n8k16.row.col.f32.f16.f16.f32 "
                 "{%0,%1,%2,%3}, {%4,%5,%6,%7}, {%8,%9}, {%0,%1,%2,%3};"
                 : "+f"(c[0]), "+f"(c[1]), "+f"(c[2]), "+f"(c[3])
                 : "r"(a[0]), "r"(a[1]), "r"(a[2]), "r"(a[3]), "r"(b[0]), "r"(b[1]));
}

// swizzled 64B-row addressing: row r, 16B slot s -> conflict-free ldmatrix
__device__ __forceinline__ uint32_t swz(uint32_t row, uint32_t slot) {
    return row * 64u + ((slot ^ ((row >> 1) & 3u)) << 4);
}

// ---------------- K_prep: wsplit + xpw pad + dtw pad + colsum ----------------
#define PB_WSPLIT ((2 * DIN * DMOD) / 256)       // 9216
#define PB_XPAD   ((128 * DIN) / 256)            // 768
#define PB_DTW    ((DIN * 64) / 256)             // 384
#define PB_COLSUM (DIN / 16)                     // 96
__global__ void k_prep(const float* __restrict__ w,
                       const float* __restrict__ xpw,
                       const float* __restrict__ dtw,
                       const float* __restrict__ opw) {
    int bid = blockIdx.x;
    int t = threadIdx.x;
    if (bid < PB_WSPLIT) {
        int idx = bid * 256 + t;
        d_wh[idx] = __float2half(w[idx]);
    } else if (bid < PB_WSPLIT + PB_XPAD) {
        int idx = (bid - PB_WSPLIT) * 256 + t;   // row*1536 + k
        int row = idx / DIN;
        d_xpwh[idx] = __float2half((row < NCOL) ? xpw[idx] : 0.0f);
    } else if (bid < PB_WSPLIT + PB_XPAD + PB_DTW) {
        int idx = (bid - PB_WSPLIT - PB_XPAD) * 256 + t;   // row*64 + k
        int row = idx >> 6;
        int k   = idx & 63;
        d_dtwh[idx] = __float2half((k < RNK) ? dtw[row * RNK + k] : 0.0f);
    } else {
        int cb = bid - PB_WSPLIT - PB_XPAD - PB_DTW;
        __shared__ float sh[16][17];
        int dl = t & 15;
        int mg = t >> 4;
        int d  = cb * 16 + dl;
        float s = 0.0f;
        for (int m = mg * 48; m < mg * 48 + 48; m++) s += opw[m * DIN + d];
        sh[dl][mg] = s;
        __syncthreads();
        if (t < 16) {
            float tot = 0.0f;
            #pragma unroll
            for (int g = 0; g < 16; g++) tot += sh[t][g];
            d_wsum[cb * 16 + t] = tot;
        }
    }
}

// ---------------- K_patchT: coalesced patchify via smem transpose ------------
__global__ void k_patchT(const float* __restrict__ x) {
    __shared__ __half sh[8][1024];
    int bid = blockIdx.x;              // 3 * 16 * 16 / 2 = 384
    int c   = bid >> 7;
    int rem = bid & 127;
    int ih0 = (rem >> 4) * 8;
    int a   = rem & 15;
    int t = threadIdx.x;

    #pragma unroll
    for (int rep = 0; rep < 8; rep++) {
        int j    = t + rep * 256;      // float4 index 0..2047
        int row  = j >> 8;
        int col4 = j & 255;
        int H = (ih0 + row) * 16 + a;
        float4 v = *(const float4*)&x[c * 1048576 + H * 1024 + col4 * 4];
        sh[row][col4 * 4 + 0] = __float2half(v.x);
        sh[row][col4 * 4 + 1] = __float2half(v.y);
        sh[row][col4 * 4 + 2] = __float2half(v.z);
        sh[row][col4 * 4 + 3] = __float2half(v.w);
    }
    __syncthreads();

    int iwr = t >> 4, b = t & 15;
    int l  = iwr * 256 + a * 16 + b;
    int d0 = c * 256 + ih0 * 4;
    int colbase = iwr * 16 + b;
    uint32_t hv[16];
    #pragma unroll
    for (int j = 0; j < 16; j++) {
        int d2 = 2 * j;
        int i0 = d2 >> 2,       q0 = d2 & 3;
        int i1 = (d2 + 1) >> 2, q1 = (d2 + 1) & 3;
        __half2 hp = {sh[i0][q0 * 256 + colbase], sh[i1][q1 * 256 + colbase]};
        hv[j] = *(uint32_t*)&hp;
    }
    long base = (long)l * DMOD + d0;
    #pragma unroll
    for (int j = 0; j < 4; j++) {
        uint4 qh = {hv[4 * j], hv[4 * j + 1], hv[4 * j + 2], hv[4 * j + 3]};
        *(uint4*)&d_uh[base + j * 8] = qh;
    }
}

// ---------------- shared GEMM machinery (fp16, single term) ------------------
#define G1_TILE   8192                  // 128 rows * 64 B
#define G1_STAGE  (2 * G1_TILE)         // A, B = 16384 B
#define G1_SMEM   (3 * G1_STAGE)        // 49152 B
#define G1_ITERS  24                    // 768 / 32

__device__ __forceinline__ void gx_prefetch(
        uint32_t sbase, int stage, int k0, int l0, int n0, int t,
        const __half* A, const __half* B, int kstride) {
    const uint32_t so = sbase + stage * G1_STAGE;
    const int prow = t >> 2;
    const int pq   = t & 3;
    #pragma unroll
    for (int rep = 0; rep < 2; rep++) {
        int row = prow + rep * 64;
        uint32_t soff = swz((uint32_t)row, (uint32_t)pq);
        long ga = (long)(l0 + row) * kstride + k0 + pq * 8;
        long gb = (long)(n0 + row) * kstride + k0 + pq * 8;
        CP16(so + soff,           (const void*)(A + ga));
        CP16(so + G1_TILE + soff, (const void*)(B + gb));
    }
}

__device__ __forceinline__ void gx_mainloop_iter(uint32_t so, int lane, int wm, int wn,
                                                 float acc[4][4][4]) {
    #pragma unroll
    for (int kk = 0; kk < 2; kk++) {
        const uint32_t arow = (uint32_t)(wm * 64 + (lane & 15));
        const uint32_t aslot = (uint32_t)(kk * 2 + (lane >> 4));
        const int g = lane >> 3;
        const uint32_t brow = (uint32_t)(wn * 32 + ((g >> 1) << 3) + (lane & 7));
        const uint32_t bslot = (uint32_t)(kk * 2 + (g & 1));

        uint32_t af[4][4];
        #pragma unroll
        for (int mt = 0; mt < 4; mt++) {
            uint32_t addr = so + swz(arow + mt * 16, aslot);
            ldsm_x4(af[mt][0], af[mt][1], af[mt][2], af[mt][3], addr);
        }
        uint32_t bf[4][2];
        #pragma unroll
        for (int np = 0; np < 2; np++) {
            uint32_t addr = so + G1_TILE + swz(brow + np * 16, bslot);
            ldsm_x4(bf[2 * np][0], bf[2 * np][1],
                    bf[2 * np + 1][0], bf[2 * np + 1][1], addr);
        }
        #pragma unroll
        for (int mt = 0; mt < 4; mt++)
            #pragma unroll
            for (int nt = 0; nt < 4; nt++)
                mma16816(acc[mt][nt], af[mt], bf[nt]);
    }
}

// ---------------- K2: GEMM1 --------------------------------------------------
__global__ void __launch_bounds__(256, 2) k_gemm1_mma() {
    extern __shared__ char smem[];
    const uint32_t sbase = smem_to_u32(smem);
    const int t    = threadIdx.x;
    const int lane = t & 31;
    const int wid  = t >> 5;
    const int wm   = wid >> 2;
    const int wn   = wid & 3;
    const int n0   = blockIdx.x * 128;
    const int l0   = blockIdx.y * 128;

    float acc[4][4][4];
    #pragma unroll
    for (int i = 0; i < 4; i++)
        #pragma unroll
        for (int j = 0; j < 4; j++)
            #pragma unroll
            for (int q = 0; q < 4; q++) acc[i][j][q] = 0.0f;

    gx_prefetch(sbase, 0, 0, l0, n0, t, d_uh, d_wh, DMOD);
    CP_COMMIT();
    gx_prefetch(sbase, 1, 32, l0, n0, t, d_uh, d_wh, DMOD);
    CP_COMMIT();

    for (int c = 0; c < G1_ITERS; c++) {
        CP_WAIT1();
        __syncthreads();
        if (c + 2 < G1_ITERS)
            gx_prefetch(sbase, (c + 2) % 3, (c + 2) * 32, l0, n0, t, d_uh, d_wh, DMOD);
        CP_COMMIT();
        gx_mainloop_iter(sbase + (c % 3) * G1_STAGE, lane, wm, wn, acc);
    }

    #pragma unroll
    for (int mt = 0; mt < 4; mt++) {
        int r0 = l0 + wm * 64 + mt * 16 + (lane >> 2);
        #pragma unroll
        for (int nt = 0; nt < 4; nt++) {
            int cc = n0 + wn * 32 + nt * 8 + 2 * (lane & 3);
            float2 v0 = {acc[mt][nt][0], acc[mt][nt][1]};
            float2 v1 = {acc[mt][nt][2], acc[mt][nt][3]};
            *(float2*)&d_xz[(long)r0 * (2 * DIN) + cc]       = v0;
            *(float2*)&d_xz[(long)(r0 + 8) * (2 * DIN) + cc] = v1;
        }
    }
}

// -------- K3: causal depthwise conv(4) + silu, emits fp32 + fp16 -------------
__global__ void k_conv(const float* __restrict__ convw,
                       const float* __restrict__ convb,
                       const float* __restrict__ Dvec) {
    int idx = blockIdx.x * blockDim.x + threadIdx.x;
    int lq  = idx / (DIN / 4);
    int q   = idx - lq * (DIN / 4);
    int ch0 = q * 4;
    int l0  = lq * 4;

    float4 bia = *(const float4*)&convb[ch0];
    float w4[4][4];
    #pragma unroll
    for (int j = 0; j < 4; j++) {
        float4 w = *(const float4*)&convw[(ch0 + j) * 4];
        w4[j][0] = w.x; w4[j][1] = w.y; w4[j][2] = w.z; w4[j][3] = w.w;
    }
    float4 ws = *(const float4*)&d_wsum[ch0];
    float4 Dv = *(const float4*)&Dvec[ch0];

    float4 r[7];
    #pragma unroll
    for (int k = 0; k < 7; k++) {
        int lk = l0 - 3 + k;
        if (lk >= 0) r[k] = *(const float4*)&d_xz[(long)lk * (2 * DIN) + ch0];
        else         r[k] = make_float4(0.f, 0.f, 0.f, 0.f);
    }
    float local = 0.0f;
    #pragma unroll
    for (int i = 0; i < 4; i++) {
        int l = l0 + i;
        float s0 = bia.x, s1 = bia.y, s2 = bia.z, s3 = bia.w;
        #pragma unroll
        for (int k = 0; k < 4; k++) {
            float4 v = r[i + k];
            s0 += w4[0][k] * v.x;
            s1 += w4[1][k] * v.y;
            s2 += w4[2][k] * v.z;
            s3 += w4[3][k] * v.w;
        }
        float4 zv = *(const float4*)&d_xz[(long)l * (2 * DIN) + DIN + ch0];
        float xs0 = siluf(s0), xs1 = siluf(s1), xs2 = siluf(s2), xs3 = siluf(s3);
        float g0 = siluf(zv.x) * ws.x * INV_LM;
        float g1 = siluf(zv.y) * ws.y * INV_LM;
        float g2 = siluf(zv.z) * ws.z * INV_LM;
        float g3 = siluf(zv.w) * ws.w * INV_LM;
        float4 xso = {xs0, xs1, xs2, xs3};
        float4 go  = {g0, g1, g2, g3};
        *(float4*)&d_xs[(long)l * DIN + ch0] = xso;
        *(float4*)&d_g [(long)l * DIN + ch0] = go;
        __half2 hp0 = {__float2half(xs0), __float2half(xs1)};
        __half2 hp1 = {__float2half(xs2), __float2half(xs3)};
        uint2 hv = {*(uint32_t*)&hp0, *(uint32_t*)&hp1};
        *(uint2*)&d_xsh[(long)l * DIN + ch0] = hv;
        local += xs0 * Dv.x * g0 + xs1 * Dv.y * g1 + xs2 * Dv.z * g2 + xs3 * Dv.w * g3;
    }
    float tot = blockReduceSum(local);
    if (threadIdx.x == 0) d_part_conv[blockIdx.x] = tot;
}

// ---------------- K4: GEMM2 via mma.sync, split-K 8 --------------------------
#define G2_KLEN  (DIN / G2_KSPLIT)     // 192
#define G2_ITERS (G2_KLEN / 32)        // 6
__global__ void __launch_bounds__(256, 2) k_gemm2_mma() {
    extern __shared__ char smem[];
    const uint32_t sbase = smem_to_u32(smem);
    const int t    = threadIdx.x;
    const int lane = t & 31;
    const int wid  = t >> 5;
    const int wm   = wid >> 2;
    const int wn   = wid & 3;
    const int l0   = blockIdx.x * 128;
    const int kz   = blockIdx.y;
    const int kbase = kz * G2_KLEN;

    float acc[4][4][4];
    #pragma unroll
    for (int i = 0; i < 4; i++)
        #pragma unroll
        for (int j = 0; j < 4; j++)
            #pragma unroll
            for (int q = 0; q < 4; q++) acc[i][j][q] = 0.0f;

    gx_prefetch(sbase, 0, kbase, l0, 0, t, d_xsh, d_xpwh, DIN);
    CP_COMMIT();
    gx_prefetch(sbase, 1, kbase + 32, l0, 0, t, d_xsh, d_xpwh, DIN);
    CP_COMMIT();

    for (int c = 0; c < G2_ITERS; c++) {
        CP_WAIT1();
        __syncthreads();
        if (c + 2 < G2_ITERS)
            gx_prefetch(sbase, (c + 2) % 3, kbase + (c + 2) * 32, l0, 0, t,
                        d_xsh, d_xpwh, DIN);
        CP_COMMIT();
        gx_mainloop_iter(sbase + (c % 3) * G1_STAGE, lane, wm, wn, acc);
    }

    #pragma unroll
    for (int mt = 0; mt < 4; mt++) {
        int r0 = l0 + wm * 64 + mt * 16 + (lane >> 2);
        #pragma unroll
        for (int nt = 0; nt < 4; nt++) {
            int cc = wn * 32 + nt * 8 + 2 * (lane & 3);
            if (cc + 1 < NCOL) {
                float2 v0 = {acc[mt][nt][0], acc[mt][nt][1]};
                float2 v1 = {acc[mt][nt][2], acc[mt][nt][3]};
                *(float2*)&d_dbc_part[kz][(long)r0 * NCOL + cc]       = v0;
                *(float2*)&d_dbc_part[kz][(long)(r0 + 8) * NCOL + cc] = v1;
            }
        }
    }
}

// ---------------- K4b: reduce split-K partials + emit dbc fp16 ---------------
__global__ void k_g2red() {
    int idx = blockIdx.x * 256 + threadIdx.x;   // < LSEQ*NCOL
    float s = 0.0f;
    #pragma unroll
    for (int kz = 0; kz < G2_KSPLIT; kz++) s += d_dbc_part[kz][idx];
    d_dbc[idx] = s;
    int l   = idx / NCOL;
    int col = idx - l * NCOL;
    if (col < RNK) {
        d_dbch[l * 64 + col] = __float2half(s);
    } else if (col >= 64) {
        d_dbch[l * 64 + col - 16] = __float2half(0.0f);
    }
}

// ---------------- K5: dt via mma.sync (M=4096, N=1536, K=48->64) -------------
#define DT_ITERS 2
__global__ void __launch_bounds__(256, 2) k_dt_mma(const float* __restrict__ dtb) {
    extern __shared__ char smem[];
    const uint32_t sbase = smem_to_u32(smem);
    const int t    = threadIdx.x;
    const int lane = t & 31;
    const int wid  = t >> 5;
    const int wm   = wid >> 2;
    const int wn   = wid & 3;
    const int l0   = blockIdx.x * 128;
    const int n0   = blockIdx.y * 128;

    float acc[4][4][4];
    #pragma unroll
    for (int i = 0; i < 4; i++)
        #pragma unroll
        for (int j = 0; j < 4; j++)
            #pragma unroll
            for (int q = 0; q < 4; q++) acc[i][j][q] = 0.0f;

    gx_prefetch(sbase, 0, 0, l0, n0, t, d_dbch, d_dtwh, 64);
    CP_COMMIT();
    gx_prefetch(sbase, 1, 32, l0, n0, t, d_dbch, d_dtwh, 64);
    CP_COMMIT();

    for (int c = 0; c < DT_ITERS; c++) {
        CP_WAIT1();
        __syncthreads();
        CP_COMMIT();
        gx_mainloop_iter(sbase + (c % 3) * G1_STAGE, lane, wm, wn, acc);
    }

    #pragma unroll
    for (int mt = 0; mt < 4; mt++) {
        int r0 = l0 + wm * 64 + mt * 16 + (lane >> 2);
        #pragma unroll
        for (int nt = 0; nt < 4; nt++) {
            int cc = n0 + wn * 32 + nt * 8 + 2 * (lane & 3);
            float b0 = dtb[cc], b1 = dtb[cc + 1];
            float2 v0 = {softplusf(acc[mt][nt][0] + b0), softplusf(acc[mt][nt][1] + b1)};
            float2 v1 = {softplusf(acc[mt][nt][2] + b0), softplusf(acc[mt][nt][3] + b1)};
            *(float2*)&d_dt[(long)r0 * DIN + cc]       = v0;
            *(float2*)&d_dt[(long)(r0 + 8) * DIN + cc] = v1;
        }
    }
}

// ---------------- K6: scan pass 1 — one thread owns 16 states of one d -------
__global__ void k_scan1(const float* __restrict__ A_log) {
    __shared__ __align__(16) float sB[CHLEN][DST];
    __shared__ __align__(16) float sC[CHLEN][DST];
    int t = threadIdx.x;
    int d = blockIdx.x * 256 + t;
    int c = blockIdx.y;
    int base = c * CHLEN;
    for (int p = t; p < CHLEN * DST; p += 256) {
        int r = p >> 4, s = p & 15;
        sB[r][s] = d_dbc[(base + r) * NCOL + RNK + s];
        sC[r][s] = d_dbc[(base + r) * NCOL + RNK + DST + s];
    }
    __syncthreads();

    float Av[DST];
    #pragma unroll
    for (int s = 0; s < DST; s++) Av[s] = -__expf(A_log[d * DST + s]);
    bool fast = true;
    #pragma unroll
    for (int s = 1; s < DST; s++) {
        float r = Av[s] / Av[0];
        fast = fast && (fabsf(r - (float)(s + 1)) < 1e-3f);
    }

    float h[DST], cp[DST], K[DST];
    #pragma unroll
    for (int s = 0; s < DST; s++) { h[s] = 0.0f; cp[s] = 1.0f; K[s] = 0.0f; }
    float acc = 0.0f;

    for (int i = 0; i < CHLEN; i++) {
        int l = base + i;
        float dtv = d_dt[(long)l * DIN + d];
        float xsv = d_xs[(long)l * DIN + d];
        float gv  = d_g [(long)l * DIN + d];
        float dtx = dtv * xsv;
        float dAv[DST];
        if (fast) {
            float E  = __expf(dtv * Av[0]);
            float p2 = E * E, p4 = p2 * p2, p8 = p4 * p4;
            dAv[0] = E;        dAv[1] = p2;       dAv[2] = p2 * E;
            dAv[3] = p4;       dAv[4] = p4 * E;   dAv[5] = p4 * p2;
            dAv[6] = p4 * dAv[2]; dAv[7] = p8;
            dAv[8] = p8 * E;   dAv[9] = p8 * p2;  dAv[10] = p8 * dAv[2];
            dAv[11] = p8 * p4; dAv[12] = p8 * dAv[4]; dAv[13] = p8 * dAv[5];
            dAv[14] = p8 * dAv[6]; dAv[15] = p8 * p8;
        } else {
            #pragma unroll
            for (int s = 0; s < DST; s++) dAv[s] = __expf(dtv * Av[s]);
        }
        #pragma unroll
        for (int s = 0; s < DST; s++) {
            float dA = dAv[s];
            cp[s] *= dA;
            h[s] = dA * h[s] + dtx * sB[i][s];
            float cg = sC[i][s] * gv;
            acc  += h[s] * cg;
            K[s] += cp[s] * cg;
        }
    }
    long off = ((long)c * DIN + d) * DST;
    #pragma unroll
    for (int s = 0; s < DST; s++) {
        d_P [off + s] = cp[s];
        d_E [off + s] = h[s];
        d_Kc[off + s] = K[s];
    }
    float tot = blockReduceSum(acc);
    if (t == 0) d_part_scan[c * 6 + blockIdx.x] = tot;
}

// ---------------- K7: scan pass 2 (chunk combine) ----------------------------
__global__ void k_scan2() {
    int gid = blockIdx.x * 256 + threadIdx.x;
    float h = 0.0f, St = 0.0f;
    for (int c = 0; c < NCHUNK; c++) {
        long off = (long)c * (DIN * DST) + gid;
        St += d_Kc[off] * h;
        h   = d_P[off] * h + d_E[off];
    }
    float tot = blockReduceSum(St);
    if (threadIdx.x == 0) d_part_p2[blockIdx.x] = tot;
}

// ---------------- K8: deterministic final reduce -----------------------------
__global__ void k_final(float* __restrict__ out) {
    int t = threadIdx.x;
    float v = 0.0f;
    for (int i = t; i < 1536; i += 256)          v += d_part_conv[i];
    for (int i = t; i < NCHUNK * 6; i += 256)    v += d_part_scan[i];
    for (int i = t; i < 96; i += 256)            v += d_part_p2[i];
    float tot = blockReduceSum(v);
    if (t == 0) out[0] = tot;
}

// ---------------- launch -----------------------------------------------------
extern "C" void kernel_launch(void* const* d_in, const int* in_sizes, int n_in,
                              void* d_out, int out_size) {
    const float* x     = (const float*)d_in[0];
    const float* w_in  = (const float*)d_in[1];
    const float* convw = (const float*)d_in[2];
    const float* convb = (const float*)d_in[3];
    const float* xpw   = (const float*)d_in[4];
    const float* dtw   = (const float*)d_in[5];
    const float* dtb   = (const float*)d_in[6];
    const float* A_log = (const float*)d_in[7];
    const float* Dvec  = (const float*)d_in[8];
    const float* opw   = (const float*)d_in[9];
    float* out = (float*)d_out;

    static int configured = 0;
    if (!configured) {
        cudaFuncSetAttribute(k_gemm1_mma, cudaFuncAttributeMaxDynamicSharedMemorySize, G1_SMEM);
        cudaFuncSetAttribute(k_gemm2_mma, cudaFuncAttributeMaxDynamicSharedMemorySize, G1_SMEM);
        cudaFuncSetAttribute(k_dt_mma,   cudaFuncAttributeMaxDynamicSharedMemorySize, G1_SMEM);
        configured = 1;
    }

    k_prep<<<PB_WSPLIT + PB_XPAD + PB_DTW + PB_COLSUM, 256>>>(w_in, xpw, dtw, opw);
    k_patchT<<<384, 256>>>(x);
    k_gemm1_mma<<<dim3(2 * DIN / 128, LSEQ / 128), 256, G1_SMEM>>>();
    k_conv<<<(LSEQ / 4) * (DIN / 4) / 256, 256>>>(convw, convb, Dvec);
    k_gemm2_mma<<<dim3(LSEQ / 128, G2_KSPLIT), 256, G1_SMEM>>>();
    k_g2red<<<(LSEQ * NCOL) / 256, 256>>>();
    k_dt_mma<<<dim3(LSEQ / 128, DIN / 128), 256, G1_SMEM>>>(dtb);
    k_scan1<<<dim3(DIN / 256, NCHUNK), 256>>>(A_log);
    k_scan2<<<96, 256>>>();
    k_final<<<1, 256>>>(out);
}

// round 12
// speedup vs baseline: 4.0903x; 1.0740x over previous
#include <cuda_runtime.h>
#include <cuda_bf16.h>
#include <cuda_fp16.h>
#include <math.h>
#include <stdint.h>

#define LSEQ 4096
#define DMOD 768
#define DIN  1536
#define DST  16
#define RNK  48
#define NCOL 80
#define NCHUNK 64
#define CHLEN  64
#define INV_LM (1.0f / (4096.0f * 768.0f))

// ---------------- scratch ----------------------------------------------------
__device__ float d_wsum[DIN];
__device__ __half d_uh [LSEQ * DMOD];
__device__ __half d_wh [2 * DIN * DMOD];
__device__ __half d_xsh[LSEQ * DIN];
__device__ __half d_xpwh[128 * DIN];     // padded x_proj_w (rows 80..127 = 0)
__device__ __half d_dbch[LSEQ * 64];     // dbc[:, :48] K-padded to 64
__device__ __half d_dtwh[DIN * 64];      // dt_proj_w K-padded to 64
__device__ float d_xz[LSEQ * 2 * DIN];
__device__ float d_xs[LSEQ * DIN];
__device__ float d_g [LSEQ * DIN];
__device__ float d_dt[LSEQ * DIN];
__device__ float d_dbc[LSEQ * NCOL];
#define G2_KSPLIT 8
__device__ float d_dbc_part[G2_KSPLIT][LSEQ * NCOL];
__device__ float d_P [NCHUNK * DIN * DST];
__device__ float d_E [NCHUNK * DIN * DST];
__device__ float d_Kc[NCHUNK * DIN * DST];
__device__ float d_part_conv[1536];
__device__ float d_part_scan[NCHUNK * 6];
__device__ float d_part_p2[96];

__device__ __forceinline__ float siluf(float x) { return x / (1.0f + __expf(-x)); }
__device__ __forceinline__ float softplusf(float s) {
    return (s > 20.0f) ? s : __logf(1.0f + __expf(s));
}

__device__ __forceinline__ float blockReduceSum(float v) {
    __shared__ float sh[32];
    int lane = threadIdx.x & 31;
    int w    = threadIdx.x >> 5;
    #pragma unroll
    for (int o = 16; o > 0; o >>= 1) v += __shfl_down_sync(0xffffffffu, v, o);
    if (lane == 0) sh[w] = v;
    __syncthreads();
    int nw = blockDim.x >> 5;
    v = (threadIdx.x < nw) ? sh[threadIdx.x] : 0.0f;
    if (w == 0) {
        #pragma unroll
        for (int o = 16; o > 0; o >>= 1) v += __shfl_down_sync(0xffffffffu, v, o);
    }
    return v;
}

// ---------------- asm helpers (sm_80-baseline) -------------------------------
__device__ __forceinline__ uint32_t smem_to_u32(const void* p) {
    uint32_t a;
    asm("{ .reg .u64 t; cvta.to.shared.u64 t, %1; cvt.u32.u64 %0, t; }" : "=r"(a) : "l"(p));
    return a;
}
#define CP16(sm, gp) \
    asm volatile("cp.async.cg.shared.global [%0], [%1], 16;" :: "r"(sm), "l"(gp))
#define CP_COMMIT() asm volatile("cp.async.commit_group;" ::: "memory")
#define CP_WAIT0()  asm volatile("cp.async.wait_group 0;" ::: "memory")
#define CP_WAIT1()  asm volatile("cp.async.wait_group 1;" ::: "memory")
#define CP_WAIT2()  asm volatile("cp.async.wait_group 2;" ::: "memory")

__device__ __forceinline__ void ldsm_x4(uint32_t& r0, uint32_t& r1, uint32_t& r2,
                                        uint32_t& r3, uint32_t addr) {
    asm volatile("ldmatrix.sync.aligned.m8n8.x4.shared.b16 {%0,%1,%2,%3}, [%4];"
                 : "=r"(r0), "=r"(r1), "=r"(r2), "=r"(r3) : "r"(addr));
}
__device__ __forceinline__ void mma16816(float* c, const uint32_t* a, const uint32_t* b) {
    asm volatile("mma.sync.aligned.m16n8k16.row.col.f32.f16.f16.f32 "
                 "{%0,%1,%2,%3}, {%4,%5,%6,%7}, {%8,%9}, {%0,%1,%2,%3};"
                 : "+f"(c[0]), "+f"(c[1]), "+f"(c[2]), "+f"(c[3])
                 : "r"(a[0]), "r"(a[1]), "r"(a[2]), "r"(a[3]), "r"(b[0]), "r"(b[1]));
}

// swizzled 64B-row addressing: row r, 16B slot s -> conflict-free ldmatrix
__device__ __forceinline__ uint32_t swz(uint32_t row, uint32_t slot) {
    return row * 64u + ((slot ^ ((row >> 1) & 3u)) << 4);
}

// ---------------- K_prep: wsplit + xpw pad + dtw pad + colsum ----------------
#define PB_WSPLIT ((2 * DIN * DMOD) / 256)       // 9216
#define PB_XPAD   ((128 * DIN) / 256)            // 768
#define PB_DTW    ((DIN * 64) / 256)             // 384
#define PB_COLSUM (DIN / 16)                     // 96
__global__ void k_prep(const float* __restrict__ w,
                       const float* __restrict__ xpw,
                       const float* __restrict__ dtw,
                       const float* __restrict__ opw) {
    int bid = blockIdx.x;
    int t = threadIdx.x;
    if (bid < PB_WSPLIT) {
        int idx = bid * 256 + t;
        d_wh[idx] = __float2half(w[idx]);
    } else if (bid < PB_WSPLIT + PB_XPAD) {
        int idx = (bid - PB_WSPLIT) * 256 + t;   // row*1536 + k
        int row = idx / DIN;
        d_xpwh[idx] = __float2half((row < NCOL) ? xpw[idx] : 0.0f);
    } else if (bid < PB_WSPLIT + PB_XPAD + PB_DTW) {
        int idx = (bid - PB_WSPLIT - PB_XPAD) * 256 + t;   // row*64 + k
        int row = idx >> 6;
        int k   = idx & 63;
        d_dtwh[idx] = __float2half((k < RNK) ? dtw[row * RNK + k] : 0.0f);
    } else {
        int cb = bid - PB_WSPLIT - PB_XPAD - PB_DTW;
        __shared__ float sh[16][17];
        int dl = t & 15;
        int mg = t >> 4;
        int d  = cb * 16 + dl;
        float s = 0.0f;
        for (int m = mg * 48; m < mg * 48 + 48; m++) s += opw[m * DIN + d];
        sh[dl][mg] = s;
        __syncthreads();
        if (t < 16) {
            float tot = 0.0f;
            #pragma unroll
            for (int g = 0; g < 16; g++) tot += sh[t][g];
            d_wsum[cb * 16 + t] = tot;
        }
    }
}

// ---------------- K_patchT: coalesced patchify via smem transpose ------------
__global__ void k_patchT(const float* __restrict__ x) {
    __shared__ __half sh[8][1024];
    int bid = blockIdx.x;              // 384
    int c   = bid >> 7;
    int rem = bid & 127;
    int ih0 = (rem >> 4) * 8;
    int a   = rem & 15;
    int t = threadIdx.x;

    #pragma unroll
    for (int rep = 0; rep < 8; rep++) {
        int j    = t + rep * 256;      // float4 index 0..2047
        int row  = j >> 8;
        int col4 = j & 255;
        int H = (ih0 + row) * 16 + a;
        float4 v = *(const float4*)&x[c * 1048576 + H * 1024 + col4 * 4];
        sh[row][col4 * 4 + 0] = __float2half(v.x);
        sh[row][col4 * 4 + 1] = __float2half(v.y);
        sh[row][col4 * 4 + 2] = __float2half(v.z);
        sh[row][col4 * 4 + 3] = __float2half(v.w);
    }
    __syncthreads();

    int iwr = t >> 4, b = t & 15;
    int l  = iwr * 256 + a * 16 + b;
    int d0 = c * 256 + ih0 * 4;
    int colbase = iwr * 16 + b;
    uint32_t hv[16];
    #pragma unroll
    for (int j = 0; j < 16; j++) {
        int d2 = 2 * j;
        int i0 = d2 >> 2,       q0 = d2 & 3;
        int i1 = (d2 + 1) >> 2, q1 = (d2 + 1) & 3;
        __half2 hp = {sh[i0][q0 * 256 + colbase], sh[i1][q1 * 256 + colbase]};
        hv[j] = *(uint32_t*)&hp;
    }
    long base = (long)l * DMOD + d0;
    #pragma unroll
    for (int j = 0; j < 4; j++) {
        uint4 qh = {hv[4 * j], hv[4 * j + 1], hv[4 * j + 2], hv[4 * j + 3]};
        *(uint4*)&d_uh[base + j * 8] = qh;
    }
}

// ---------------- shared GEMM machinery (fp16, single term, 4-stage) ---------
#define G1_TILE   8192                  // 128 rows * 64 B
#define G1_STAGE  (2 * G1_TILE)         // A, B = 16384 B
#define G1_NSTG   4
#define G1_SMEM   (G1_NSTG * G1_STAGE)  // 65536 B
#define G1_ITERS  24                    // 768 / 32

__device__ __forceinline__ void gx_prefetch(
        uint32_t sbase, int stage, int k0, int l0, int n0, int t,
        const __half* A, const __half* B, int kstride) {
    const uint32_t so = sbase + stage * G1_STAGE;
    const int prow = t >> 2;
    const int pq   = t & 3;
    #pragma unroll
    for (int rep = 0; rep < 2; rep++) {
        int row = prow + rep * 64;
        uint32_t soff = swz((uint32_t)row, (uint32_t)pq);
        long ga = (long)(l0 + row) * kstride + k0 + pq * 8;
        long gb = (long)(n0 + row) * kstride + k0 + pq * 8;
        CP16(so + soff,           (const void*)(A + ga));
        CP16(so + G1_TILE + soff, (const void*)(B + gb));
    }
}

__device__ __forceinline__ void gx_mainloop_iter(uint32_t so, int lane, int wm, int wn,
                                                 float acc[4][4][4]) {
    #pragma unroll
    for (int kk = 0; kk < 2; kk++) {
        const uint32_t arow = (uint32_t)(wm * 64 + (lane & 15));
        const uint32_t aslot = (uint32_t)(kk * 2 + (lane >> 4));
        const int g = lane >> 3;
        const uint32_t brow = (uint32_t)(wn * 32 + ((g >> 1) << 3) + (lane & 7));
        const uint32_t bslot = (uint32_t)(kk * 2 + (g & 1));

        uint32_t af[4][4];
        #pragma unroll
        for (int mt = 0; mt < 4; mt++) {
            uint32_t addr = so + swz(arow + mt * 16, aslot);
            ldsm_x4(af[mt][0], af[mt][1], af[mt][2], af[mt][3], addr);
        }
        uint32_t bf[4][2];
        #pragma unroll
        for (int np = 0; np < 2; np++) {
            uint32_t addr = so + G1_TILE + swz(brow + np * 16, bslot);
            ldsm_x4(bf[2 * np][0], bf[2 * np][1],
                    bf[2 * np + 1][0], bf[2 * np + 1][1], addr);
        }
        #pragma unroll
        for (int mt = 0; mt < 4; mt++)
            #pragma unroll
            for (int nt = 0; nt < 4; nt++)
                mma16816(acc[mt][nt], af[mt], bf[nt]);
    }
}

// ---------------- K2: GEMM1 --------------------------------------------------
__global__ void __launch_bounds__(256, 2) k_gemm1_mma() {
    extern __shared__ char smem[];
    const uint32_t sbase = smem_to_u32(smem);
    const int t    = threadIdx.x;
    const int lane = t & 31;
    const int wid  = t >> 5;
    const int wm   = wid >> 2;
    const int wn   = wid & 3;
    const int n0   = blockIdx.x * 128;
    const int l0   = blockIdx.y * 128;

    float acc[4][4][4];
    #pragma unroll
    for (int i = 0; i < 4; i++)
        #pragma unroll
        for (int j = 0; j < 4; j++)
            #pragma unroll
            for (int q = 0; q < 4; q++) acc[i][j][q] = 0.0f;

    #pragma unroll
    for (int s = 0; s < 3; s++) {
        gx_prefetch(sbase, s, s * 32, l0, n0, t, d_uh, d_wh, DMOD);
        CP_COMMIT();
    }

    for (int c = 0; c < G1_ITERS; c++) {
        CP_WAIT2();            // group c complete (c+1, c+2 may be in flight)
        __syncthreads();       // stage (c+3)%4's previous consumers done
        if (c + 3 < G1_ITERS)
            gx_prefetch(sbase, (c + 3) % G1_NSTG, (c + 3) * 32, l0, n0, t,
                        d_uh, d_wh, DMOD);
        CP_COMMIT();
        gx_mainloop_iter(sbase + (c % G1_NSTG) * G1_STAGE, lane, wm, wn, acc);
    }

    #pragma unroll
    for (int mt = 0; mt < 4; mt++) {
        int r0 = l0 + wm * 64 + mt * 16 + (lane >> 2);
        #pragma unroll
        for (int nt = 0; nt < 4; nt++) {
            int cc = n0 + wn * 32 + nt * 8 + 2 * (lane & 3);
            float2 v0 = {acc[mt][nt][0], acc[mt][nt][1]};
            float2 v1 = {acc[mt][nt][2], acc[mt][nt][3]};
            *(float2*)&d_xz[(long)r0 * (2 * DIN) + cc]       = v0;
            *(float2*)&d_xz[(long)(r0 + 8) * (2 * DIN) + cc] = v1;
        }
    }
}

// -------- K3: causal depthwise conv(4) + silu, emits fp32 + fp16 -------------
__global__ void k_conv(const float* __restrict__ convw,
                       const float* __restrict__ convb,
                       const float* __restrict__ Dvec) {
    int idx = blockIdx.x * blockDim.x + threadIdx.x;
    int lq  = idx / (DIN / 4);
    int q   = idx - lq * (DIN / 4);
    int ch0 = q * 4;
    int l0  = lq * 4;

    float4 bia = *(const float4*)&convb[ch0];
    float w4[4][4];
    #pragma unroll
    for (int j = 0; j < 4; j++) {
        float4 w = *(const float4*)&convw[(ch0 + j) * 4];
        w4[j][0] = w.x; w4[j][1] = w.y; w4[j][2] = w.z; w4[j][3] = w.w;
    }
    float4 ws = *(const float4*)&d_wsum[ch0];
    float4 Dv = *(const float4*)&Dvec[ch0];

    float4 r[7];
    #pragma unroll
    for (int k = 0; k < 7; k++) {
        int lk = l0 - 3 + k;
        if (lk >= 0) r[k] = *(const float4*)&d_xz[(long)lk * (2 * DIN) + ch0];
        else         r[k] = make_float4(0.f, 0.f, 0.f, 0.f);
    }
    float local = 0.0f;
    #pragma unroll
    for (int i = 0; i < 4; i++) {
        int l = l0 + i;
        float s0 = bia.x, s1 = bia.y, s2 = bia.z, s3 = bia.w;
        #pragma unroll
        for (int k = 0; k < 4; k++) {
            float4 v = r[i + k];
            s0 += w4[0][k] * v.x;
            s1 += w4[1][k] * v.y;
            s2 += w4[2][k] * v.z;
            s3 += w4[3][k] * v.w;
        }
        float4 zv = *(const float4*)&d_xz[(long)l * (2 * DIN) + DIN + ch0];
        float xs0 = siluf(s0), xs1 = siluf(s1), xs2 = siluf(s2), xs3 = siluf(s3);
        float g0 = siluf(zv.x) * ws.x * INV_LM;
        float g1 = siluf(zv.y) * ws.y * INV_LM;
        float g2 = siluf(zv.z) * ws.z * INV_LM;
        float g3 = siluf(zv.w) * ws.w * INV_LM;
        float4 xso = {xs0, xs1, xs2, xs3};
        float4 go  = {g0, g1, g2, g3};
        *(float4*)&d_xs[(long)l * DIN + ch0] = xso;
        *(float4*)&d_g [(long)l * DIN + ch0] = go;
        __half2 hp0 = {__float2half(xs0), __float2half(xs1)};
        __half2 hp1 = {__float2half(xs2), __float2half(xs3)};
        uint2 hv = {*(uint32_t*)&hp0, *(uint32_t*)&hp1};
        *(uint2*)&d_xsh[(long)l * DIN + ch0] = hv;
        local += xs0 * Dv.x * g0 + xs1 * Dv.y * g1 + xs2 * Dv.z * g2 + xs3 * Dv.w * g3;
    }
    float tot = blockReduceSum(local);
    if (threadIdx.x == 0) d_part_conv[blockIdx.x] = tot;
}

// ---------------- K4: GEMM2 via mma.sync, split-K 8 --------------------------
#define G2_KLEN  (DIN / G2_KSPLIT)     // 192
#define G2_ITERS (G2_KLEN / 32)        // 6
__global__ void __launch_bounds__(256, 2) k_gemm2_mma() {
    extern __shared__ char smem[];
    const uint32_t sbase = smem_to_u32(smem);
    const int t    = threadIdx.x;
    const int lane = t & 31;
    const int wid  = t >> 5;
    const int wm   = wid >> 2;
    const int wn   = wid & 3;
    const int l0   = blockIdx.x * 128;
    const int kz   = blockIdx.y;
    const int kbase = kz * G2_KLEN;

    float acc[4][4][4];
    #pragma unroll
    for (int i = 0; i < 4; i++)
        #pragma unroll
        for (int j = 0; j < 4; j++)
            #pragma unroll
            for (int q = 0; q < 4; q++) acc[i][j][q] = 0.0f;

    #pragma unroll
    for (int s = 0; s < 3; s++) {
        gx_prefetch(sbase, s, kbase + s * 32, l0, 0, t, d_xsh, d_xpwh, DIN);
        CP_COMMIT();
    }

    for (int c = 0; c < G2_ITERS; c++) {
        CP_WAIT2();
        __syncthreads();
        if (c + 3 < G2_ITERS)
            gx_prefetch(sbase, (c + 3) % G1_NSTG, kbase + (c + 3) * 32, l0, 0, t,
                        d_xsh, d_xpwh, DIN);
        CP_COMMIT();
        gx_mainloop_iter(sbase + (c % G1_NSTG) * G1_STAGE, lane, wm, wn, acc);
    }

    #pragma unroll
    for (int mt = 0; mt < 4; mt++) {
        int r0 = l0 + wm * 64 + mt * 16 + (lane >> 2);
        #pragma unroll
        for (int nt = 0; nt < 4; nt++) {
            int cc = wn * 32 + nt * 8 + 2 * (lane & 3);
            if (cc + 1 < NCOL) {
                float2 v0 = {acc[mt][nt][0], acc[mt][nt][1]};
                float2 v1 = {acc[mt][nt][2], acc[mt][nt][3]};
                *(float2*)&d_dbc_part[kz][(long)r0 * NCOL + cc]       = v0;
                *(float2*)&d_dbc_part[kz][(long)(r0 + 8) * NCOL + cc] = v1;
            }
        }
    }
}

// ---------------- K4b: reduce split-K partials + emit dbc fp16 ---------------
__global__ void k_g2red() {
    int idx = blockIdx.x * 256 + threadIdx.x;   // < LSEQ*NCOL
    float s = 0.0f;
    #pragma unroll
    for (int kz = 0; kz < G2_KSPLIT; kz++) s += d_dbc_part[kz][idx];
    d_dbc[idx] = s;
    int l   = idx / NCOL;
    int col = idx - l * NCOL;
    if (col < RNK) {
        d_dbch[l * 64 + col] = __float2half(s);
    } else if (col >= 64) {
        d_dbch[l * 64 + col - 16] = __float2half(0.0f);
    }
}

// ---------------- K5: dt via mma.sync (M=4096, N=1536, K=48->64) -------------
__global__ void __launch_bounds__(256, 2) k_dt_mma(const float* __restrict__ dtb) {
    extern __shared__ char smem[];
    const uint32_t sbase = smem_to_u32(smem);
    const int t    = threadIdx.x;
    const int lane = t & 31;
    const int wid  = t >> 5;
    const int wm   = wid >> 2;
    const int wn   = wid & 3;
    const int l0   = blockIdx.x * 128;
    const int n0   = blockIdx.y * 128;

    float acc[4][4][4];
    #pragma unroll
    for (int i = 0; i < 4; i++)
        #pragma unroll
        for (int j = 0; j < 4; j++)
            #pragma unroll
            for (int q = 0; q < 4; q++) acc[i][j][q] = 0.0f;

    gx_prefetch(sbase, 0, 0, l0, n0, t, d_dbch, d_dtwh, 64);
    CP_COMMIT();
    gx_prefetch(sbase, 1, 32, l0, n0, t, d_dbch, d_dtwh, 64);
    CP_COMMIT();

    CP_WAIT1();
    __syncthreads();
    gx_mainloop_iter(sbase, lane, wm, wn, acc);
    CP_WAIT0();
    __syncthreads();
    gx_mainloop_iter(sbase + G1_STAGE, lane, wm, wn, acc);

    #pragma unroll
    for (int mt = 0; mt < 4; mt++) {
        int r0 = l0 + wm * 64 + mt * 16 + (lane >> 2);
        #pragma unroll
        for (int nt = 0; nt < 4; nt++) {
            int cc = n0 + wn * 32 + nt * 8 + 2 * (lane & 3);
            float b0 = dtb[cc], b1 = dtb[cc + 1];
            float2 v0 = {softplusf(acc[mt][nt][0] + b0), softplusf(acc[mt][nt][1] + b1)};
            float2 v1 = {softplusf(acc[mt][nt][2] + b0), softplusf(acc[mt][nt][3] + b1)};
            *(float2*)&d_dt[(long)r0 * DIN + cc]       = v0;
            *(float2*)&d_dt[(long)(r0 + 8) * DIN + cc] = v1;
        }
    }
}

// ---------------- K6: scan pass 1 — one thread owns 16 states of one d -------
__global__ void k_scan1(const float* __restrict__ A_log) {
    __shared__ __align__(16) float sB[CHLEN][DST];
    __shared__ __align__(16) float sC[CHLEN][DST];
    int t = threadIdx.x;
    int d = blockIdx.x * 256 + t;
    int c = blockIdx.y;
    int base = c * CHLEN;
    for (int p = t; p < CHLEN * DST; p += 256) {
        int r = p >> 4, s = p & 15;
        sB[r][s] = d_dbc[(base + r) * NCOL + RNK + s];
        sC[r][s] = d_dbc[(base + r) * NCOL + RNK + DST + s];
    }
    __syncthreads();

    float Av[DST];
    #pragma unroll
    for (int s = 0; s < DST; s++) Av[s] = -__expf(A_log[d * DST + s]);
    bool fast = true;
    #pragma unroll
    for (int s = 1; s < DST; s++) {
        float r = Av[s] / Av[0];
        fast = fast && (fabsf(r - (float)(s + 1)) < 1e-3f);
    }

    float h[DST], cp[DST], K[DST];
    #pragma unroll
    for (int s = 0; s < DST; s++) { h[s] = 0.0f; cp[s] = 1.0f; K[s] = 0.0f; }
    float acc = 0.0f;

    for (int i = 0; i < CHLEN; i++) {
        int l = base + i;
        float dtv = d_dt[(long)l * DIN + d];
        float xsv = d_xs[(long)l * DIN + d];
        float gv  = d_g [(long)l * DIN + d];
        float dtx = dtv * xsv;
        float dAv[DST];
        if (fast) {
            float E  = __expf(dtv * Av[0]);
            float p2 = E * E, p4 = p2 * p2, p8 = p4 * p4;
            dAv[0] = E;        dAv[1] = p2;       dAv[2] = p2 * E;
            dAv[3] = p4;       dAv[4] = p4 * E;   dAv[5] = p4 * p2;
            dAv[6] = p4 * dAv[2]; dAv[7] = p8;
            dAv[8] = p8 * E;   dAv[9] = p8 * p2;  dAv[10] = p8 * dAv[2];
            dAv[11] = p8 * p4; dAv[12] = p8 * dAv[4]; dAv[13] = p8 * dAv[5];
            dAv[14] = p8 * dAv[6]; dAv[15] = p8 * p8;
        } else {
            #pragma unroll
            for (int s = 0; s < DST; s++) dAv[s] = __expf(dtv * Av[s]);
        }
        #pragma unroll
        for (int s = 0; s < DST; s++) {
            float dA = dAv[s];
            cp[s] *= dA;
            h[s] = dA * h[s] + dtx * sB[i][s];
            float cg = sC[i][s] * gv;
            acc  += h[s] * cg;
            K[s] += cp[s] * cg;
        }
    }
    long off = ((long)c * DIN + d) * DST;
    #pragma unroll
    for (int s = 0; s < DST; s++) {
        d_P [off + s] = cp[s];
        d_E [off + s] = h[s];
        d_Kc[off + s] = K[s];
    }
    float tot = blockReduceSum(acc);
    if (t == 0) d_part_scan[c * 6 + blockIdx.x] = tot;
}

// ---------------- K7: scan pass 2 (chunk combine) ----------------------------
__global__ void k_scan2() {
    int gid = blockIdx.x * 256 + threadIdx.x;
    float h = 0.0f, St = 0.0f;
    for (int c = 0; c < NCHUNK; c++) {
        long off = (long)c * (DIN * DST) + gid;
        St += d_Kc[off] * h;
        h   = d_P[off] * h + d_E[off];
    }
    float tot = blockReduceSum(St);
    if (threadIdx.x == 0) d_part_p2[blockIdx.x] = tot;
}

// ---------------- K8: deterministic final reduce -----------------------------
__global__ void k_final(float* __restrict__ out) {
    int t = threadIdx.x;
    float v = 0.0f;
    for (int i = t; i < 1536; i += 256)          v += d_part_conv[i];
    for (int i = t; i < NCHUNK * 6; i += 256)    v += d_part_scan[i];
    for (int i = t; i < 96; i += 256)            v += d_part_p2[i];
    float tot = blockReduceSum(v);
    if (t == 0) out[0] = tot;
}

// ---------------- launch -----------------------------------------------------
extern "C" void kernel_launch(void* const* d_in, const int* in_sizes, int n_in,
                              void* d_out, int out_size) {
    const float* x     = (const float*)d_in[0];
    const float* w_in  = (const float*)d_in[1];
    const float* convw = (const float*)d_in[2];
    const float* convb = (const float*)d_in[3];
    const float* xpw   = (const float*)d_in[4];
    const float* dtw   = (const float*)d_in[5];
    const float* dtb   = (const float*)d_in[6];
    const float* A_log = (const float*)d_in[7];
    const float* Dvec  = (const float*)d_in[8];
    const float* opw   = (const float*)d_in[9];
    float* out = (float*)d_out;

    static int configured = 0;
    if (!configured) {
        cudaFuncSetAttribute(k_gemm1_mma, cudaFuncAttributeMaxDynamicSharedMemorySize, G1_SMEM);
        cudaFuncSetAttribute(k_gemm2_mma, cudaFuncAttributeMaxDynamicSharedMemorySize, G1_SMEM);
        cudaFuncSetAttribute(k_dt_mma,   cudaFuncAttributeMaxDynamicSharedMemorySize, G1_SMEM);
        configured = 1;
    }

    k_prep<<<PB_WSPLIT + PB_XPAD + PB_DTW + PB_COLSUM, 256>>>(w_in, xpw, dtw, opw);
    k_patchT<<<384, 256>>>(x);
    k_gemm1_mma<<<dim3(2 * DIN / 128, LSEQ / 128), 256, G1_SMEM>>>();
    k_conv<<<(LSEQ / 4) * (DIN / 4) / 256, 256>>>(convw, convb, Dvec);
    k_gemm2_mma<<<dim3(LSEQ / 128, G2_KSPLIT), 256, G1_SMEM>>>();
    k_g2red<<<(LSEQ * NCOL) / 256, 256>>>();
    k_dt_mma<<<dim3(LSEQ / 128, DIN / 128), 256, G1_SMEM>>>(dtb);
    k_scan1<<<dim3(DIN / 256, NCHUNK), 256>>>(A_log);
    k_scan2<<<96, 256>>>();
    k_final<<<1, 256>>>(out);
}

// round 13
// speedup vs baseline: 4.5315x; 1.1079x over previous
#include <cuda_runtime.h>
#include <cuda_bf16.h>
#include <cuda_fp16.h>
#include <math.h>
#include <stdint.h>

#define LSEQ 4096
#define DMOD 768
#define DIN  1536
#define DST  16
#define RNK  48
#define NCOL 80
#define NCHUNK 64
#define CHLEN  64
#define INV_LM (1.0f / (4096.0f * 768.0f))

// ---------------- scratch ----------------------------------------------------
__device__ float d_wsum[DIN];
__device__ __half d_uh [LSEQ * DMOD];
__device__ __half d_wh [2 * DIN * DMOD];
__device__ __half d_xsh[LSEQ * DIN];
__device__ __half d_xpwh[128 * DIN];     // padded x_proj_w (rows 80..127 = 0)
__device__ __half d_dbch[LSEQ * 64];     // dbc[:, :48] K-padded to 64
__device__ __half d_dtwh[DIN * 64];      // dt_proj_w K-padded to 64
__device__ float d_xz[LSEQ * 2 * DIN];
__device__ float d_g [LSEQ * DIN];
__device__ float d_dt[LSEQ * DIN];
__device__ float d_dbc[LSEQ * NCOL];
#define G2_KSPLIT 8
__device__ float d_dbc_part[G2_KSPLIT][LSEQ * NCOL];
__device__ float d_P [NCHUNK * DIN * DST];
__device__ float d_E [NCHUNK * DIN * DST];
__device__ float d_Kc[NCHUNK * DIN * DST];
__device__ float d_part_conv[1536];
__device__ float d_part_scan[NCHUNK * 6];
__device__ float d_part_p2[96];

__device__ __forceinline__ float siluf(float x) { return x / (1.0f + __expf(-x)); }
__device__ __forceinline__ float softplusf(float s) {
    return (s > 20.0f) ? s : __logf(1.0f + __expf(s));
}

__device__ __forceinline__ float blockReduceSum(float v) {
    __shared__ float sh[32];
    int lane = threadIdx.x & 31;
    int w    = threadIdx.x >> 5;
    #pragma unroll
    for (int o = 16; o > 0; o >>= 1) v += __shfl_down_sync(0xffffffffu, v, o);
    if (lane == 0) sh[w] = v;
    __syncthreads();
    int nw = blockDim.x >> 5;
    v = (threadIdx.x < nw) ? sh[threadIdx.x] : 0.0f;
    if (w == 0) {
        #pragma unroll
        for (int o = 16; o > 0; o >>= 1) v += __shfl_down_sync(0xffffffffu, v, o);
    }
    return v;
}

// ---------------- asm helpers (sm_80-baseline) -------------------------------
__device__ __forceinline__ uint32_t smem_to_u32(const void* p) {
    uint32_t a;
    asm("{ .reg .u64 t; cvta.to.shared.u64 t, %1; cvt.u32.u64 %0, t; }" : "=r"(a) : "l"(p));
    return a;
}
#define CP16(sm, gp) \
    asm volatile("cp.async.cg.shared.global [%0], [%1], 16;" :: "r"(sm), "l"(gp))
#define CP_COMMIT() asm volatile("cp.async.commit_group;" ::: "memory")
#define CP_WAIT0()  asm volatile("cp.async.wait_group 0;" ::: "memory")
#define CP_WAIT1()  asm volatile("cp.async.wait_group 1;" ::: "memory")
#define CP_WAIT2()  asm volatile("cp.async.wait_group 2;" ::: "memory")

__device__ __forceinline__ void ldsm_x4(uint32_t& r0, uint32_t& r1, uint32_t& r2,
                                        uint32_t& r3, uint32_t addr) {
    asm volatile("ldmatrix.sync.aligned.m8n8.x4.shared.b16 {%0,%1,%2,%3}, [%4];"
                 : "=r"(r0), "=r"(r1), "=r"(r2), "=r"(r3) : "r"(addr));
}
__device__ __forceinline__ void mma16816(float* c, const uint32_t* a, const uint32_t* b) {
    asm volatile("mma.sync.aligned.m16n8k16.row.col.f32.f16.f16.f32 "
                 "{%0,%1,%2,%3}, {%4,%5,%6,%7}, {%8,%9}, {%0,%1,%2,%3};"
                 : "+f"(c[0]), "+f"(c[1]), "+f"(c[2]), "+f"(c[3])
                 : "r"(a[0]), "r"(a[1]), "r"(a[2]), "r"(a[3]), "r"(b[0]), "r"(b[1]));
}

// swizzled 64B-row addressing: row r, 16B slot s -> conflict-free ldmatrix
__device__ __forceinline__ uint32_t swz(uint32_t row, uint32_t slot) {
    return row * 64u + ((slot ^ ((row >> 1) & 3u)) << 4);
}

// ---------------- K_prep: patchT + wsplit + xpw pad + dtw pad + colsum -------
#define PB_PATCH  384
#define PB_WSPLIT ((2 * DIN * DMOD) / 256)       // 9216
#define PB_XPAD   ((128 * DIN) / 256)            // 768
#define PB_DTW    ((DIN * 64) / 256)             // 384
#define PB_COLSUM (DIN / 16)                     // 96
__global__ void k_prep(const float* __restrict__ x,
                       const float* __restrict__ w,
                       const float* __restrict__ xpw,
                       const float* __restrict__ dtw,
                       const float* __restrict__ opw) {
    __shared__ __half shp[8][1024];              // patchify staging (16 KB)
    int bid = blockIdx.x;
    int t = threadIdx.x;
    if (bid < PB_PATCH) {
        // coalesced patchify via smem transpose
        int c   = bid >> 7;
        int rem = bid & 127;
        int ih0 = (rem >> 4) * 8;
        int a   = rem & 15;
        #pragma unroll
        for (int rep = 0; rep < 8; rep++) {
            int j    = t + rep * 256;      // float4 index 0..2047
            int row  = j >> 8;
            int col4 = j & 255;
            int H = (ih0 + row) * 16 + a;
            float4 v = *(const float4*)&x[c * 1048576 + H * 1024 + col4 * 4];
            shp[row][col4 * 4 + 0] = __float2half(v.x);
            shp[row][col4 * 4 + 1] = __float2half(v.y);
            shp[row][col4 * 4 + 2] = __float2half(v.z);
            shp[row][col4 * 4 + 3] = __float2half(v.w);
        }
        __syncthreads();
        int iwr = t >> 4, b = t & 15;
        int l  = iwr * 256 + a * 16 + b;
        int d0 = c * 256 + ih0 * 4;
        int colbase = iwr * 16 + b;
        uint32_t hv[16];
        #pragma unroll
        for (int j = 0; j < 16; j++) {
            int d2 = 2 * j;
            int i0 = d2 >> 2,       q0 = d2 & 3;
            int i1 = (d2 + 1) >> 2, q1 = (d2 + 1) & 3;
            __half2 hp = {shp[i0][q0 * 256 + colbase], shp[i1][q1 * 256 + colbase]};
            hv[j] = *(uint32_t*)&hp;
        }
        long base = (long)l * DMOD + d0;
        #pragma unroll
        for (int j = 0; j < 4; j++) {
            uint4 qh = {hv[4 * j], hv[4 * j + 1], hv[4 * j + 2], hv[4 * j + 3]};
            *(uint4*)&d_uh[base + j * 8] = qh;
        }
    } else if (bid < PB_PATCH + PB_WSPLIT) {
        int idx = (bid - PB_PATCH) * 256 + t;
        d_wh[idx] = __float2half(w[idx]);
    } else if (bid < PB_PATCH + PB_WSPLIT + PB_XPAD) {
        int idx = (bid - PB_PATCH - PB_WSPLIT) * 256 + t;   // row*1536 + k
        int row = idx / DIN;
        d_xpwh[idx] = __float2half((row < NCOL) ? xpw[idx] : 0.0f);
    } else if (bid < PB_PATCH + PB_WSPLIT + PB_XPAD + PB_DTW) {
        int idx = (bid - PB_PATCH - PB_WSPLIT - PB_XPAD) * 256 + t;   // row*64 + k
        int row = idx >> 6;
        int k   = idx & 63;
        d_dtwh[idx] = __float2half((k < RNK) ? dtw[row * RNK + k] : 0.0f);
    } else {
        int cb = bid - PB_PATCH - PB_WSPLIT - PB_XPAD - PB_DTW;
        __shared__ float shc[16][17];
        int dl = t & 15;
        int mg = t >> 4;
        int d  = cb * 16 + dl;
        float s = 0.0f;
        for (int m = mg * 48; m < mg * 48 + 48; m++) s += opw[m * DIN + d];
        shc[dl][mg] = s;
        __syncthreads();
        if (t < 16) {
            float tot = 0.0f;
            #pragma unroll
            for (int g = 0; g < 16; g++) tot += shc[t][g];
            d_wsum[cb * 16 + t] = tot;
        }
    }
}

// ---------------- shared GEMM machinery (fp16, single term, 4-stage) ---------
#define G1_TILE   8192                  // 128 rows * 64 B
#define G1_STAGE  (2 * G1_TILE)         // A, B = 16384 B
#define G1_NSTG   4
#define G1_SMEM   (G1_NSTG * G1_STAGE)  // 65536 B
#define G1_ITERS  24                    // 768 / 32

__device__ __forceinline__ void gx_prefetch(
        uint32_t sbase, int stage, int k0, int l0, int n0, int t,
        const __half* A, const __half* B, int kstride) {
    const uint32_t so = sbase + stage * G1_STAGE;
    const int prow = t >> 2;
    const int pq   = t & 3;
    #pragma unroll
    for (int rep = 0; rep < 2; rep++) {
        int row = prow + rep * 64;
        uint32_t soff = swz((uint32_t)row, (uint32_t)pq);
        long ga = (long)(l0 + row) * kstride + k0 + pq * 8;
        long gb = (long)(n0 + row) * kstride + k0 + pq * 8;
        CP16(so + soff,           (const void*)(A + ga));
        CP16(so + G1_TILE + soff, (const void*)(B + gb));
    }
}

__device__ __forceinline__ void gx_mainloop_iter(uint32_t so, int lane, int wm, int wn,
                                                 float acc[4][4][4]) {
    #pragma unroll
    for (int kk = 0; kk < 2; kk++) {
        const uint32_t arow = (uint32_t)(wm * 64 + (lane & 15));
        const uint32_t aslot = (uint32_t)(kk * 2 + (lane >> 4));
        const int g = lane >> 3;
        const uint32_t brow = (uint32_t)(wn * 32 + ((g >> 1) << 3) + (lane & 7));
        const uint32_t bslot = (uint32_t)(kk * 2 + (g & 1));

        uint32_t af[4][4];
        #pragma unroll
        for (int mt = 0; mt < 4; mt++) {
            uint32_t addr = so + swz(arow + mt * 16, aslot);
            ldsm_x4(af[mt][0], af[mt][1], af[mt][2], af[mt][3], addr);
        }
        uint32_t bf[4][2];
        #pragma unroll
        for (int np = 0; np < 2; np++) {
            uint32_t addr = so + G1_TILE + swz(brow + np * 16, bslot);
            ldsm_x4(bf[2 * np][0], bf[2 * np][1],
                    bf[2 * np + 1][0], bf[2 * np + 1][1], addr);
        }
        #pragma unroll
        for (int mt = 0; mt < 4; mt++)
            #pragma unroll
            for (int nt = 0; nt < 4; nt++)
                mma16816(acc[mt][nt], af[mt], bf[nt]);
    }
}

// ---------------- K2: GEMM1 --------------------------------------------------
__global__ void __launch_bounds__(256, 2) k_gemm1_mma() {
    extern __shared__ char smem[];
    const uint32_t sbase = smem_to_u32(smem);
    const int t    = threadIdx.x;
    const int lane = t & 31;
    const int wid  = t >> 5;
    const int wm   = wid >> 2;
    const int wn   = wid & 3;
    const int n0   = blockIdx.x * 128;
    const int l0   = blockIdx.y * 128;

    float acc[4][4][4];
    #pragma unroll
    for (int i = 0; i < 4; i++)
        #pragma unroll
        for (int j = 0; j < 4; j++)
            #pragma unroll
            for (int q = 0; q < 4; q++) acc[i][j][q] = 0.0f;

    #pragma unroll
    for (int s = 0; s < 3; s++) {
        gx_prefetch(sbase, s, s * 32, l0, n0, t, d_uh, d_wh, DMOD);
        CP_COMMIT();
    }

    for (int c = 0; c < G1_ITERS; c++) {
        CP_WAIT2();
        __syncthreads();
        if (c + 3 < G1_ITERS)
            gx_prefetch(sbase, (c + 3) % G1_NSTG, (c + 3) * 32, l0, n0, t,
                        d_uh, d_wh, DMOD);
        CP_COMMIT();
        gx_mainloop_iter(sbase + (c % G1_NSTG) * G1_STAGE, lane, wm, wn, acc);
    }

    #pragma unroll
    for (int mt = 0; mt < 4; mt++) {
        int r0 = l0 + wm * 64 + mt * 16 + (lane >> 2);
        #pragma unroll
        for (int nt = 0; nt < 4; nt++) {
            int cc = n0 + wn * 32 + nt * 8 + 2 * (lane & 3);
            float2 v0 = {acc[mt][nt][0], acc[mt][nt][1]};
            float2 v1 = {acc[mt][nt][2], acc[mt][nt][3]};
            *(float2*)&d_xz[(long)r0 * (2 * DIN) + cc]       = v0;
            *(float2*)&d_xz[(long)(r0 + 8) * (2 * DIN) + cc] = v1;
        }
    }
}

// -------- K3: causal depthwise conv(4) + silu, emits fp16 xs + fp32 g --------
__global__ void __launch_bounds__(256, 3) k_conv(const float* __restrict__ convw,
                                                 const float* __restrict__ convb,
                                                 const float* __restrict__ Dvec) {
    int idx = blockIdx.x * blockDim.x + threadIdx.x;
    int lq  = idx / (DIN / 4);
    int q   = idx - lq * (DIN / 4);
    int ch0 = q * 4;
    int l0  = lq * 4;

    float4 bia = *(const float4*)&convb[ch0];
    float w4[4][4];
    #pragma unroll
    for (int j = 0; j < 4; j++) {
        float4 w = *(const float4*)&convw[(ch0 + j) * 4];
        w4[j][0] = w.x; w4[j][1] = w.y; w4[j][2] = w.z; w4[j][3] = w.w;
    }
    float4 ws = *(const float4*)&d_wsum[ch0];
    float4 Dv = *(const float4*)&Dvec[ch0];

    float4 r[7];
    #pragma unroll
    for (int k = 0; k < 7; k++) {
        int lk = l0 - 3 + k;
        if (lk >= 0) r[k] = *(const float4*)&d_xz[(long)lk * (2 * DIN) + ch0];
        else         r[k] = make_float4(0.f, 0.f, 0.f, 0.f);
    }
    float local = 0.0f;
    #pragma unroll
    for (int i = 0; i < 4; i++) {
        int l = l0 + i;
        float s0 = bia.x, s1 = bia.y, s2 = bia.z, s3 = bia.w;
        #pragma unroll
        for (int k = 0; k < 4; k++) {
            float4 v = r[i + k];
            s0 += w4[0][k] * v.x;
            s1 += w4[1][k] * v.y;
            s2 += w4[2][k] * v.z;
            s3 += w4[3][k] * v.w;
        }
        float4 zv = *(const float4*)&d_xz[(long)l * (2 * DIN) + DIN + ch0];
        float xs0 = siluf(s0), xs1 = siluf(s1), xs2 = siluf(s2), xs3 = siluf(s3);
        float g0 = siluf(zv.x) * ws.x * INV_LM;
        float g1 = siluf(zv.y) * ws.y * INV_LM;
        float g2 = siluf(zv.z) * ws.z * INV_LM;
        float g3 = siluf(zv.w) * ws.w * INV_LM;
        float4 go = {g0, g1, g2, g3};
        *(float4*)&d_g[(long)l * DIN + ch0] = go;
        __half2 hp0 = {__float2half(xs0), __float2half(xs1)};
        __half2 hp1 = {__float2half(xs2), __float2half(xs3)};
        uint2 hv = {*(uint32_t*)&hp0, *(uint32_t*)&hp1};
        *(uint2*)&d_xsh[(long)l * DIN + ch0] = hv;
        local += xs0 * Dv.x * g0 + xs1 * Dv.y * g1 + xs2 * Dv.z * g2 + xs3 * Dv.w * g3;
    }
    float tot = blockReduceSum(local);
    if (threadIdx.x == 0) d_part_conv[blockIdx.x] = tot;
}

// ---------------- K4: GEMM2 via mma.sync, split-K 8 --------------------------
#define G2_KLEN  (DIN / G2_KSPLIT)     // 192
#define G2_ITERS (G2_KLEN / 32)        // 6
__global__ void __launch_bounds__(256, 2) k_gemm2_mma() {
    extern __shared__ char smem[];
    const uint32_t sbase = smem_to_u32(smem);
    const int t    = threadIdx.x;
    const int lane = t & 31;
    const int wid  = t >> 5;
    const int wm   = wid >> 2;
    const int wn   = wid & 3;
    const int l0   = blockIdx.x * 128;
    const int kz   = blockIdx.y;
    const int kbase = kz * G2_KLEN;

    float acc[4][4][4];
    #pragma unroll
    for (int i = 0; i < 4; i++)
        #pragma unroll
        for (int j = 0; j < 4; j++)
            #pragma unroll
            for (int q = 0; q < 4; q++) acc[i][j][q] = 0.0f;

    #pragma unroll
    for (int s = 0; s < 3; s++) {
        gx_prefetch(sbase, s, kbase + s * 32, l0, 0, t, d_xsh, d_xpwh, DIN);
        CP_COMMIT();
    }

    for (int c = 0; c < G2_ITERS; c++) {
        CP_WAIT2();
        __syncthreads();
        if (c + 3 < G2_ITERS)
            gx_prefetch(sbase, (c + 3) % G1_NSTG, kbase + (c + 3) * 32, l0, 0, t,
                        d_xsh, d_xpwh, DIN);
        CP_COMMIT();
        gx_mainloop_iter(sbase + (c % G1_NSTG) * G1_STAGE, lane, wm, wn, acc);
    }

    #pragma unroll
    for (int mt = 0; mt < 4; mt++) {
        int r0 = l0 + wm * 64 + mt * 16 + (lane >> 2);
        #pragma unroll
        for (int nt = 0; nt < 4; nt++) {
            int cc = wn * 32 + nt * 8 + 2 * (lane & 3);
            if (cc + 1 < NCOL) {
                float2 v0 = {acc[mt][nt][0], acc[mt][nt][1]};
                float2 v1 = {acc[mt][nt][2], acc[mt][nt][3]};
                *(float2*)&d_dbc_part[kz][(long)r0 * NCOL + cc]       = v0;
                *(float2*)&d_dbc_part[kz][(long)(r0 + 8) * NCOL + cc] = v1;
            }
        }
    }
}

// ---------------- K4b: reduce split-K partials + emit dbc fp16 ---------------
__global__ void k_g2red() {
    int idx = blockIdx.x * 256 + threadIdx.x;   // < LSEQ*NCOL
    float s = 0.0f;
    #pragma unroll
    for (int kz = 0; kz < G2_KSPLIT; kz++) s += d_dbc_part[kz][idx];
    d_dbc[idx] = s;
    int l   = idx / NCOL;
    int col = idx - l * NCOL;
    if (col < RNK) {
        d_dbch[l * 64 + col] = __float2half(s);
    } else if (col >= 64) {
        d_dbch[l * 64 + col - 16] = __float2half(0.0f);
    }
}

// ---------------- K5: dt via mma.sync (M=4096, N=1536, K=48->64) -------------
__global__ void __launch_bounds__(256, 2) k_dt_mma(const float* __restrict__ dtb) {
    extern __shared__ char smem[];
    const uint32_t sbase = smem_to_u32(smem);
    const int t    = threadIdx.x;
    const int lane = t & 31;
    const int wid  = t >> 5;
    const int wm   = wid >> 2;
    const int wn   = wid & 3;
    const int l0   = blockIdx.x * 128;
    const int n0   = blockIdx.y * 128;

    float acc[4][4][4];
    #pragma unroll
    for (int i = 0; i < 4; i++)
        #pragma unroll
        for (int j = 0; j < 4; j++)
            #pragma unroll
            for (int q = 0; q < 4; q++) acc[i][j][q] = 0.0f;

    gx_prefetch(sbase, 0, 0, l0, n0, t, d_dbch, d_dtwh, 64);
    CP_COMMIT();
    gx_prefetch(sbase, 1, 32, l0, n0, t, d_dbch, d_dtwh, 64);
    CP_COMMIT();

    CP_WAIT1();
    __syncthreads();
    gx_mainloop_iter(sbase, lane, wm, wn, acc);
    CP_WAIT0();
    __syncthreads();
    gx_mainloop_iter(sbase + G1_STAGE, lane, wm, wn, acc);

    #pragma unroll
    for (int mt = 0; mt < 4; mt++) {
        int r0 = l0 + wm * 64 + mt * 16 + (lane >> 2);
        #pragma unroll
        for (int nt = 0; nt < 4; nt++) {
            int cc = n0 + wn * 32 + nt * 8 + 2 * (lane & 3);
            float b0 = dtb[cc], b1 = dtb[cc + 1];
            float2 v0 = {softplusf(acc[mt][nt][0] + b0), softplusf(acc[mt][nt][1] + b1)};
            float2 v1 = {softplusf(acc[mt][nt][2] + b0), softplusf(acc[mt][nt][3] + b1)};
            *(float2*)&d_dt[(long)r0 * DIN + cc]       = v0;
            *(float2*)&d_dt[(long)(r0 + 8) * DIN + cc] = v1;
        }
    }
}

// ---------------- K6: scan pass 1 — one thread owns 16 states of one d -------
__global__ void k_scan1(const float* __restrict__ A_log) {
    __shared__ __align__(16) float sB[CHLEN][DST];
    __shared__ __align__(16) float sC[CHLEN][DST];
    int t = threadIdx.x;
    int d = blockIdx.x * 256 + t;
    int c = blockIdx.y;
    int base = c * CHLEN;
    for (int p = t; p < CHLEN * DST; p += 256) {
        int r = p >> 4, s = p & 15;
        sB[r][s] = d_dbc[(base + r) * NCOL + RNK + s];
        sC[r][s] = d_dbc[(base + r) * NCOL + RNK + DST + s];
    }
    __syncthreads();

    float Av[DST];
    #pragma unroll
    for (int s = 0; s < DST; s++) Av[s] = -__expf(A_log[d * DST + s]);
    bool fast = true;
    #pragma unroll
    for (int s = 1; s < DST; s++) {
        float r = Av[s] / Av[0];
        fast = fast && (fabsf(r - (float)(s + 1)) < 1e-3f);
    }

    float h[DST], cp[DST], K[DST];
    #pragma unroll
    for (int s = 0; s < DST; s++) { h[s] = 0.0f; cp[s] = 1.0f; K[s] = 0.0f; }
    float acc = 0.0f;

    for (int i = 0; i < CHLEN; i++) {
        int l = base + i;
        float dtv = d_dt[(long)l * DIN + d];
        float xsv = __half2float(d_xsh[(long)l * DIN + d]);
        float gv  = d_g [(long)l * DIN + d];
        float dtx = dtv * xsv;
        float dAv[DST];
        if (fast) {
            float E  = __expf(dtv * Av[0]);
            float p2 = E * E, p4 = p2 * p2, p8 = p4 * p4;
            dAv[0] = E;        dAv[1] = p2;       dAv[2] = p2 * E;
            dAv[3] = p4;       dAv[4] = p4 * E;   dAv[5] = p4 * p2;
            dAv[6] = p4 * dAv[2]; dAv[7] = p8;
            dAv[8] = p8 * E;   dAv[9] = p8 * p2;  dAv[10] = p8 * dAv[2];
            dAv[11] = p8 * p4; dAv[12] = p8 * dAv[4]; dAv[13] = p8 * dAv[5];
            dAv[14] = p8 * dAv[6]; dAv[15] = p8 * p8;
        } else {
            #pragma unroll
            for (int s = 0; s < DST; s++) dAv[s] = __expf(dtv * Av[s]);
        }
        #pragma unroll
        for (int s = 0; s < DST; s++) {
            float dA = dAv[s];
            cp[s] *= dA;
            h[s] = dA * h[s] + dtx * sB[i][s];
            float cg = sC[i][s] * gv;
            acc  += h[s] * cg;
            K[s] += cp[s] * cg;
        }
    }
    long off = ((long)c * DIN + d) * DST;
    #pragma unroll
    for (int s = 0; s < DST; s++) {
        d_P [off + s] = cp[s];
        d_E [off + s] = h[s];
        d_Kc[off + s] = K[s];
    }
    float tot = blockReduceSum(acc);
    if (t == 0) d_part_scan[c * 6 + blockIdx.x] = tot;
}

// ---------------- K7: scan pass 2 (chunk combine) ----------------------------
__global__ void k_scan2() {
    int gid = blockIdx.x * 256 + threadIdx.x;
    float h = 0.0f, St = 0.0f;
    for (int c = 0; c < NCHUNK; c++) {
        long off = (long)c * (DIN * DST) + gid;
        St += d_Kc[off] * h;
        h   = d_P[off] * h + d_E[off];
    }
    float tot = blockReduceSum(St);
    if (threadIdx.x == 0) d_part_p2[blockIdx.x] = tot;
}

// ---------------- K8: deterministic final reduce -----------------------------
__global__ void k_final(float* __restrict__ out) {
    int t = threadIdx.x;
    float v = 0.0f;
    for (int i = t; i < 1536; i += 256)          v += d_part_conv[i];
    for (int i = t; i < NCHUNK * 6; i += 256)    v += d_part_scan[i];
    for (int i = t; i < 96; i += 256)            v += d_part_p2[i];
    float tot = blockReduceSum(v);
    if (t == 0) out[0] = tot;
}

// ---------------- launch -----------------------------------------------------
extern "C" void kernel_launch(void* const* d_in, const int* in_sizes, int n_in,
                              void* d_out, int out_size) {
    const float* x     = (const float*)d_in[0];
    const float* w_in  = (const float*)d_in[1];
    const float* convw = (const float*)d_in[2];
    const float* convb = (const float*)d_in[3];
    const float* xpw   = (const float*)d_in[4];
    const float* dtw   = (const float*)d_in[5];
    const float* dtb   = (const float*)d_in[6];
    const float* A_log = (const float*)d_in[7];
    const float* Dvec  = (const float*)d_in[8];
    const float* opw   = (const float*)d_in[9];
    float* out = (float*)d_out;

    static int configured = 0;
    if (!configured) {
        cudaFuncSetAttribute(k_gemm1_mma, cudaFuncAttributeMaxDynamicSharedMemorySize, G1_SMEM);
        cudaFuncSetAttribute(k_gemm2_mma, cudaFuncAttributeMaxDynamicSharedMemorySize, G1_SMEM);
        cudaFuncSetAttribute(k_dt_mma,   cudaFuncAttributeMaxDynamicSharedMemorySize, G1_SMEM);
        configured = 1;
    }

    k_prep<<<PB_PATCH + PB_WSPLIT + PB_XPAD + PB_DTW + PB_COLSUM, 256>>>(
        x, w_in, xpw, dtw, opw);
    k_gemm1_mma<<<dim3(2 * DIN / 128, LSEQ / 128), 256, G1_SMEM>>>();
    k_conv<<<(LSEQ / 4) * (DIN / 4) / 256, 256>>>(convw, convb, Dvec);
    k_gemm2_mma<<<dim3(LSEQ / 128, G2_KSPLIT), 256, G1_SMEM>>>();
    k_g2red<<<(LSEQ * NCOL) / 256, 256>>>();
    k_dt_mma<<<dim3(LSEQ / 128, DIN / 128), 256, G1_SMEM>>>(dtb);
    k_scan1<<<dim3(DIN / 256, NCHUNK), 256>>>(A_log);
    k_scan2<<<96, 256>>>();
    k_final<<<1, 256>>>(out);
}

// round 15
// speedup vs baseline: 4.5610x; 1.0065x over previous
#include <cuda_runtime.h>
#include <cuda_bf16.h>
#include <cuda_fp16.h>
#include <math.h>
#include <stdint.h>

#define LSEQ 4096
#define DMOD 768
#define DIN  1536
#define DST  16
#define RNK  48
#define NCOL 80
#define NCHUNK 64
#define CHLEN  64
#define INV_LM (1.0f / (4096.0f * 768.0f))

// ---------------- scratch ----------------------------------------------------
__device__ float d_wsum[DIN];
__device__ __half d_uh [LSEQ * DMOD];
__device__ __half d_wh [2 * DIN * DMOD];
__device__ __half d_xsh[LSEQ * DIN];
__device__ __half d_gh [LSEQ * DIN];     // g' = silu(z)*wsum  (INV_LM applied later)
__device__ __half d_xpwh[128 * DIN];     // padded x_proj_w (rows 80..127 = 0)
__device__ __half d_dbch[LSEQ * 64];     // dbc[:, :48] K-padded to 64
__device__ __half d_dtwh[DIN * 64];      // dt_proj_w K-padded to 64
__device__ float d_xz[LSEQ * DIN];       // x-half only (z gated in gemm1 epilogue)
__device__ float d_dt[LSEQ * DIN];
__device__ float d_dbc[LSEQ * NCOL];
#define G2_KSPLIT 8
__device__ float d_dbc_part[G2_KSPLIT][LSEQ * NCOL];
__device__ float d_P [NCHUNK * DIN * DST];
__device__ float d_E [NCHUNK * DIN * DST];
__device__ float d_Kc[NCHUNK * DIN * DST];
__device__ float d_part_conv[1536];
__device__ float d_part_scan[NCHUNK * 6];
__device__ float d_part_p2[96];

__device__ __forceinline__ float siluf(float x) { return x / (1.0f + __expf(-x)); }
__device__ __forceinline__ float softplusf(float s) {
    return (s > 20.0f) ? s : __logf(1.0f + __expf(s));
}

__device__ __forceinline__ float blockReduceSum(float v) {
    __shared__ float sh[32];
    int lane = threadIdx.x & 31;
    int w    = threadIdx.x >> 5;
    #pragma unroll
    for (int o = 16; o > 0; o >>= 1) v += __shfl_down_sync(0xffffffffu, v, o);
    if (lane == 0) sh[w] = v;
    __syncthreads();
    int nw = blockDim.x >> 5;
    v = (threadIdx.x < nw) ? sh[threadIdx.x] : 0.0f;
    if (w == 0) {
        #pragma unroll
        for (int o = 16; o > 0; o >>= 1) v += __shfl_down_sync(0xffffffffu, v, o);
    }
    return v;
}

// ---------------- asm helpers (sm_80-baseline) -------------------------------
__device__ __forceinline__ uint32_t smem_to_u32(const void* p) {
    uint32_t a;
    asm("{ .reg .u64 t; cvta.to.shared.u64 t, %1; cvt.u32.u64 %0, t; }" : "=r"(a) : "l"(p));
    return a;
}
#define CP16(sm, gp) \
    asm volatile("cp.async.cg.shared.global [%0], [%1], 16;" :: "r"(sm), "l"(gp))
#define CP_COMMIT() asm volatile("cp.async.commit_group;" ::: "memory")
#define CP_WAIT0()  asm volatile("cp.async.wait_group 0;" ::: "memory")
#define CP_WAIT1()  asm volatile("cp.async.wait_group 1;" ::: "memory")
#define CP_WAIT2()  asm volatile("cp.async.wait_group 2;" ::: "memory")

__device__ __forceinline__ void ldsm_x4(uint32_t& r0, uint32_t& r1, uint32_t& r2,
                                        uint32_t& r3, uint32_t addr) {
    asm volatile("ldmatrix.sync.aligned.m8n8.x4.shared.b16 {%0,%1,%2,%3}, [%4];"
                 : "=r"(r0), "=r"(r1), "=r"(r2), "=r"(r3) : "r"(addr));
}
__device__ __forceinline__ void mma16816(float* c, const uint32_t* a, const uint32_t* b) {
    asm volatile("mma.sync.aligned.m16n8k16.row.col.f32.f16.f16.f32 "
                 "{%0,%1,%2,%3}, {%4,%5,%6,%7}, {%8,%9}, {%0,%1,%2,%3};"
                 : "+f"(c[0]), "+f"(c[1]), "+f"(c[2]), "+f"(c[3])
                 : "r"(a[0]), "r"(a[1]), "r"(a[2]), "r"(a[3]), "r"(b[0]), "r"(b[1]));
}

// swizzled 64B-row addressing: row r, 16B slot s -> conflict-free ldmatrix
__device__ __forceinline__ uint32_t swz(uint32_t row, uint32_t slot) {
    return row * 64u + ((slot ^ ((row >> 1) & 3u)) << 4);
}

// ---------------- K_prep: patchT + wsplit + xpw pad + dtw pad + colsum -------
#define PB_PATCH  384
#define PB_WSPLIT ((2 * DIN * DMOD) / 256)       // 9216
#define PB_XPAD   ((128 * DIN) / 256)            // 768
#define PB_DTW    ((DIN * 64) / 256)             // 384
#define PB_COLSUM (DIN / 16)                     // 96
__global__ void k_prep(const float* __restrict__ x,
                       const float* __restrict__ w,
                       const float* __restrict__ xpw,
                       const float* __restrict__ dtw,
                       const float* __restrict__ opw) {
    __shared__ __half shp[8][1024];              // patchify staging (16 KB)
    int bid = blockIdx.x;
    int t = threadIdx.x;
    if (bid < PB_PATCH) {
        int c   = bid >> 7;
        int rem = bid & 127;
        int ih0 = (rem >> 4) * 8;
        int a   = rem & 15;
        #pragma unroll
        for (int rep = 0; rep < 8; rep++) {
            int j    = t + rep * 256;
            int row  = j >> 8;
            int col4 = j & 255;
            int H = (ih0 + row) * 16 + a;
            float4 v = *(const float4*)&x[c * 1048576 + H * 1024 + col4 * 4];
            shp[row][col4 * 4 + 0] = __float2half(v.x);
            shp[row][col4 * 4 + 1] = __float2half(v.y);
            shp[row][col4 * 4 + 2] = __float2half(v.z);
            shp[row][col4 * 4 + 3] = __float2half(v.w);
        }
        __syncthreads();
        int iwr = t >> 4, b = t & 15;
        int l  = iwr * 256 + a * 16 + b;
        int d0 = c * 256 + ih0 * 4;
        int colbase = iwr * 16 + b;
        uint32_t hv[16];
        #pragma unroll
        for (int j = 0; j < 16; j++) {
            int d2 = 2 * j;
            int i0 = d2 >> 2,       q0 = d2 & 3;
            int i1 = (d2 + 1) >> 2, q1 = (d2 + 1) & 3;
            __half2 hp = {shp[i0][q0 * 256 + colbase], shp[i1][q1 * 256 + colbase]};
            hv[j] = *(uint32_t*)&hp;
        }
        long base = (long)l * DMOD + d0;
        #pragma unroll
        for (int j = 0; j < 4; j++) {
            uint4 qh = {hv[4 * j], hv[4 * j + 1], hv[4 * j + 2], hv[4 * j + 3]};
            *(uint4*)&d_uh[base + j * 8] = qh;
        }
    } else if (bid < PB_PATCH + PB_WSPLIT) {
        int idx = (bid - PB_PATCH) * 256 + t;
        d_wh[idx] = __float2half(w[idx]);
    } else if (bid < PB_PATCH + PB_WSPLIT + PB_XPAD) {
        int idx = (bid - PB_PATCH - PB_WSPLIT) * 256 + t;
        int row = idx / DIN;
        d_xpwh[idx] = __float2half((row < NCOL) ? xpw[idx] : 0.0f);
    } else if (bid < PB_PATCH + PB_WSPLIT + PB_XPAD + PB_DTW) {
        int idx = (bid - PB_PATCH - PB_WSPLIT - PB_XPAD) * 256 + t;
        int row = idx >> 6;
        int k   = idx & 63;
        d_dtwh[idx] = __float2half((k < RNK) ? dtw[row * RNK + k] : 0.0f);
    } else {
        int cb = bid - PB_PATCH - PB_WSPLIT - PB_XPAD - PB_DTW;
        __shared__ float shc[16][17];
        int dl = t & 15;
        int mg = t >> 4;
        int d  = cb * 16 + dl;
        float s = 0.0f;
        for (int m = mg * 48; m < mg * 48 + 48; m++) s += opw[m * DIN + d];
        shc[dl][mg] = s;
        __syncthreads();
        if (t < 16) {
            float tot = 0.0f;
            #pragma unroll
            for (int g = 0; g < 16; g++) tot += shc[t][g];
            d_wsum[cb * 16 + t] = tot;
        }
    }
}

// ---------------- shared GEMM machinery (fp16, single term, 4-stage) ---------
#define G1_TILE   8192                  // 128 rows * 64 B
#define G1_STAGE  (2 * G1_TILE)         // A, B = 16384 B
#define G1_NSTG   4
#define G1_SMEM   (G1_NSTG * G1_STAGE)  // 65536 B
#define G1_ITERS  24                    // 768 / 32

__device__ __forceinline__ void gx_prefetch(
        uint32_t sbase, int stage, int k0, int l0, int n0, int t,
        const __half* A, const __half* B, int kstride) {
    const uint32_t so = sbase + stage * G1_STAGE;
    const int prow = t >> 2;
    const int pq   = t & 3;
    #pragma unroll
    for (int rep = 0; rep < 2; rep++) {
        int row = prow + rep * 64;
        uint32_t soff = swz((uint32_t)row, (uint32_t)pq);
        long ga = (long)(l0 + row) * kstride + k0 + pq * 8;
        long gb = (long)(n0 + row) * kstride + k0 + pq * 8;
        CP16(so + soff,           (const void*)(A + ga));
        CP16(so + G1_TILE + soff, (const void*)(B + gb));
    }
}

__device__ __forceinline__ void gx_mainloop_iter(uint32_t so, int lane, int wm, int wn,
                                                 float acc[4][4][4]) {
    #pragma unroll
    for (int kk = 0; kk < 2; kk++) {
        const uint32_t arow = (uint32_t)(wm * 64 + (lane & 15));
        const uint32_t aslot = (uint32_t)(kk * 2 + (lane >> 4));
        const int g = lane >> 3;
        const uint32_t brow = (uint32_t)(wn * 32 + ((g >> 1) << 3) + (lane & 7));
        const uint32_t bslot = (uint32_t)(kk * 2 + (g & 1));

        uint32_t af[4][4];
        #pragma unroll
        for (int mt = 0; mt < 4; mt++) {
            uint32_t addr = so + swz(arow + mt * 16, aslot);
            ldsm_x4(af[mt][0], af[mt][1], af[mt][2], af[mt][3], addr);
        }
        uint32_t bf[4][2];
        #pragma unroll
        for (int np = 0; np < 2; np++) {
            uint32_t addr = so + G1_TILE + swz(brow + np * 16, bslot);
            ldsm_x4(bf[2 * np][0], bf[2 * np][1],
                    bf[2 * np + 1][0], bf[2 * np + 1][1], addr);
        }
        #pragma unroll
        for (int mt = 0; mt < 4; mt++)
            #pragma unroll
            for (int nt = 0; nt < 4; nt++)
                mma16816(acc[mt][nt], af[mt], bf[nt]);
    }
}

// ---------------- K2: GEMM1 (x-half -> fp32 xz; z-half -> gated fp16 g') -----
__global__ void __launch_bounds__(256, 2) k_gemm1_mma() {
    extern __shared__ char smem[];
    const uint32_t sbase = smem_to_u32(smem);
    const int t    = threadIdx.x;
    const int lane = t & 31;
    const int wid  = t >> 5;
    const int wm   = wid >> 2;
    const int wn   = wid & 3;
    const int n0   = blockIdx.x * 128;
    const int l0   = blockIdx.y * 128;

    float acc[4][4][4];
    #pragma unroll
    for (int i = 0; i < 4; i++)
        #pragma unroll
        for (int j = 0; j < 4; j++)
            #pragma unroll
            for (int q = 0; q < 4; q++) acc[i][j][q] = 0.0f;

    #pragma unroll
    for (int s = 0; s < 3; s++) {
        gx_prefetch(sbase, s, s * 32, l0, n0, t, d_uh, d_wh, DMOD);
        CP_COMMIT();
    }

    for (int c = 0; c < G1_ITERS; c++) {
        CP_WAIT2();
        __syncthreads();
        if (c + 3 < G1_ITERS)
            gx_prefetch(sbase, (c + 3) % G1_NSTG, (c + 3) * 32, l0, n0, t,
                        d_uh, d_wh, DMOD);
        CP_COMMIT();
        gx_mainloop_iter(sbase + (c % G1_NSTG) * G1_STAGE, lane, wm, wn, acc);
    }

    if (n0 < DIN) {
        // x-half: store fp32 for the conv stencil
        #pragma unroll
        for (int mt = 0; mt < 4; mt++) {
            int r0 = l0 + wm * 64 + mt * 16 + (lane >> 2);
            #pragma unroll
            for (int nt = 0; nt < 4; nt++) {
                int cc = n0 + wn * 32 + nt * 8 + 2 * (lane & 3);
                float2 v0 = {acc[mt][nt][0], acc[mt][nt][1]};
                float2 v1 = {acc[mt][nt][2], acc[mt][nt][3]};
                *(float2*)&d_xz[(long)r0 * DIN + cc]       = v0;
                *(float2*)&d_xz[(long)(r0 + 8) * DIN + cc] = v1;
            }
        }
    } else {
        // z-half: g' = silu(z) * wsum   (NO INV_LM here — fp16 subnormal hazard)
        const int zb = n0 - DIN;
        #pragma unroll
        for (int mt = 0; mt < 4; mt++) {
            int r0 = l0 + wm * 64 + mt * 16 + (lane >> 2);
            #pragma unroll
            for (int nt = 0; nt < 4; nt++) {
                int cc = zb + wn * 32 + nt * 8 + 2 * (lane & 3);
                float w0 = d_wsum[cc];
                float w1 = d_wsum[cc + 1];
                __half2 g0 = __floats2half2_rn(siluf(acc[mt][nt][0]) * w0,
                                               siluf(acc[mt][nt][1]) * w1);
                __half2 g1 = __floats2half2_rn(siluf(acc[mt][nt][2]) * w0,
                                               siluf(acc[mt][nt][3]) * w1);
                *(uint32_t*)&d_gh[(long)r0 * DIN + cc]       = *(uint32_t*)&g0;
                *(uint32_t*)&d_gh[(long)(r0 + 8) * DIN + cc] = *(uint32_t*)&g1;
            }
        }
    }
}

// -------- K3: causal depthwise conv(4) + silu, reads g' fp16, emits xs fp16 --
__global__ void __launch_bounds__(256, 3) k_conv(const float* __restrict__ convw,
                                                 const float* __restrict__ convb,
                                                 const float* __restrict__ Dvec) {
    int idx = blockIdx.x * blockDim.x + threadIdx.x;
    int lq  = idx / (DIN / 4);
    int q   = idx - lq * (DIN / 4);
    int ch0 = q * 4;
    int l0  = lq * 4;

    float4 bia = *(const float4*)&convb[ch0];
    float w4[4][4];
    #pragma unroll
    for (int j = 0; j < 4; j++) {
        float4 w = *(const float4*)&convw[(ch0 + j) * 4];
        w4[j][0] = w.x; w4[j][1] = w.y; w4[j][2] = w.z; w4[j][3] = w.w;
    }
    float4 Dv = *(const float4*)&Dvec[ch0];
    Dv.x *= INV_LM; Dv.y *= INV_LM; Dv.z *= INV_LM; Dv.w *= INV_LM;  // fold scale

    float4 r[7];
    #pragma unroll
    for (int k = 0; k < 7; k++) {
        int lk = l0 - 3 + k;
        if (lk >= 0) r[k] = *(const float4*)&d_xz[(long)lk * DIN + ch0];
        else         r[k] = make_float4(0.f, 0.f, 0.f, 0.f);
    }
    float local = 0.0f;
    #pragma unroll
    for (int i = 0; i < 4; i++) {
        int l = l0 + i;
        float s0 = bia.x, s1 = bia.y, s2 = bia.z, s3 = bia.w;
        #pragma unroll
        for (int k = 0; k < 4; k++) {
            float4 v = r[i + k];
            s0 += w4[0][k] * v.x;
            s1 += w4[1][k] * v.y;
            s2 += w4[2][k] * v.z;
            s3 += w4[3][k] * v.w;
        }
        float xs0 = siluf(s0), xs1 = siluf(s1), xs2 = siluf(s2), xs3 = siluf(s3);
        uint2 gvv = *(const uint2*)&d_gh[(long)l * DIN + ch0];
        float2 ga = __half22float2(*(__half2*)&gvv.x);
        float2 gb = __half22float2(*(__half2*)&gvv.y);
        __half2 hp0 = {__float2half(xs0), __float2half(xs1)};
        __half2 hp1 = {__float2half(xs2), __float2half(xs3)};
        uint2 hv = {*(uint32_t*)&hp0, *(uint32_t*)&hp1};
        *(uint2*)&d_xsh[(long)l * DIN + ch0] = hv;
        local += xs0 * Dv.x * ga.x + xs1 * Dv.y * ga.y
               + xs2 * Dv.z * gb.x + xs3 * Dv.w * gb.y;
    }
    float tot = blockReduceSum(local);
    if (threadIdx.x == 0) d_part_conv[blockIdx.x] = tot;
}

// ---------------- K4: GEMM2 via mma.sync, split-K 8 --------------------------
#define G2_KLEN  (DIN / G2_KSPLIT)     // 192
#define G2_ITERS (G2_KLEN / 32)        // 6
__global__ void __launch_bounds__(256, 2) k_gemm2_mma() {
    extern __shared__ char smem[];
    const uint32_t sbase = smem_to_u32(smem);
    const int t    = threadIdx.x;
    const int lane = t & 31;
    const int wid  = t >> 5;
    const int wm   = wid >> 2;
    const int wn   = wid & 3;
    const int l0   = blockIdx.x * 128;
    const int kz   = blockIdx.y;
    const int kbase = kz * G2_KLEN;

    float acc[4][4][4];
    #pragma unroll
    for (int i = 0; i < 4; i++)
        #pragma unroll
        for (int j = 0; j < 4; j++)
            #pragma unroll
            for (int q = 0; q < 4; q++) acc[i][j][q] = 0.0f;

    #pragma unroll
    for (int s = 0; s < 3; s++) {
        gx_prefetch(sbase, s, kbase + s * 32, l0, 0, t, d_xsh, d_xpwh, DIN);
        CP_COMMIT();
    }

    for (int c = 0; c < G2_ITERS; c++) {
        CP_WAIT2();
        __syncthreads();
        if (c + 3 < G2_ITERS)
            gx_prefetch(sbase, (c + 3) % G1_NSTG, kbase + (c + 3) * 32, l0, 0, t,
                        d_xsh, d_xpwh, DIN);
        CP_COMMIT();
        gx_mainloop_iter(sbase + (c % G1_NSTG) * G1_STAGE, lane, wm, wn, acc);
    }

    #pragma unroll
    for (int mt = 0; mt < 4; mt++) {
        int r0 = l0 + wm * 64 + mt * 16 + (lane >> 2);
        #pragma unroll
        for (int nt = 0; nt < 4; nt++) {
            int cc = wn * 32 + nt * 8 + 2 * (lane & 3);
            if (cc + 1 < NCOL) {
                float2 v0 = {acc[mt][nt][0], acc[mt][nt][1]};
                float2 v1 = {acc[mt][nt][2], acc[mt][nt][3]};
                *(float2*)&d_dbc_part[kz][(long)r0 * NCOL + cc]       = v0;
                *(float2*)&d_dbc_part[kz][(long)(r0 + 8) * NCOL + cc] = v1;
            }
        }
    }
}

// ---------------- K4b: reduce split-K partials + emit dbc fp16 ---------------
__global__ void k_g2red() {
    int idx = blockIdx.x * 256 + threadIdx.x;   // < LSEQ*NCOL
    float s = 0.0f;
    #pragma unroll
    for (int kz = 0; kz < G2_KSPLIT; kz++) s += d_dbc_part[kz][idx];
    d_dbc[idx] = s;
    int l   = idx / NCOL;
    int col = idx - l * NCOL;
    if (col < RNK) {
        d_dbch[l * 64 + col] = __float2half(s);
    } else if (col >= 64) {
        d_dbch[l * 64 + col - 16] = __float2half(0.0f);
    }
}

// ---------------- K5: dt via mma.sync (M=4096, N=1536, K=48->64) -------------
__global__ void __launch_bounds__(256, 2) k_dt_mma(const float* __restrict__ dtb) {
    extern __shared__ char smem[];
    const uint32_t sbase = smem_to_u32(smem);
    const int t    = threadIdx.x;
    const int lane = t & 31;
    const int wid  = t >> 5;
    const int wm   = wid >> 2;
    const int wn   = wid & 3;
    const int l0   = blockIdx.x * 128;
    const int n0   = blockIdx.y * 128;

    float acc[4][4][4];
    #pragma unroll
    for (int i = 0; i < 4; i++)
        #pragma unroll
        for (int j = 0; j < 4; j++)
            #pragma unroll
            for (int q = 0; q < 4; q++) acc[i][j][q] = 0.0f;

    gx_prefetch(sbase, 0, 0, l0, n0, t, d_dbch, d_dtwh, 64);
    CP_COMMIT();
    gx_prefetch(sbase, 1, 32, l0, n0, t, d_dbch, d_dtwh, 64);
    CP_COMMIT();

    CP_WAIT1();
    __syncthreads();
    gx_mainloop_iter(sbase, lane, wm, wn, acc);
    CP_WAIT0();
    __syncthreads();
    gx_mainloop_iter(sbase + G1_STAGE, lane, wm, wn, acc);

    #pragma unroll
    for (int mt = 0; mt < 4; mt++) {
        int r0 = l0 + wm * 64 + mt * 16 + (lane >> 2);
        #pragma unroll
        for (int nt = 0; nt < 4; nt++) {
            int cc = n0 + wn * 32 + nt * 8 + 2 * (lane & 3);
            float b0 = dtb[cc], b1 = dtb[cc + 1];
            float2 v0 = {softplusf(acc[mt][nt][0] + b0), softplusf(acc[mt][nt][1] + b1)};
            float2 v1 = {softplusf(acc[mt][nt][2] + b0), softplusf(acc[mt][nt][3] + b1)};
            *(float2*)&d_dt[(long)r0 * DIN + cc]       = v0;
            *(float2*)&d_dt[(long)(r0 + 8) * DIN + cc] = v1;
        }
    }
}

// ---------------- K6: scan pass 1 — one thread owns 16 states of one d -------
__global__ void k_scan1(const float* __restrict__ A_log) {
    __shared__ __align__(16) float sB[CHLEN][DST];
    __shared__ __align__(16) float sC[CHLEN][DST];
    int t = threadIdx.x;
    int d = blockIdx.x * 256 + t;
    int c = blockIdx.y;
    int base = c * CHLEN;
    for (int p = t; p < CHLEN * DST; p += 256) {
        int r = p >> 4, s = p & 15;
        sB[r][s] = d_dbc[(base + r) * NCOL + RNK + s];
        sC[r][s] = d_dbc[(base + r) * NCOL + RNK + DST + s];
    }
    __syncthreads();

    float Av[DST];
    #pragma unroll
    for (int s = 0; s < DST; s++) Av[s] = -__expf(A_log[d * DST + s]);
    bool fast = true;
    #pragma unroll
    for (int s = 1; s < DST; s++) {
        float r = Av[s] / Av[0];
        fast = fast && (fabsf(r - (float)(s + 1)) < 1e-3f);
    }

    float h[DST], cp[DST], K[DST];
    #pragma unroll
    for (int s = 0; s < DST; s++) { h[s] = 0.0f; cp[s] = 1.0f; K[s] = 0.0f; }
    float acc = 0.0f;

    for (int i = 0; i < CHLEN; i++) {
        int l = base + i;
        float dtv = d_dt[(long)l * DIN + d];
        float xsv = __half2float(d_xsh[(long)l * DIN + d]);
        float gv  = __half2float(d_gh [(long)l * DIN + d]) * INV_LM;
        float dtx = dtv * xsv;
        float dAv[DST];
        if (fast) {
            float E  = __expf(dtv * Av[0]);
            float p2 = E * E, p4 = p2 * p2, p8 = p4 * p4;
            dAv[0] = E;        dAv[1] = p2;       dAv[2] = p2 * E;
            dAv[3] = p4;       dAv[4] = p4 * E;   dAv[5] = p4 * p2;
            dAv[6] = p4 * dAv[2]; dAv[7] = p8;
            dAv[8] = p8 * E;   dAv[9] = p8 * p2;  dAv[10] = p8 * dAv[2];
            dAv[11] = p8 * p4; dAv[12] = p8 * dAv[4]; dAv[13] = p8 * dAv[5];
            dAv[14] = p8 * dAv[6]; dAv[15] = p8 * p8;
        } else {
            #pragma unroll
            for (int s = 0; s < DST; s++) dAv[s] = __expf(dtv * Av[s]);
        }
        #pragma unroll
        for (int s = 0; s < DST; s++) {
            float dA = dAv[s];
            cp[s] *= dA;
            h[s] = dA * h[s] + dtx * sB[i][s];
            float cg = sC[i][s] * gv;
            acc  += h[s] * cg;
            K[s] += cp[s] * cg;
        }
    }
    long off = ((long)c * DIN + d) * DST;
    #pragma unroll
    for (int s = 0; s < DST; s++) {
        d_P [off + s] = cp[s];
        d_E [off + s] = h[s];
        d_Kc[off + s] = K[s];
    }
    float tot = blockReduceSum(acc);
    if (t == 0) d_part_scan[c * 6 + blockIdx.x] = tot;
}

// ---------------- K7: scan pass 2 (chunk combine) ----------------------------
__global__ void k_scan2() {
    int gid = blockIdx.x * 256 + threadIdx.x;
    float h = 0.0f, St = 0.0f;
    for (int c = 0; c < NCHUNK; c++) {
        long off = (long)c * (DIN * DST) + gid;
        St += d_Kc[off] * h;
        h   = d_P[off] * h + d_E[off];
    }
    float tot = blockReduceSum(St);
    if (threadIdx.x == 0) d_part_p2[blockIdx.x] = tot;
}

// ---------------- K8: deterministic final reduce -----------------------------
__global__ void k_final(float* __restrict__ out) {
    int t = threadIdx.x;
    float v = 0.0f;
    for (int i = t; i < 1536; i += 256)          v += d_part_conv[i];
    for (int i = t; i < NCHUNK * 6; i += 256)    v += d_part_scan[i];
    for (int i = t; i < 96; i += 256)            v += d_part_p2[i];
    float tot = blockReduceSum(v);
    if (t == 0) out[0] = tot;
}

// ---------------- launch -----------------------------------------------------
extern "C" void kernel_launch(void* const* d_in, const int* in_sizes, int n_in,
                              void* d_out, int out_size) {
    const float* x     = (const float*)d_in[0];
    const float* w_in  = (const float*)d_in[1];
    const float* convw = (const float*)d_in[2];
    const float* convb = (const float*)d_in[3];
    const float* xpw   = (const float*)d_in[4];
    const float* dtw   = (const float*)d_in[5];
    const float* dtb   = (const float*)d_in[6];
    const float* A_log = (const float*)d_in[7];
    const float* Dvec  = (const float*)d_in[8];
    const float* opw   = (const float*)d_in[9];
    float* out = (float*)d_out;

    static int configured = 0;
    if (!configured) {
        cudaFuncSetAttribute(k_gemm1_mma, cudaFuncAttributeMaxDynamicSharedMemorySize, G1_SMEM);
        cudaFuncSetAttribute(k_gemm2_mma, cudaFuncAttributeMaxDynamicSharedMemorySize, G1_SMEM);
        cudaFuncSetAttribute(k_dt_mma,   cudaFuncAttributeMaxDynamicSharedMemorySize, G1_SMEM);
        configured = 1;
    }

    k_prep<<<PB_PATCH + PB_WSPLIT + PB_XPAD + PB_DTW + PB_COLSUM, 256>>>(
        x, w_in, xpw, dtw, opw);
    k_gemm1_mma<<<dim3(2 * DIN / 128, LSEQ / 128), 256, G1_SMEM>>>();
    k_conv<<<(LSEQ / 4) * (DIN / 4) / 256, 256>>>(convw, convb, Dvec);
    k_gemm2_mma<<<dim3(LSEQ / 128, G2_KSPLIT), 256, G1_SMEM>>>();
    k_g2red<<<(LSEQ * NCOL) / 256, 256>>>();
    k_dt_mma<<<dim3(LSEQ / 128, DIN / 128), 256, G1_SMEM>>>(dtb);
    k_scan1<<<dim3(DIN / 256, NCHUNK), 256>>>(A_log);
    k_scan2<<<96, 256>>>();
    k_final<<<1, 256>>>(out);
}